// round 1
// baseline (speedup 1.0000x reference)
#include <cuda_runtime.h>
#include <math.h>

#define D_MODEL 768
#define HEADS   12
#define HD      64
#define BATCH   4
#define SEQ     2048
#define M_TOTAL (BATCH*SEQ)      // 8192
#define N_QKV   (3*D_MODEL)      // 2304
#define BH      (BATCH*HEADS)    // 48

// Scratch (device globals — no allocation allowed in kernel_launch)
__device__ float g_q[BH*SEQ*HD];
__device__ float g_k[BH*SEQ*HD];
__device__ float g_v[BH*SEQ*HD];
__device__ float g_attn[M_TOTAL*D_MODEL];

// ---------------------------------------------------------------------------
// GEMM1: QKV = X @ W_qkv + b_qkv, scattered into per-head q/k/v buffers
// X: [8192, 768], W: [768, 2304]. BM=BN=64, BK=16, 256 threads, 4x4 microtile.
// ---------------------------------------------------------------------------
__global__ __launch_bounds__(256) void qkv_gemm_kernel(
    const float* __restrict__ X, const float* __restrict__ W,
    const float* __restrict__ bias)
{
    __shared__ float As[16][64];   // [k][m]
    __shared__ float Bs[16][64];   // [k][n]
    const int tid = threadIdx.x;
    const int tx = tid & 15, ty = tid >> 4;
    const int m0 = blockIdx.y * 64;
    const int n0 = blockIdx.x * 64;
    const int arow = tid >> 2, aseg = (tid & 3) << 2;
    const int brow = tid >> 4, bcol = (tid & 15) << 2;

    float acc[4][4] = {};

    for (int k0 = 0; k0 < D_MODEL; k0 += 16) {
        float4 a = *(const float4*)&X[(size_t)(m0 + arow) * D_MODEL + k0 + aseg];
        As[aseg + 0][arow] = a.x;
        As[aseg + 1][arow] = a.y;
        As[aseg + 2][arow] = a.z;
        As[aseg + 3][arow] = a.w;
        *(float4*)&Bs[brow][bcol] =
            *(const float4*)&W[(size_t)(k0 + brow) * N_QKV + n0 + bcol];
        __syncthreads();
        #pragma unroll
        for (int kk = 0; kk < 16; kk++) {
            float4 av = *(const float4*)&As[kk][ty << 2];
            float4 bv = *(const float4*)&Bs[kk][tx << 2];
            float ar[4] = {av.x, av.y, av.z, av.w};
            float br[4] = {bv.x, bv.y, bv.z, bv.w};
            #pragma unroll
            for (int i = 0; i < 4; i++)
                #pragma unroll
                for (int j = 0; j < 4; j++)
                    acc[i][j] = fmaf(ar[i], br[j], acc[i][j]);
        }
        __syncthreads();
    }

    // Entire 64-wide n tile lies inside one (which, head) pair: 64 | 768.
    const int w = n0 / D_MODEL;
    const int h = (n0 % D_MODEL) / HD;
    float* dst = (w == 0) ? g_q : (w == 1) ? g_k : g_v;

    #pragma unroll
    for (int i = 0; i < 4; i++) {
        const int m  = m0 + (ty << 2) + i;
        const int bb = m >> 11;          // / 2048
        const int l  = m & (SEQ - 1);
        #pragma unroll
        for (int j = 0; j < 4; j++) {
            const int n = n0 + (tx << 2) + j;
            const int d = n & (HD - 1);
            const float val = acc[i][j] + bias[n];
            dst[(((size_t)bb * HEADS + h) * SEQ + l) * HD + d] = val;
        }
    }
}

// ---------------------------------------------------------------------------
// Flash-attention style kernel. One CTA = one (batch*head, 64-query tile).
// Online softmax over 32 key tiles of 64. 256 threads, 4x4 microtiles.
// Writes directly into [B, L, H*64] layout for the output GEMM.
// ---------------------------------------------------------------------------
__global__ __launch_bounds__(256) void attn_kernel(float* __restrict__ attn_out)
{
    extern __shared__ float smem[];
    float* Qs = smem;            // [64][64]  k-major: Qs[kk*64 + qrow]
    float* Ks = Qs + 64 * 64;    // [64][64]  k-major: Ks[kk*64 + krow]
    float* Vs = Ks + 64 * 64;    // [64][64]  natural: Vs[krow*64 + d]
    float* Ps = Vs + 64 * 64;    // [64][65]  Ps[qrow*65 + kcol]

    const int tid = threadIdx.x;
    const int tx = tid & 15, ty = tid >> 4;
    const int qt = blockIdx.x;       // 0..31
    const int bh = blockIdx.y;       // 0..47
    const int r   = tid >> 2;        // 0..63 (load row)
    const int seg = (tid & 3) << 2;  // 0,4,8,12

    const size_t head_base = (size_t)bh * SEQ * HD;

    // Load Q tile transposed (resident for whole kernel)
    #pragma unroll
    for (int c = 0; c < 4; c++) {
        const int d0 = c * 16 + seg;
        float4 qv = *(const float4*)&g_q[head_base + (size_t)(qt * 64 + r) * HD + d0];
        Qs[(d0 + 0) * 64 + r] = qv.x;
        Qs[(d0 + 1) * 64 + r] = qv.y;
        Qs[(d0 + 2) * 64 + r] = qv.z;
        Qs[(d0 + 3) * 64 + r] = qv.w;
    }

    float o[4][4] = {};
    float m_old[4] = {-INFINITY, -INFINITY, -INFINITY, -INFINITY};
    float l_old[4] = {};

    for (int kt = 0; kt < SEQ / 64; kt++) {
        // Load K (transposed) and V (natural) tiles
        #pragma unroll
        for (int c = 0; c < 4; c++) {
            const int d0 = c * 16 + seg;
            const size_t src = head_base + (size_t)(kt * 64 + r) * HD + d0;
            float4 kv = *(const float4*)&g_k[src];
            Ks[(d0 + 0) * 64 + r] = kv.x;
            Ks[(d0 + 1) * 64 + r] = kv.y;
            Ks[(d0 + 2) * 64 + r] = kv.z;
            Ks[(d0 + 3) * 64 + r] = kv.w;
            *(float4*)&Vs[r * 64 + d0] = *(const float4*)&g_v[src];
        }
        __syncthreads();

        // S = Q K^T (4x4 microtile per thread), scaled by 1/8
        float s[4][4] = {};
        #pragma unroll 16
        for (int kk = 0; kk < 64; kk++) {
            float4 qv = *(const float4*)&Qs[kk * 64 + (ty << 2)];
            float4 kv = *(const float4*)&Ks[kk * 64 + (tx << 2)];
            float qr[4] = {qv.x, qv.y, qv.z, qv.w};
            float kr[4] = {kv.x, kv.y, kv.z, kv.w};
            #pragma unroll
            for (int i = 0; i < 4; i++)
                #pragma unroll
                for (int j = 0; j < 4; j++)
                    s[i][j] = fmaf(qr[i], kr[j], s[i][j]);
        }

        // Online softmax (row groups = 16 lanes sharing ty; shfl stays in-half)
        #pragma unroll
        for (int i = 0; i < 4; i++) {
            float mloc = -INFINITY;
            #pragma unroll
            for (int j = 0; j < 4; j++) {
                s[i][j] *= 0.125f;   // 1/sqrt(64)
                mloc = fmaxf(mloc, s[i][j]);
            }
            #pragma unroll
            for (int off = 8; off > 0; off >>= 1)
                mloc = fmaxf(mloc, __shfl_xor_sync(0xffffffffu, mloc, off));
            const float m_new = fmaxf(m_old[i], mloc);
            const float alpha = __expf(m_old[i] - m_new);
            float lsum = 0.0f;
            #pragma unroll
            for (int j = 0; j < 4; j++) {
                s[i][j] = __expf(s[i][j] - m_new);
                lsum += s[i][j];
            }
            #pragma unroll
            for (int off = 8; off > 0; off >>= 1)
                lsum += __shfl_xor_sync(0xffffffffu, lsum, off);
            l_old[i] = alpha * l_old[i] + lsum;
            m_old[i] = m_new;
            #pragma unroll
            for (int j = 0; j < 4; j++)
                o[i][j] *= alpha;
            // stash P tile
            #pragma unroll
            for (int j = 0; j < 4; j++)
                Ps[((ty << 2) + i) * 65 + (tx << 2) + j] = s[i][j];
        }
        __syncthreads();

        // O += P V
        #pragma unroll 16
        for (int kk = 0; kk < 64; kk++) {
            float4 vv = *(const float4*)&Vs[kk * 64 + (tx << 2)];
            float vr[4] = {vv.x, vv.y, vv.z, vv.w};
            float pr[4];
            #pragma unroll
            for (int i = 0; i < 4; i++)
                pr[i] = Ps[((ty << 2) + i) * 65 + kk];
            #pragma unroll
            for (int i = 0; i < 4; i++)
                #pragma unroll
                for (int j = 0; j < 4; j++)
                    o[i][j] = fmaf(pr[i], vr[j], o[i][j]);
        }
        __syncthreads();   // protect Ks/Vs/Ps for next tile
    }

    // Normalize + write to [B, L, H*64]
    const int bb = bh / HEADS;
    const int h  = bh % HEADS;
    #pragma unroll
    for (int i = 0; i < 4; i++) {
        const float inv_l = 1.0f / l_old[i];
        const int l_idx = qt * 64 + (ty << 2) + i;
        #pragma unroll
        for (int j = 0; j < 4; j++) {
            const int d = (tx << 2) + j;
            attn_out[((size_t)bb * SEQ + l_idx) * D_MODEL + h * HD + d] = o[i][j] * inv_l;
        }
    }
}

// ---------------------------------------------------------------------------
// GEMM3: out = attn @ W_out + b_out. [8192,768] x [768,768].
// ---------------------------------------------------------------------------
__global__ __launch_bounds__(256) void out_gemm_kernel(
    const float* __restrict__ A, const float* __restrict__ W,
    const float* __restrict__ bias, float* __restrict__ out)
{
    __shared__ float As[16][64];
    __shared__ float Bs[16][64];
    const int tid = threadIdx.x;
    const int tx = tid & 15, ty = tid >> 4;
    const int m0 = blockIdx.y * 64;
    const int n0 = blockIdx.x * 64;
    const int arow = tid >> 2, aseg = (tid & 3) << 2;
    const int brow = tid >> 4, bcol = (tid & 15) << 2;

    float acc[4][4] = {};

    for (int k0 = 0; k0 < D_MODEL; k0 += 16) {
        float4 a = *(const float4*)&A[(size_t)(m0 + arow) * D_MODEL + k0 + aseg];
        As[aseg + 0][arow] = a.x;
        As[aseg + 1][arow] = a.y;
        As[aseg + 2][arow] = a.z;
        As[aseg + 3][arow] = a.w;
        *(float4*)&Bs[brow][bcol] =
            *(const float4*)&W[(size_t)(k0 + brow) * D_MODEL + n0 + bcol];
        __syncthreads();
        #pragma unroll
        for (int kk = 0; kk < 16; kk++) {
            float4 av = *(const float4*)&As[kk][ty << 2];
            float4 bv = *(const float4*)&Bs[kk][tx << 2];
            float ar[4] = {av.x, av.y, av.z, av.w};
            float br[4] = {bv.x, bv.y, bv.z, bv.w};
            #pragma unroll
            for (int i = 0; i < 4; i++)
                #pragma unroll
                for (int j = 0; j < 4; j++)
                    acc[i][j] = fmaf(ar[i], br[j], acc[i][j]);
        }
        __syncthreads();
    }

    #pragma unroll
    for (int i = 0; i < 4; i++) {
        const int m = m0 + (ty << 2) + i;
        #pragma unroll
        for (int j = 0; j < 4; j++) {
            const int n = n0 + (tx << 2) + j;
            out[(size_t)m * D_MODEL + n] = acc[i][j] + bias[n];
        }
    }
}

// ---------------------------------------------------------------------------

static const int ATTN_SMEM = (64 * 64 * 3 + 64 * 65) * (int)sizeof(float); // 65792

extern "C" void kernel_launch(void* const* d_in, const int* in_sizes, int n_in,
                              void* d_out, int out_size)
{
    const float* x     = (const float*)d_in[0];
    const float* W_qkv = (const float*)d_in[1];
    const float* b_qkv = (const float*)d_in[2];
    const float* W_out = (const float*)d_in[3];
    const float* b_out = (const float*)d_in[4];
    float* out = (float*)d_out;

    cudaFuncSetAttribute(attn_kernel,
                         cudaFuncAttributeMaxDynamicSharedMemorySize, ATTN_SMEM);

    dim3 g1(N_QKV / 64, M_TOTAL / 64);     // 36 x 128
    qkv_gemm_kernel<<<g1, 256>>>(x, W_qkv, b_qkv);

    float* attn_ptr;
    cudaGetSymbolAddress((void**)&attn_ptr, g_attn);

    dim3 g2(SEQ / 64, BH);                 // 32 x 48
    attn_kernel<<<g2, 256, ATTN_SMEM>>>(attn_ptr);

    dim3 g3(D_MODEL / 64, M_TOTAL / 64);   // 12 x 128
    out_gemm_kernel<<<g3, 256>>>(attn_ptr, W_out, b_out, out);
}

// round 2
// speedup vs baseline: 1.1439x; 1.1439x over previous
#include <cuda_runtime.h>
#include <math.h>

#define D_MODEL 768
#define HEADS   12
#define HD      64
#define BATCH   4
#define SEQ     2048
#define M_TOTAL (BATCH*SEQ)      // 8192
#define N_QKV   (3*D_MODEL)      // 2304
#define BH      (BATCH*HEADS)    // 48

// Scratch (device globals — no allocation allowed in kernel_launch)
__device__ float g_q[BH*SEQ*HD];
__device__ float g_k[BH*SEQ*HD];
__device__ float g_v[BH*SEQ*HD];
__device__ float g_attn[M_TOTAL*D_MODEL];

// ---------------------------------------------------------------------------
// GEMM1: QKV = X @ W_qkv + b_qkv, scattered into per-head q/k/v buffers.
// 128x128x16 tiles, 256 threads, 8x8 microtile, register double-buffered.
// ---------------------------------------------------------------------------
__global__ __launch_bounds__(256, 2) void qkv_gemm_kernel(
    const float* __restrict__ X, const float* __restrict__ W,
    const float* __restrict__ bias)
{
    __shared__ float As[16][132];   // [k][m] transposed
    __shared__ float Bs[16][132];   // [k][n]
    const int tid = threadIdx.x;
    const int tx = tid & 15, ty = tid >> 4;
    const int m0 = blockIdx.y * 128;
    const int n0 = blockIdx.x * 128;
    const int ar  = tid >> 2;              // 0..63
    const int aseg = (tid & 3) << 2;       // 0,4,8,12
    const int brow = tid >> 4;             // 0..15
    const int bc   = (tid & 15) << 2;      // 0..60

    float acc[8][8] = {};

    // prefetch k-tile 0
    float4 pa0 = *(const float4*)&X[(size_t)(m0 + ar) * D_MODEL + aseg];
    float4 pa1 = *(const float4*)&X[(size_t)(m0 + ar + 64) * D_MODEL + aseg];
    float4 pb0 = *(const float4*)&W[(size_t)brow * N_QKV + n0 + bc];
    float4 pb1 = *(const float4*)&W[(size_t)brow * N_QKV + n0 + bc + 64];

    for (int k0 = 0; k0 < D_MODEL; k0 += 16) {
        As[aseg + 0][ar] = pa0.x;  As[aseg + 1][ar] = pa0.y;
        As[aseg + 2][ar] = pa0.z;  As[aseg + 3][ar] = pa0.w;
        As[aseg + 0][ar + 64] = pa1.x;  As[aseg + 1][ar + 64] = pa1.y;
        As[aseg + 2][ar + 64] = pa1.z;  As[aseg + 3][ar + 64] = pa1.w;
        *(float4*)&Bs[brow][bc]      = pb0;
        *(float4*)&Bs[brow][bc + 64] = pb1;
        __syncthreads();

        if (k0 + 16 < D_MODEL) {
            pa0 = *(const float4*)&X[(size_t)(m0 + ar) * D_MODEL + k0 + 16 + aseg];
            pa1 = *(const float4*)&X[(size_t)(m0 + ar + 64) * D_MODEL + k0 + 16 + aseg];
            pb0 = *(const float4*)&W[(size_t)(k0 + 16 + brow) * N_QKV + n0 + bc];
            pb1 = *(const float4*)&W[(size_t)(k0 + 16 + brow) * N_QKV + n0 + bc + 64];
        }

        #pragma unroll
        for (int kk = 0; kk < 16; kk++) {
            float4 x0 = *(const float4*)&As[kk][ty << 3];
            float4 x1 = *(const float4*)&As[kk][(ty << 3) + 4];
            float4 y0 = *(const float4*)&Bs[kk][tx << 3];
            float4 y1 = *(const float4*)&Bs[kk][(tx << 3) + 4];
            float ax[8] = {x0.x, x0.y, x0.z, x0.w, x1.x, x1.y, x1.z, x1.w};
            float bx[8] = {y0.x, y0.y, y0.z, y0.w, y1.x, y1.y, y1.z, y1.w};
            #pragma unroll
            for (int i = 0; i < 8; i++)
                #pragma unroll
                for (int j = 0; j < 8; j++)
                    acc[i][j] = fmaf(ax[i], bx[j], acc[i][j]);
        }
        __syncthreads();
    }

    // Scatter epilogue. 128 | 768, so the n-tile is inside one of {q,k,v};
    // a thread's 8 n's never cross a 64-wide head boundary (start mult of 8).
    const int w = n0 / D_MODEL;
    const int nbase = n0 + (tx << 3);
    const int h  = (nbase % D_MODEL) >> 6;
    const int d0 = nbase & (HD - 1);
    float* dst = (w == 0) ? g_q : (w == 1) ? g_k : g_v;

    float bsv[8];
    #pragma unroll
    for (int j = 0; j < 8; j++) bsv[j] = bias[nbase + j];

    #pragma unroll
    for (int i = 0; i < 8; i++) {
        const int m  = m0 + (ty << 3) + i;
        const int bb = m >> 11;
        const int l  = m & (SEQ - 1);
        float4 v0 = {acc[i][0] + bsv[0], acc[i][1] + bsv[1],
                     acc[i][2] + bsv[2], acc[i][3] + bsv[3]};
        float4 v1 = {acc[i][4] + bsv[4], acc[i][5] + bsv[5],
                     acc[i][6] + bsv[6], acc[i][7] + bsv[7]};
        float* p = &dst[(((size_t)bb * HEADS + h) * SEQ + l) * HD + d0];
        *(float4*)p = v0;
        *(float4*)(p + 4) = v1;
    }
}

// ---------------------------------------------------------------------------
// Flash attention. One CTA = one (batch*head, 128-query tile).
// 32 key tiles of 64. 256 threads. S: 8q x 4k microtile; PV: 8q x 4d.
// P stored transposed [k][q] so PV reads are contiguous float4.
// ---------------------------------------------------------------------------
#define QT 128
#define QPITCH 132
#define KPITCH 68

__global__ __launch_bounds__(256, 2) void attn_kernel(float* __restrict__ attn_out)
{
    extern __shared__ float sm[];
    float* Qs = sm;                    // [d=64][q pitch 132]
    float* Ks = Qs + 64 * QPITCH;      // [d=64][k pitch 68]
    float* Vs = Ks + 64 * KPITCH;      // [k=64][d pitch 68]
    float* Pt = Vs + 64 * KPITCH;      // [k=64][q pitch 132]

    const int tid = threadIdx.x;
    const int tx = tid & 15, ty = tid >> 4;
    const int qt = blockIdx.x;         // 0..15
    const int bh = blockIdx.y;         // 0..47
    const size_t head_base = (size_t)bh * SEQ * HD;

    // Load Q tile transposed: 128 q x 64 d
    {
        const int qr = tid >> 1;
        const int dh = (tid & 1) * 32;
        #pragma unroll
        for (int c = 0; c < 8; c++) {
            const int d = dh + c * 4;
            float4 qv = *(const float4*)&g_q[head_base + (size_t)(qt * QT + qr) * HD + d];
            Qs[(d + 0) * QPITCH + qr] = qv.x;
            Qs[(d + 1) * QPITCH + qr] = qv.y;
            Qs[(d + 2) * QPITCH + qr] = qv.z;
            Qs[(d + 3) * QPITCH + qr] = qv.w;
        }
    }

    float o[8][4] = {};
    float mo[8], lo[8];
    #pragma unroll
    for (int i = 0; i < 8; i++) { mo[i] = -INFINITY; lo[i] = 0.0f; }

    const int lr = tid >> 2;           // 0..63
    const int lseg = (tid & 3) * 16;   // 0,16,32,48

    for (int kt = 0; kt < SEQ / 64; kt++) {
        // Load K (transposed [d][k]) and V (natural [k][d])
        #pragma unroll
        for (int c = 0; c < 4; c++) {
            const int d = lseg + c * 4;
            const size_t src = head_base + (size_t)(kt * 64 + lr) * HD + d;
            float4 kv = *(const float4*)&g_k[src];
            Ks[(d + 0) * KPITCH + lr] = kv.x;
            Ks[(d + 1) * KPITCH + lr] = kv.y;
            Ks[(d + 2) * KPITCH + lr] = kv.z;
            Ks[(d + 3) * KPITCH + lr] = kv.w;
            *(float4*)&Vs[lr * KPITCH + d] = *(const float4*)&g_v[src];
        }
        __syncthreads();

        // S = Q K^T : [128q][64k], thread = 8q x 4k
        float s[8][4] = {};
        #pragma unroll 16
        for (int dd = 0; dd < 64; dd++) {
            float4 q0 = *(const float4*)&Qs[dd * QPITCH + (ty << 3)];
            float4 q1 = *(const float4*)&Qs[dd * QPITCH + (ty << 3) + 4];
            float4 kv = *(const float4*)&Ks[dd * KPITCH + (tx << 2)];
            float qr_[8] = {q0.x, q0.y, q0.z, q0.w, q1.x, q1.y, q1.z, q1.w};
            float kr_[4] = {kv.x, kv.y, kv.z, kv.w};
            #pragma unroll
            for (int i = 0; i < 8; i++)
                #pragma unroll
                for (int j = 0; j < 4; j++)
                    s[i][j] = fmaf(qr_[i], kr_[j], s[i][j]);
        }

        // Online softmax (row = 16 tx lanes; xor shuffles stay in the half)
        #pragma unroll
        for (int i = 0; i < 8; i++) {
            float mloc = -INFINITY;
            #pragma unroll
            for (int j = 0; j < 4; j++) {
                s[i][j] *= 0.125f;                 // 1/sqrt(64)
                mloc = fmaxf(mloc, s[i][j]);
            }
            #pragma unroll
            for (int off = 8; off > 0; off >>= 1)
                mloc = fmaxf(mloc, __shfl_xor_sync(0xffffffffu, mloc, off));
            const float m_new = fmaxf(mo[i], mloc);
            const float alpha = __expf(mo[i] - m_new);
            float lsum = 0.0f;
            #pragma unroll
            for (int j = 0; j < 4; j++) {
                s[i][j] = __expf(s[i][j] - m_new);
                lsum += s[i][j];
            }
            #pragma unroll
            for (int off = 8; off > 0; off >>= 1)
                lsum += __shfl_xor_sync(0xffffffffu, lsum, off);
            lo[i] = alpha * lo[i] + lsum;
            mo[i] = m_new;
            #pragma unroll
            for (int j = 0; j < 4; j++) {
                o[i][j] *= alpha;
                Pt[((tx << 2) + j) * QPITCH + (ty << 3) + i] = s[i][j];
            }
        }
        __syncthreads();

        // O += P V : thread = 8q x 4d
        #pragma unroll 16
        for (int kk = 0; kk < 64; kk++) {
            float4 p0 = *(const float4*)&Pt[kk * QPITCH + (ty << 3)];
            float4 p1 = *(const float4*)&Pt[kk * QPITCH + (ty << 3) + 4];
            float4 vv = *(const float4*)&Vs[kk * KPITCH + (tx << 2)];
            float pr[8] = {p0.x, p0.y, p0.z, p0.w, p1.x, p1.y, p1.z, p1.w};
            float vr[4] = {vv.x, vv.y, vv.z, vv.w};
            #pragma unroll
            for (int i = 0; i < 8; i++)
                #pragma unroll
                for (int j = 0; j < 4; j++)
                    o[i][j] = fmaf(pr[i], vr[j], o[i][j]);
        }
        __syncthreads();
    }

    // Normalize + write to [B, L, H*64]
    const int bb = bh / HEADS;
    const int h  = bh % HEADS;
    #pragma unroll
    for (int i = 0; i < 8; i++) {
        const float inv_l = 1.0f / lo[i];
        const int l_idx = qt * QT + (ty << 3) + i;
        float4 r = {o[i][0] * inv_l, o[i][1] * inv_l,
                    o[i][2] * inv_l, o[i][3] * inv_l};
        *(float4*)&attn_out[((size_t)bb * SEQ + l_idx) * D_MODEL + h * HD + (tx << 2)] = r;
    }
}

// ---------------------------------------------------------------------------
// GEMM3: out = attn @ W_out + b_out. [8192,768] x [768,768]. Same skeleton.
// ---------------------------------------------------------------------------
__global__ __launch_bounds__(256, 2) void out_gemm_kernel(
    const float* __restrict__ A, const float* __restrict__ W,
    const float* __restrict__ bias, float* __restrict__ out)
{
    __shared__ float As[16][132];
    __shared__ float Bs[16][132];
    const int tid = threadIdx.x;
    const int tx = tid & 15, ty = tid >> 4;
    const int m0 = blockIdx.y * 128;
    const int n0 = blockIdx.x * 128;
    const int ar  = tid >> 2;
    const int aseg = (tid & 3) << 2;
    const int brow = tid >> 4;
    const int bc   = (tid & 15) << 2;

    float acc[8][8] = {};

    float4 pa0 = *(const float4*)&A[(size_t)(m0 + ar) * D_MODEL + aseg];
    float4 pa1 = *(const float4*)&A[(size_t)(m0 + ar + 64) * D_MODEL + aseg];
    float4 pb0 = *(const float4*)&W[(size_t)brow * D_MODEL + n0 + bc];
    float4 pb1 = *(const float4*)&W[(size_t)brow * D_MODEL + n0 + bc + 64];

    for (int k0 = 0; k0 < D_MODEL; k0 += 16) {
        As[aseg + 0][ar] = pa0.x;  As[aseg + 1][ar] = pa0.y;
        As[aseg + 2][ar] = pa0.z;  As[aseg + 3][ar] = pa0.w;
        As[aseg + 0][ar + 64] = pa1.x;  As[aseg + 1][ar + 64] = pa1.y;
        As[aseg + 2][ar + 64] = pa1.z;  As[aseg + 3][ar + 64] = pa1.w;
        *(float4*)&Bs[brow][bc]      = pb0;
        *(float4*)&Bs[brow][bc + 64] = pb1;
        __syncthreads();

        if (k0 + 16 < D_MODEL) {
            pa0 = *(const float4*)&A[(size_t)(m0 + ar) * D_MODEL + k0 + 16 + aseg];
            pa1 = *(const float4*)&A[(size_t)(m0 + ar + 64) * D_MODEL + k0 + 16 + aseg];
            pb0 = *(const float4*)&W[(size_t)(k0 + 16 + brow) * D_MODEL + n0 + bc];
            pb1 = *(const float4*)&W[(size_t)(k0 + 16 + brow) * D_MODEL + n0 + bc + 64];
        }

        #pragma unroll
        for (int kk = 0; kk < 16; kk++) {
            float4 x0 = *(const float4*)&As[kk][ty << 3];
            float4 x1 = *(const float4*)&As[kk][(ty << 3) + 4];
            float4 y0 = *(const float4*)&Bs[kk][tx << 3];
            float4 y1 = *(const float4*)&Bs[kk][(tx << 3) + 4];
            float ax[8] = {x0.x, x0.y, x0.z, x0.w, x1.x, x1.y, x1.z, x1.w};
            float bx[8] = {y0.x, y0.y, y0.z, y0.w, y1.x, y1.y, y1.z, y1.w};
            #pragma unroll
            for (int i = 0; i < 8; i++)
                #pragma unroll
                for (int j = 0; j < 8; j++)
                    acc[i][j] = fmaf(ax[i], bx[j], acc[i][j]);
        }
        __syncthreads();
    }

    float bsv[8];
    #pragma unroll
    for (int j = 0; j < 8; j++) bsv[j] = bias[n0 + (tx << 3) + j];

    #pragma unroll
    for (int i = 0; i < 8; i++) {
        const int m = m0 + (ty << 3) + i;
        float4 v0 = {acc[i][0] + bsv[0], acc[i][1] + bsv[1],
                     acc[i][2] + bsv[2], acc[i][3] + bsv[3]};
        float4 v1 = {acc[i][4] + bsv[4], acc[i][5] + bsv[5],
                     acc[i][6] + bsv[6], acc[i][7] + bsv[7]};
        float* p = &out[(size_t)m * D_MODEL + n0 + (tx << 3)];
        *(float4*)p = v0;
        *(float4*)(p + 4) = v1;
    }
}

// ---------------------------------------------------------------------------

static const int ATTN_SMEM = (64 * QPITCH * 2 + 64 * KPITCH * 2) * (int)sizeof(float); // 102400

extern "C" void kernel_launch(void* const* d_in, const int* in_sizes, int n_in,
                              void* d_out, int out_size)
{
    const float* x     = (const float*)d_in[0];
    const float* W_qkv = (const float*)d_in[1];
    const float* b_qkv = (const float*)d_in[2];
    const float* W_out = (const float*)d_in[3];
    const float* b_out = (const float*)d_in[4];
    float* out = (float*)d_out;

    cudaFuncSetAttribute(attn_kernel,
                         cudaFuncAttributeMaxDynamicSharedMemorySize, ATTN_SMEM);

    dim3 g1(N_QKV / 128, M_TOTAL / 128);     // 18 x 64
    qkv_gemm_kernel<<<g1, 256>>>(x, W_qkv, b_qkv);

    float* attn_ptr;
    cudaGetSymbolAddress((void**)&attn_ptr, g_attn);

    dim3 g2(SEQ / QT, BH);                   // 16 x 48
    attn_kernel<<<g2, 256, ATTN_SMEM>>>(attn_ptr);

    dim3 g3(D_MODEL / 128, M_TOTAL / 128);   // 6 x 64
    out_gemm_kernel<<<g3, 256>>>(attn_ptr, W_out, b_out, out);
}

// round 4
// speedup vs baseline: 1.5091x; 1.3192x over previous
#include <cuda_runtime.h>
#include <math.h>
#include <stdint.h>

#define D_MODEL 768
#define HEADS   12
#define HD      64
#define BATCH   4
#define SEQ     2048
#define M_TOTAL (BATCH*SEQ)      // 8192
#define N_QKV   (3*D_MODEL)      // 2304
#define BH      (BATCH*HEADS)    // 48
#define KDIM    768
#define NCHUNK  (KDIM/32)        // 24

// Scratch (device globals — no allocation allowed in kernel_launch)
__device__ float g_q[BH*SEQ*HD];
__device__ float g_k[BH*SEQ*HD];
__device__ float g_v[BH*SEQ*HD];
__device__ float g_attn[M_TOTAL*D_MODEL];
__device__ float g_wqkv_t[N_QKV*D_MODEL];   // [2304][768]
__device__ float g_wout_t[D_MODEL*D_MODEL]; // [768][768]

// ---------------------------------------------------------------------------
// helpers
// ---------------------------------------------------------------------------
__device__ __forceinline__ uint32_t smem_to_u32(const void* p) {
    uint32_t a;
    asm("{ .reg .u64 t; cvta.to.shared.u64 t, %1; cvt.u32.u64 %0, t; }"
        : "=r"(a) : "l"(p));
    return a;
}
#define CP_ASYNC16(smem_addr, gptr) \
    asm volatile("cp.async.cg.shared.global [%0], [%1], 16;" \
        :: "r"(smem_addr), "l"(gptr))
#define CP_COMMIT() asm volatile("cp.async.commit_group;" ::: "memory")
#define CP_WAIT1()  asm volatile("cp.async.wait_group 1;" ::: "memory")
#define CP_WAIT0()  asm volatile("cp.async.wait_group 0;" ::: "memory")

__device__ __forceinline__ void mma_tf32(float c[4],
    uint32_t a0, uint32_t a1, uint32_t a2, uint32_t a3,
    uint32_t b0, uint32_t b1)
{
    asm volatile(
        "mma.sync.aligned.m16n8k8.row.col.f32.tf32.tf32.f32 "
        "{%0,%1,%2,%3}, {%4,%5,%6,%7}, {%8,%9}, {%0,%1,%2,%3};"
        : "+f"(c[0]), "+f"(c[1]), "+f"(c[2]), "+f"(c[3])
        : "r"(a0), "r"(a1), "r"(a2), "r"(a3), "r"(b0), "r"(b1));
}

// ---------------------------------------------------------------------------
// Weight transpose: dst[N][K] = src[K][N]
// ---------------------------------------------------------------------------
__global__ void transpose_kernel(const float* __restrict__ src,
                                 float* __restrict__ dst, int R, int C)
{
    __shared__ float t[32][33];
    const int bx = blockIdx.x * 32, by = blockIdx.y * 32;
    const int x = threadIdx.x, y = threadIdx.y;
    #pragma unroll
    for (int i = 0; i < 32; i += 8)
        t[y + i][x] = src[(size_t)(by + y + i) * C + bx + x];
    __syncthreads();
    #pragma unroll
    for (int i = 0; i < 32; i += 8)
        dst[(size_t)(bx + y + i) * R + by + x] = t[x][y + i];
}

// ---------------------------------------------------------------------------
// tf32 mma.sync GEMM: C[m][n] = sum_k A[m][k] * Bt[n][k] + bias[n]
// CTA tile 128x128, 8 warps of 32m x 64n, K chunks of 32 (4 MMA k-steps),
// cp.async double buffered. Raw f32 bits fed to tf32 MMA (HW truncation).
// MODE 0: scatter into g_q/g_k/g_v. MODE 1: plain [M][768] out.
// smem: 2 bufs x (A 128x36 + B 128x36) u32 = 73728 B; epilogue reuses as
// float Cs[128][132].
// ---------------------------------------------------------------------------
#define APITCH 36
#define ABUF   (128*APITCH)      // u32 elements per operand buffer

template<int MODE>
__global__ __launch_bounds__(256, 2)
void mma_gemm_kernel(const float* __restrict__ A, const float* __restrict__ Bt,
                     const float* __restrict__ bias, float* __restrict__ out)
{
    extern __shared__ uint32_t smu[];
    float* smf = (float*)smu;

    const int tid  = threadIdx.x;
    const int wid  = tid >> 5;
    const int lane = tid & 31;
    const int m0 = blockIdx.y * 128;
    const int n0 = blockIdx.x * 128;

    const int wm = (wid >> 1) * 32;   // warp m offset 0/32/64/96
    const int wn = (wid & 1) * 64;    // warp n offset 0/64

    const uint32_t sbase = smem_to_u32(smu);

    // cp.async load mapping: 4 x float4 per thread per operand per chunk
    const int ldrow = tid >> 1;            // reused below per i
    (void)ldrow;

    float acc[2][8][4] = {};

    // issue chunk 0
    {
        #pragma unroll
        for (int i = 0; i < 4; i++) {
            const int idx = i * 256 + tid;       // 0..1023
            const int row = idx >> 3;
            const int seg = (idx & 7) * 4;
            const uint32_t da = sbase + (uint32_t)(0*ABUF + row*APITCH + seg) * 4;
            CP_ASYNC16(da, &A[(size_t)(m0 + row) * KDIM + seg]);
            const uint32_t db = sbase + (uint32_t)(2*ABUF + row*APITCH + seg) * 4;
            CP_ASYNC16(db, &Bt[(size_t)(n0 + row) * KDIM + seg]);
        }
        CP_COMMIT();
    }

    const int r = lane >> 2;      // 0..7
    const int cl = lane & 3;      // 0..3

    for (int c = 0; c < NCHUNK; c++) {
        const int buf = c & 1;
        if (c + 1 < NCHUNK) {
            const int nb = (c + 1) & 1;
            const int k0 = (c + 1) * 32;
            #pragma unroll
            for (int i = 0; i < 4; i++) {
                const int idx = i * 256 + tid;
                const int row = idx >> 3;
                const int seg = (idx & 7) * 4;
                const uint32_t da = sbase + (uint32_t)(nb*ABUF + row*APITCH + seg) * 4;
                CP_ASYNC16(da, &A[(size_t)(m0 + row) * KDIM + k0 + seg]);
                const uint32_t db = sbase + (uint32_t)((2+nb)*ABUF + row*APITCH + seg) * 4;
                CP_ASYNC16(db, &Bt[(size_t)(n0 + row) * KDIM + k0 + seg]);
            }
            CP_COMMIT();
            CP_WAIT1();
        } else {
            CP_WAIT0();
        }
        __syncthreads();

        const uint32_t* as = smu + buf*ABUF + wm*APITCH;
        const uint32_t* bs = smu + (2+buf)*ABUF + wn*APITCH;

        #pragma unroll
        for (int ks = 0; ks < 4; ks++) {
            const int kb = ks * 8;
            uint32_t af[2][4];
            #pragma unroll
            for (int mi = 0; mi < 2; mi++) {
                const int base = (mi*16 + r) * APITCH + kb + cl;
                af[mi][0] = as[base];
                af[mi][1] = as[base + 8*APITCH];
                af[mi][2] = as[base + 4];
                af[mi][3] = as[base + 8*APITCH + 4];
            }
            uint32_t bf[8][2];
            #pragma unroll
            for (int ni = 0; ni < 8; ni++) {
                const int base = (ni*8 + r) * APITCH + kb + cl;
                bf[ni][0] = bs[base];
                bf[ni][1] = bs[base + 4];
            }
            #pragma unroll
            for (int mi = 0; mi < 2; mi++)
                #pragma unroll
                for (int ni = 0; ni < 8; ni++)
                    mma_tf32(acc[mi][ni], af[mi][0], af[mi][1], af[mi][2], af[mi][3],
                             bf[ni][0], bf[ni][1]);
        }
        __syncthreads();   // compute done before next chunk overwrites this buf
    }

    // ---- epilogue: stage C through smem for coalesced global stores ----
    // (all cp.async drained, both syncs passed)
    #pragma unroll
    for (int mi = 0; mi < 2; mi++) {
        #pragma unroll
        for (int ni = 0; ni < 8; ni++) {
            const int row = wm + mi*16 + r;
            const int col = wn + ni*8 + 2*cl;
            smf[row * 132 + col]       = acc[mi][ni][0];
            smf[row * 132 + col + 1]   = acc[mi][ni][1];
            smf[(row+8) * 132 + col]   = acc[mi][ni][2];
            smf[(row+8) * 132 + col+1] = acc[mi][ni][3];
        }
    }
    __syncthreads();

    // 128x128 floats = 4096 float4; 16 per thread
    #pragma unroll
    for (int i = 0; i < 16; i++) {
        const int f = i * 256 + tid;
        const int row  = f >> 5;          // 0..127
        const int col  = (f & 31) * 4;    // 0..124
        const int m  = m0 + row;
        const int ng = n0 + col;
        float4 v = { smf[row*132 + col + 0] + bias[ng + 0],
                     smf[row*132 + col + 1] + bias[ng + 1],
                     smf[row*132 + col + 2] + bias[ng + 2],
                     smf[row*132 + col + 3] + bias[ng + 3] };
        if (MODE == 0) {
            const int wsel = ng / D_MODEL;
            const int h = (ng % D_MODEL) >> 6;
            const int d = ng & 63;
            const int bb = m >> 11;
            const int l  = m & (SEQ - 1);
            float* dst = (wsel == 0) ? g_q : (wsel == 1) ? g_k : g_v;
            *(float4*)&dst[(((size_t)bb * HEADS + h) * SEQ + l) * HD + d] = v;
        } else {
            *(float4*)&out[(size_t)m * D_MODEL + ng] = v;
        }
    }
}

// ---------------------------------------------------------------------------
// Flash attention (SIMT, unchanged from R2). One CTA = (bh, 128-query tile).
// ---------------------------------------------------------------------------
#define QT 128
#define QPITCH 132
#define KPITCH 68

__global__ __launch_bounds__(256, 2) void attn_kernel(float* __restrict__ attn_out)
{
    extern __shared__ float sm[];
    float* Qs = sm;
    float* Ks = Qs + 64 * QPITCH;
    float* Vs = Ks + 64 * KPITCH;
    float* Pt = Vs + 64 * KPITCH;

    const int tid = threadIdx.x;
    const int tx = tid & 15, ty = tid >> 4;
    const int qt = blockIdx.x;
    const int bh = blockIdx.y;
    const size_t head_base = (size_t)bh * SEQ * HD;

    {
        const int qr = tid >> 1;
        const int dh = (tid & 1) * 32;
        #pragma unroll
        for (int c = 0; c < 8; c++) {
            const int d = dh + c * 4;
            float4 qv = *(const float4*)&g_q[head_base + (size_t)(qt * QT + qr) * HD + d];
            Qs[(d + 0) * QPITCH + qr] = qv.x;
            Qs[(d + 1) * QPITCH + qr] = qv.y;
            Qs[(d + 2) * QPITCH + qr] = qv.z;
            Qs[(d + 3) * QPITCH + qr] = qv.w;
        }
    }

    float o[8][4] = {};
    float mo[8], lo[8];
    #pragma unroll
    for (int i = 0; i < 8; i++) { mo[i] = -INFINITY; lo[i] = 0.0f; }

    const int lr = tid >> 2;
    const int lseg = (tid & 3) * 16;

    for (int kt = 0; kt < SEQ / 64; kt++) {
        #pragma unroll
        for (int c = 0; c < 4; c++) {
            const int d = lseg + c * 4;
            const size_t src = head_base + (size_t)(kt * 64 + lr) * HD + d;
            float4 kv = *(const float4*)&g_k[src];
            Ks[(d + 0) * KPITCH + lr] = kv.x;
            Ks[(d + 1) * KPITCH + lr] = kv.y;
            Ks[(d + 2) * KPITCH + lr] = kv.z;
            Ks[(d + 3) * KPITCH + lr] = kv.w;
            *(float4*)&Vs[lr * KPITCH + d] = *(const float4*)&g_v[src];
        }
        __syncthreads();

        float s[8][4] = {};
        #pragma unroll 16
        for (int dd = 0; dd < 64; dd++) {
            float4 q0 = *(const float4*)&Qs[dd * QPITCH + (ty << 3)];
            float4 q1 = *(const float4*)&Qs[dd * QPITCH + (ty << 3) + 4];
            float4 kv = *(const float4*)&Ks[dd * KPITCH + (tx << 2)];
            float qr_[8] = {q0.x, q0.y, q0.z, q0.w, q1.x, q1.y, q1.z, q1.w};
            float kr_[4] = {kv.x, kv.y, kv.z, kv.w};
            #pragma unroll
            for (int i = 0; i < 8; i++)
                #pragma unroll
                for (int j = 0; j < 4; j++)
                    s[i][j] = fmaf(qr_[i], kr_[j], s[i][j]);
        }

        #pragma unroll
        for (int i = 0; i < 8; i++) {
            float mloc = -INFINITY;
            #pragma unroll
            for (int j = 0; j < 4; j++) {
                s[i][j] *= 0.125f;
                mloc = fmaxf(mloc, s[i][j]);
            }
            #pragma unroll
            for (int off = 8; off > 0; off >>= 1)
                mloc = fmaxf(mloc, __shfl_xor_sync(0xffffffffu, mloc, off));
            const float m_new = fmaxf(mo[i], mloc);
            const float alpha = __expf(mo[i] - m_new);
            float lsum = 0.0f;
            #pragma unroll
            for (int j = 0; j < 4; j++) {
                s[i][j] = __expf(s[i][j] - m_new);
                lsum += s[i][j];
            }
            #pragma unroll
            for (int off = 8; off > 0; off >>= 1)
                lsum += __shfl_xor_sync(0xffffffffu, lsum, off);
            lo[i] = alpha * lo[i] + lsum;
            mo[i] = m_new;
            #pragma unroll
            for (int j = 0; j < 4; j++) {
                o[i][j] *= alpha;
                Pt[((tx << 2) + j) * QPITCH + (ty << 3) + i] = s[i][j];
            }
        }
        __syncthreads();

        #pragma unroll 16
        for (int kk = 0; kk < 64; kk++) {
            float4 p0 = *(const float4*)&Pt[kk * QPITCH + (ty << 3)];
            float4 p1 = *(const float4*)&Pt[kk * QPITCH + (ty << 3) + 4];
            float4 vv = *(const float4*)&Vs[kk * KPITCH + (tx << 2)];
            float pr[8] = {p0.x, p0.y, p0.z, p0.w, p1.x, p1.y, p1.z, p1.w};
            float vr[4] = {vv.x, vv.y, vv.z, vv.w};
            #pragma unroll
            for (int i = 0; i < 8; i++)
                #pragma unroll
                for (int j = 0; j < 4; j++)
                    o[i][j] = fmaf(pr[i], vr[j], o[i][j]);
        }
        __syncthreads();
    }

    const int bb = bh / HEADS;
    const int h  = bh % HEADS;
    #pragma unroll
    for (int i = 0; i < 8; i++) {
        const float inv_l = 1.0f / lo[i];
        const int l_idx = qt * QT + (ty << 3) + i;
        float4 rr = {o[i][0] * inv_l, o[i][1] * inv_l,
                     o[i][2] * inv_l, o[i][3] * inv_l};
        *(float4*)&attn_out[((size_t)bb * SEQ + l_idx) * D_MODEL + h * HD + (tx << 2)] = rr;
    }
}

// ---------------------------------------------------------------------------

static const int ATTN_SMEM = (64 * QPITCH * 2 + 64 * KPITCH * 2) * (int)sizeof(float);
static const int GEMM_SMEM = 4 * ABUF * (int)sizeof(uint32_t);   // 73728

extern "C" void kernel_launch(void* const* d_in, const int* in_sizes, int n_in,
                              void* d_out, int out_size)
{
    const float* x     = (const float*)d_in[0];
    const float* W_qkv = (const float*)d_in[1];
    const float* b_qkv = (const float*)d_in[2];
    const float* W_out = (const float*)d_in[3];
    const float* b_out = (const float*)d_in[4];
    float* out = (float*)d_out;

    cudaFuncSetAttribute(attn_kernel,
                         cudaFuncAttributeMaxDynamicSharedMemorySize, ATTN_SMEM);
    cudaFuncSetAttribute(mma_gemm_kernel<0>,
                         cudaFuncAttributeMaxDynamicSharedMemorySize, GEMM_SMEM);
    cudaFuncSetAttribute(mma_gemm_kernel<1>,
                         cudaFuncAttributeMaxDynamicSharedMemorySize, GEMM_SMEM);

    float *attn_ptr, *wqkv_t, *wout_t;
    cudaGetSymbolAddress((void**)&attn_ptr, g_attn);
    cudaGetSymbolAddress((void**)&wqkv_t, g_wqkv_t);
    cudaGetSymbolAddress((void**)&wout_t, g_wout_t);

    // Transpose weights to [N][K]
    transpose_kernel<<<dim3(N_QKV/32, D_MODEL/32), dim3(32, 8)>>>(W_qkv, wqkv_t, D_MODEL, N_QKV);
    transpose_kernel<<<dim3(D_MODEL/32, D_MODEL/32), dim3(32, 8)>>>(W_out, wout_t, D_MODEL, D_MODEL);

    // QKV projection (tf32 mma.sync)
    dim3 g1(N_QKV / 128, M_TOTAL / 128);     // 18 x 64
    mma_gemm_kernel<0><<<g1, 256, GEMM_SMEM>>>(x, wqkv_t, b_qkv, nullptr);

    // Attention (SIMT fp32)
    dim3 g2(SEQ / QT, BH);                   // 16 x 48
    attn_kernel<<<g2, 256, ATTN_SMEM>>>(attn_ptr);

    // Output projection (tf32 mma.sync)
    dim3 g3(D_MODEL / 128, M_TOTAL / 128);   // 6 x 64
    mma_gemm_kernel<1><<<g3, 256, GEMM_SMEM>>>(attn_ptr, wout_t, b_out, out);
}

// round 5
// speedup vs baseline: 3.1087x; 2.0600x over previous
#include <cuda_runtime.h>
#include <math.h>
#include <stdint.h>

#define D_MODEL 768
#define HEADS   12
#define HD      64
#define BATCH   4
#define SEQ     2048
#define M_TOTAL (BATCH*SEQ)      // 8192
#define N_QKV   (3*D_MODEL)      // 2304
#define BH      (BATCH*HEADS)    // 48
#define KDIM    768
#define NCHUNK  (KDIM/32)        // 24

// Scratch (device globals — no allocation allowed in kernel_launch)
__device__ float g_q[BH*SEQ*HD];
__device__ float g_k[BH*SEQ*HD];
__device__ float g_v[BH*SEQ*HD];
__device__ float g_attn[M_TOTAL*D_MODEL];   // also holds rounded X before attn
__device__ float g_wqkv_t[N_QKV*D_MODEL];
__device__ float g_wout_t[D_MODEL*D_MODEL];

// ---------------------------------------------------------------------------
// helpers
// ---------------------------------------------------------------------------
__device__ __forceinline__ uint32_t smem_to_u32(const void* p) {
    uint32_t a;
    asm("{ .reg .u64 t; cvta.to.shared.u64 t, %1; cvt.u32.u64 %0, t; }"
        : "=r"(a) : "l"(p));
    return a;
}
#define CP_ASYNC16(smem_addr, gptr) \
    asm volatile("cp.async.cg.shared.global [%0], [%1], 16;" \
        :: "r"(smem_addr), "l"(gptr))
#define CP_COMMIT() asm volatile("cp.async.commit_group;" ::: "memory")
#define CP_WAIT1()  asm volatile("cp.async.wait_group 1;" ::: "memory")
#define CP_WAIT0()  asm volatile("cp.async.wait_group 0;" ::: "memory")

__device__ __forceinline__ void mma_tf32u(float c[4],
    uint32_t a0, uint32_t a1, uint32_t a2, uint32_t a3,
    uint32_t b0, uint32_t b1)
{
    asm volatile(
        "mma.sync.aligned.m16n8k8.row.col.f32.tf32.tf32.f32 "
        "{%0,%1,%2,%3}, {%4,%5,%6,%7}, {%8,%9}, {%0,%1,%2,%3};"
        : "+f"(c[0]), "+f"(c[1]), "+f"(c[2]), "+f"(c[3])
        : "r"(a0), "r"(a1), "r"(a2), "r"(a3), "r"(b0), "r"(b1));
}
__device__ __forceinline__ void mma_tf32f(float c[4],
    float a0, float a1, float a2, float a3, float b0, float b1)
{
    mma_tf32u(c, __float_as_uint(a0), __float_as_uint(a1),
                 __float_as_uint(a2), __float_as_uint(a3),
                 __float_as_uint(b0), __float_as_uint(b1));
}
// round-to-nearest tf32 (13 trailing zero bits), returned as f32
__device__ __forceinline__ float rna(float f) {
    uint32_t u;
    asm("cvt.rna.tf32.f32 %0, %1;" : "=r"(u) : "f"(f));
    return __uint_as_float(u);
}

// ---------------------------------------------------------------------------
// Pre-round X to tf32 (rna) — unbiased MMA inputs
// ---------------------------------------------------------------------------
__global__ void round_kernel(const float* __restrict__ src, float* __restrict__ dst)
{
    const int i = (blockIdx.x * blockDim.x + threadIdx.x) * 4;
    float4 v = *(const float4*)&src[i];
    v.x = rna(v.x); v.y = rna(v.y); v.z = rna(v.z); v.w = rna(v.w);
    *(float4*)&dst[i] = v;
}

// ---------------------------------------------------------------------------
// Weight transpose + rna round: dst[N][K] = rna(src[K][N])
// ---------------------------------------------------------------------------
__global__ void transpose_kernel(const float* __restrict__ src,
                                 float* __restrict__ dst, int R, int C)
{
    __shared__ float t[32][33];
    const int bx = blockIdx.x * 32, by = blockIdx.y * 32;
    const int x = threadIdx.x, y = threadIdx.y;
    #pragma unroll
    for (int i = 0; i < 32; i += 8)
        t[y + i][x] = src[(size_t)(by + y + i) * C + bx + x];
    __syncthreads();
    #pragma unroll
    for (int i = 0; i < 32; i += 8)
        dst[(size_t)(bx + y + i) * R + by + x] = rna(t[x][y + i]);
}

// ---------------------------------------------------------------------------
// tf32 mma.sync GEMM (as R4): C = A @ Bt^T + bias. Inputs pre-rounded tf32.
// MODE 0: scatter rna-rounded q/k/v. MODE 1: plain fp32 out.
// ---------------------------------------------------------------------------
#define APITCH 36
#define ABUF   (128*APITCH)

template<int MODE>
__global__ __launch_bounds__(256, 2)
void mma_gemm_kernel(const float* __restrict__ A, const float* __restrict__ Bt,
                     const float* __restrict__ bias, float* __restrict__ out)
{
    extern __shared__ uint32_t smu[];
    float* smf = (float*)smu;

    const int tid  = threadIdx.x;
    const int wid  = tid >> 5;
    const int lane = tid & 31;
    const int m0 = blockIdx.y * 128;
    const int n0 = blockIdx.x * 128;
    const int wm = (wid >> 1) * 32;
    const int wn = (wid & 1) * 64;
    const uint32_t sbase = smem_to_u32(smu);

    float acc[2][8][4] = {};

    #pragma unroll
    for (int i = 0; i < 4; i++) {
        const int idx = i * 256 + tid;
        const int row = idx >> 3;
        const int seg = (idx & 7) * 4;
        CP_ASYNC16(sbase + (uint32_t)(0*ABUF + row*APITCH + seg)*4,
                   &A[(size_t)(m0 + row) * KDIM + seg]);
        CP_ASYNC16(sbase + (uint32_t)(2*ABUF + row*APITCH + seg)*4,
                   &Bt[(size_t)(n0 + row) * KDIM + seg]);
    }
    CP_COMMIT();

    const int r = lane >> 2;
    const int cl = lane & 3;

    for (int c = 0; c < NCHUNK; c++) {
        const int buf = c & 1;
        if (c + 1 < NCHUNK) {
            const int nb = (c + 1) & 1;
            const int k0 = (c + 1) * 32;
            #pragma unroll
            for (int i = 0; i < 4; i++) {
                const int idx = i * 256 + tid;
                const int row = idx >> 3;
                const int seg = (idx & 7) * 4;
                CP_ASYNC16(sbase + (uint32_t)(nb*ABUF + row*APITCH + seg)*4,
                           &A[(size_t)(m0 + row) * KDIM + k0 + seg]);
                CP_ASYNC16(sbase + (uint32_t)((2+nb)*ABUF + row*APITCH + seg)*4,
                           &Bt[(size_t)(n0 + row) * KDIM + k0 + seg]);
            }
            CP_COMMIT();
            CP_WAIT1();
        } else {
            CP_WAIT0();
        }
        __syncthreads();

        const uint32_t* as = smu + buf*ABUF + wm*APITCH;
        const uint32_t* bs = smu + (2+buf)*ABUF + wn*APITCH;

        #pragma unroll
        for (int ks = 0; ks < 4; ks++) {
            const int kb = ks * 8;
            uint32_t af[2][4];
            #pragma unroll
            for (int mi = 0; mi < 2; mi++) {
                const int base = (mi*16 + r) * APITCH + kb + cl;
                af[mi][0] = as[base];
                af[mi][1] = as[base + 8*APITCH];
                af[mi][2] = as[base + 4];
                af[mi][3] = as[base + 8*APITCH + 4];
            }
            uint32_t bf[8][2];
            #pragma unroll
            for (int ni = 0; ni < 8; ni++) {
                const int base = (ni*8 + r) * APITCH + kb + cl;
                bf[ni][0] = bs[base];
                bf[ni][1] = bs[base + 4];
            }
            #pragma unroll
            for (int mi = 0; mi < 2; mi++)
                #pragma unroll
                for (int ni = 0; ni < 8; ni++)
                    mma_tf32u(acc[mi][ni], af[mi][0], af[mi][1], af[mi][2], af[mi][3],
                              bf[ni][0], bf[ni][1]);
        }
        __syncthreads();
    }

    #pragma unroll
    for (int mi = 0; mi < 2; mi++)
        #pragma unroll
        for (int ni = 0; ni < 8; ni++) {
            const int row = wm + mi*16 + r;
            const int col = wn + ni*8 + 2*cl;
            smf[row * 132 + col]       = acc[mi][ni][0];
            smf[row * 132 + col + 1]   = acc[mi][ni][1];
            smf[(row+8) * 132 + col]   = acc[mi][ni][2];
            smf[(row+8) * 132 + col+1] = acc[mi][ni][3];
        }
    __syncthreads();

    #pragma unroll
    for (int i = 0; i < 16; i++) {
        const int f = i * 256 + tid;
        const int row  = f >> 5;
        const int col  = (f & 31) * 4;
        const int m  = m0 + row;
        const int ng = n0 + col;
        float4 v = { smf[row*132 + col + 0] + bias[ng + 0],
                     smf[row*132 + col + 1] + bias[ng + 1],
                     smf[row*132 + col + 2] + bias[ng + 2],
                     smf[row*132 + col + 3] + bias[ng + 3] };
        if (MODE == 0) {
            v.x = rna(v.x); v.y = rna(v.y); v.z = rna(v.z); v.w = rna(v.w);
            const int wsel = ng / D_MODEL;
            const int h = (ng % D_MODEL) >> 6;
            const int d = ng & 63;
            const int bb = m >> 11;
            const int l  = m & (SEQ - 1);
            float* dst = (wsel == 0) ? g_q : (wsel == 1) ? g_k : g_v;
            *(float4*)&dst[(((size_t)bb * HEADS + h) * SEQ + l) * HD + d] = v;
        } else {
            *(float4*)&out[(size_t)m * D_MODEL + ng] = v;
        }
    }
}

// ---------------------------------------------------------------------------
// Flash attention on mma.sync tf32.
// CTA = (head, 128 q). 8 warps x (16q x 64keys). 32 key tiles of 64.
// K/V smem [key][d] pitch 68, double buffered via cp.async.
// P staged through smem [q][key] pitch 68 (C-frag -> A-frag relayout).
// Q fragments cached in registers (pre-scaled by 1/8).
// ---------------------------------------------------------------------------
#define VPITCH 68
#define KVTILE (64*VPITCH)   // floats per K or V buffer

__global__ __launch_bounds__(256, 2) void attn_kernel(float* __restrict__ attn_out)
{
    extern __shared__ float sm[];
    float* Kbuf[2] = { sm,            sm + KVTILE };
    float* Vbuf[2] = { sm + 2*KVTILE, sm + 3*KVTILE };
    float* Ps = sm + 4*KVTILE;        // [128][68]

    const int tid  = threadIdx.x;
    const int wid  = tid >> 5;
    const int lane = tid & 31;
    const int r  = lane >> 2;
    const int cl = lane & 3;
    const int qt = blockIdx.x;
    const int bh = blockIdx.y;
    const size_t head_base = (size_t)bh * SEQ * HD;
    const int q0 = wid * 16;

    // cached Q fragments, pre-scaled by 1/sqrt(64)=0.125 (exact)
    float qf[8][4];
    {
        const float* Qp = &g_q[head_base + (size_t)(qt*128 + q0) * HD];
        #pragma unroll
        for (int kk = 0; kk < 8; kk++) {
            qf[kk][0] = Qp[(size_t)r      * HD + kk*8 + cl]     * 0.125f;
            qf[kk][1] = Qp[(size_t)(r+8)  * HD + kk*8 + cl]     * 0.125f;
            qf[kk][2] = Qp[(size_t)r      * HD + kk*8 + cl + 4] * 0.125f;
            qf[kk][3] = Qp[(size_t)(r+8)  * HD + kk*8 + cl + 4] * 0.125f;
        }
    }

    float o[8][4] = {};
    float mo0 = -INFINITY, mo1 = -INFINITY, lo0 = 0.0f, lo1 = 0.0f;

    const uint32_t kb[2] = { smem_to_u32(Kbuf[0]), smem_to_u32(Kbuf[1]) };
    const uint32_t vb[2] = { smem_to_u32(Vbuf[0]), smem_to_u32(Vbuf[1]) };

    // prologue: load tile 0
    #pragma unroll
    for (int i = 0; i < 4; i++) {
        const int idx = i * 256 + tid;
        const int row = idx >> 4;          // 0..63
        const int seg = (idx & 15) * 4;    // 0..60
        const size_t src = head_base + (size_t)row * HD + seg;
        CP_ASYNC16(kb[0] + (uint32_t)(row*VPITCH + seg)*4, &g_k[src]);
        CP_ASYNC16(vb[0] + (uint32_t)(row*VPITCH + seg)*4, &g_v[src]);
    }
    CP_COMMIT();

    for (int kt = 0; kt < SEQ/64; kt++) {
        const int buf = kt & 1;
        __syncthreads();   // all warps done with buf^1 from kt-1
        if (kt + 1 < SEQ/64) {
            const int nb = buf ^ 1;
            #pragma unroll
            for (int i = 0; i < 4; i++) {
                const int idx = i * 256 + tid;
                const int row = idx >> 4;
                const int seg = (idx & 15) * 4;
                const size_t src = head_base + (size_t)((kt+1)*64 + row) * HD + seg;
                CP_ASYNC16(kb[nb] + (uint32_t)(row*VPITCH + seg)*4, &g_k[src]);
                CP_ASYNC16(vb[nb] + (uint32_t)(row*VPITCH + seg)*4, &g_v[src]);
            }
            CP_COMMIT();
            CP_WAIT1();
        } else {
            CP_WAIT0();
        }
        __syncthreads();   // tile kt visible

        // ---- S = Q K^T (scaled) ----
        const float* Kc = Kbuf[buf];
        float s[8][4] = {};
        #pragma unroll
        for (int kk = 0; kk < 8; kk++) {
            #pragma unroll
            for (int nt = 0; nt < 8; nt++) {
                const int base = (nt*8 + r) * VPITCH + kk*8 + cl;
                mma_tf32f(s[nt], qf[kk][0], qf[kk][1], qf[kk][2], qf[kk][3],
                          Kc[base], Kc[base + 4]);
            }
        }

        // ---- online softmax (rows r and r+8; quad = lanes sharing r) ----
        float mx0 = -INFINITY, mx1 = -INFINITY;
        #pragma unroll
        for (int nt = 0; nt < 8; nt++) {
            mx0 = fmaxf(mx0, fmaxf(s[nt][0], s[nt][1]));
            mx1 = fmaxf(mx1, fmaxf(s[nt][2], s[nt][3]));
        }
        mx0 = fmaxf(mx0, __shfl_xor_sync(0xffffffffu, mx0, 1));
        mx0 = fmaxf(mx0, __shfl_xor_sync(0xffffffffu, mx0, 2));
        mx1 = fmaxf(mx1, __shfl_xor_sync(0xffffffffu, mx1, 1));
        mx1 = fmaxf(mx1, __shfl_xor_sync(0xffffffffu, mx1, 2));
        const float mn0 = fmaxf(mo0, mx0);
        const float mn1 = fmaxf(mo1, mx1);
        const float a0 = __expf(mo0 - mn0);
        const float a1 = __expf(mo1 - mn1);
        float sum0 = 0.0f, sum1 = 0.0f;
        #pragma unroll
        for (int nt = 0; nt < 8; nt++) {
            s[nt][0] = __expf(s[nt][0] - mn0);
            s[nt][1] = __expf(s[nt][1] - mn0);
            s[nt][2] = __expf(s[nt][2] - mn1);
            s[nt][3] = __expf(s[nt][3] - mn1);
            sum0 += s[nt][0] + s[nt][1];
            sum1 += s[nt][2] + s[nt][3];
        }
        sum0 += __shfl_xor_sync(0xffffffffu, sum0, 1);
        sum0 += __shfl_xor_sync(0xffffffffu, sum0, 2);
        sum1 += __shfl_xor_sync(0xffffffffu, sum1, 1);
        sum1 += __shfl_xor_sync(0xffffffffu, sum1, 2);
        lo0 = a0 * lo0 + sum0;  mo0 = mn0;
        lo1 = a1 * lo1 + sum1;  mo1 = mn1;
        #pragma unroll
        for (int nt = 0; nt < 8; nt++) {
            o[nt][0] *= a0; o[nt][1] *= a0;
            o[nt][2] *= a1; o[nt][3] *= a1;
        }

        // ---- stash P (rna tf32) ----
        #pragma unroll
        for (int nt = 0; nt < 8; nt++) {
            float2 p0 = { rna(s[nt][0]), rna(s[nt][1]) };
            float2 p1 = { rna(s[nt][2]), rna(s[nt][3]) };
            *(float2*)&Ps[(q0 + r)     * VPITCH + nt*8 + 2*cl] = p0;
            *(float2*)&Ps[(q0 + r + 8) * VPITCH + nt*8 + 2*cl] = p1;
        }
        __syncwarp();

        // ---- O += P V ----
        const float* Vc = Vbuf[buf];
        #pragma unroll
        for (int kk = 0; kk < 8; kk++) {
            const float pa0 = Ps[(q0 + r)     * VPITCH + kk*8 + cl];
            const float pa1 = Ps[(q0 + r + 8) * VPITCH + kk*8 + cl];
            const float pa2 = Ps[(q0 + r)     * VPITCH + kk*8 + cl + 4];
            const float pa3 = Ps[(q0 + r + 8) * VPITCH + kk*8 + cl + 4];
            #pragma unroll
            for (int nt = 0; nt < 8; nt++) {
                const float b0 = Vc[(kk*8 + cl)     * VPITCH + nt*8 + r];
                const float b1 = Vc[(kk*8 + cl + 4) * VPITCH + nt*8 + r];
                mma_tf32f(o[nt], pa0, pa1, pa2, pa3, b0, b1);
            }
        }
        __syncwarp();
    }

    // ---- epilogue: normalize, rna-round, write [B, L, H*64] ----
    const float inv0 = 1.0f / lo0;
    const float inv1 = 1.0f / lo1;
    const int bb = bh / HEADS;
    const int h  = bh % HEADS;
    const int row0 = qt*128 + q0 + r;
    #pragma unroll
    for (int nt = 0; nt < 8; nt++) {
        const int d = h * 64 + nt*8 + 2*cl;
        float2 v0 = { rna(o[nt][0] * inv0), rna(o[nt][1] * inv0) };
        float2 v1 = { rna(o[nt][2] * inv1), rna(o[nt][3] * inv1) };
        *(float2*)&attn_out[((size_t)bb * SEQ + row0)     * D_MODEL + d] = v0;
        *(float2*)&attn_out[((size_t)bb * SEQ + row0 + 8) * D_MODEL + d] = v1;
    }
}

// ---------------------------------------------------------------------------

static const int ATTN_SMEM = (4*KVTILE + 128*VPITCH) * (int)sizeof(float); // 104448
static const int GEMM_SMEM = 4 * ABUF * (int)sizeof(uint32_t);             // 73728

extern "C" void kernel_launch(void* const* d_in, const int* in_sizes, int n_in,
                              void* d_out, int out_size)
{
    const float* x     = (const float*)d_in[0];
    const float* W_qkv = (const float*)d_in[1];
    const float* b_qkv = (const float*)d_in[2];
    const float* W_out = (const float*)d_in[3];
    const float* b_out = (const float*)d_in[4];
    float* out = (float*)d_out;

    cudaFuncSetAttribute(attn_kernel,
                         cudaFuncAttributeMaxDynamicSharedMemorySize, ATTN_SMEM);
    cudaFuncSetAttribute(mma_gemm_kernel<0>,
                         cudaFuncAttributeMaxDynamicSharedMemorySize, GEMM_SMEM);
    cudaFuncSetAttribute(mma_gemm_kernel<1>,
                         cudaFuncAttributeMaxDynamicSharedMemorySize, GEMM_SMEM);

    float *attn_ptr, *wqkv_t, *wout_t;
    cudaGetSymbolAddress((void**)&attn_ptr, g_attn);
    cudaGetSymbolAddress((void**)&wqkv_t, g_wqkv_t);
    cudaGetSymbolAddress((void**)&wout_t, g_wout_t);

    // Pre-round X (rna tf32) into g_attn; round+transpose weights
    round_kernel<<<M_TOTAL*D_MODEL/(4*256), 256>>>(x, attn_ptr);
    transpose_kernel<<<dim3(N_QKV/32, D_MODEL/32), dim3(32, 8)>>>(W_qkv, wqkv_t, D_MODEL, N_QKV);
    transpose_kernel<<<dim3(D_MODEL/32, D_MODEL/32), dim3(32, 8)>>>(W_out, wout_t, D_MODEL, D_MODEL);

    // QKV projection (tf32 mma.sync), outputs rna-rounded q/k/v
    dim3 g1(N_QKV / 128, M_TOTAL / 128);
    mma_gemm_kernel<0><<<g1, 256, GEMM_SMEM>>>(attn_ptr, wqkv_t, b_qkv, nullptr);

    // Attention (tf32 mma.sync), writes rna-rounded g_attn
    dim3 g2(SEQ / 128, BH);
    attn_kernel<<<g2, 256, ATTN_SMEM>>>(attn_ptr);

    // Output projection (tf32 mma.sync), fp32 out
    dim3 g3(D_MODEL / 128, M_TOTAL / 128);
    mma_gemm_kernel<1><<<g3, 256, GEMM_SMEM>>>(attn_ptr, wout_t, b_out, out);
}

// round 8
// speedup vs baseline: 5.9080x; 1.9005x over previous
#include <cuda_runtime.h>
#include <cuda_fp16.h>
#include <math.h>
#include <stdint.h>

#define D_MODEL 768
#define HEADS   12
#define HD      64
#define BATCH   4
#define SEQ     2048
#define M_TOTAL (BATCH*SEQ)      // 8192
#define N_QKV   (3*D_MODEL)      // 2304
#define BH      (BATCH*HEADS)    // 48
#define KDIM    768
#define NCHUNK  (KDIM/64)        // 12 chunks of K=64

// Scratch (device globals)
__device__ __half g_q[BH*SEQ*HD];       // pre-scaled by 0.125
__device__ __half g_k[BH*SEQ*HD];
__device__ __half g_v[BH*SEQ*HD];       // [bh][seq][d]
__device__ __half g_vt[BH*HD*SEQ];      // [bh][d][seq]
__device__ __half g_h[M_TOTAL*D_MODEL]; // rounded X, later attn output
__device__ __half g_wqkv_t[N_QKV*KDIM];
__device__ __half g_wout_t[D_MODEL*KDIM];

// ---------------------------------------------------------------------------
__device__ __forceinline__ uint32_t smem_to_u32(const void* p) {
    uint32_t a;
    asm("{ .reg .u64 t; cvta.to.shared.u64 t, %1; cvt.u32.u64 %0, t; }"
        : "=r"(a) : "l"(p));
    return a;
}
// pack two f32 -> f16x2 in a u32 (lo -> lower 16 bits)
__device__ __forceinline__ uint32_t pack_half2(float lo, float hi) {
    uint32_t u;
    asm("cvt.rn.f16x2.f32 %0, %1, %2;" : "=r"(u) : "f"(hi), "f"(lo));
    return u;
}
#define CP_ASYNC16(smem_addr, gptr) \
    asm volatile("cp.async.cg.shared.global [%0], [%1], 16;" \
        :: "r"(smem_addr), "l"(gptr))
#define CP_COMMIT() asm volatile("cp.async.commit_group;" ::: "memory")
#define CP_WAIT1()  asm volatile("cp.async.wait_group 1;" ::: "memory")
#define CP_WAIT0()  asm volatile("cp.async.wait_group 0;" ::: "memory")

__device__ __forceinline__ void mma_f16(float c[4],
    uint32_t a0, uint32_t a1, uint32_t a2, uint32_t a3,
    uint32_t b0, uint32_t b1)
{
    asm volatile(
        "mma.sync.aligned.m16n8k16.row.col.f32.f16.f16.f32 "
        "{%0,%1,%2,%3}, {%4,%5,%6,%7}, {%8,%9}, {%0,%1,%2,%3};"
        : "+f"(c[0]), "+f"(c[1]), "+f"(c[2]), "+f"(c[3])
        : "r"(a0), "r"(a1), "r"(a2), "r"(a3), "r"(b0), "r"(b1));
}

// ---------------------------------------------------------------------------
// X -> half
__global__ void convert_x_kernel(const float* __restrict__ src, __half* __restrict__ dst)
{
    const int i = (blockIdx.x * blockDim.x + threadIdx.x) * 4;
    float4 v = *(const float4*)&src[i];
    ((uint32_t*)dst)[i/2]     = pack_half2(v.x, v.y);
    ((uint32_t*)dst)[i/2 + 1] = pack_half2(v.z, v.w);
}

// W transpose + half: dst[N][K] = half(src[K][N])
__global__ void transpose_w_kernel(const float* __restrict__ src,
                                   __half* __restrict__ dst, int R, int C)
{
    __shared__ float t[32][33];
    const int bx = blockIdx.x * 32, by = blockIdx.y * 32;
    const int x = threadIdx.x, y = threadIdx.y;
    #pragma unroll
    for (int i = 0; i < 32; i += 8)
        t[y + i][x] = src[(size_t)(by + y + i) * C + bx + x];
    __syncthreads();
    #pragma unroll
    for (int i = 0; i < 32; i += 8)
        dst[(size_t)(bx + y + i) * R + by + x] = __float2half_rn(t[x][y + i]);
}

// V transpose (half): [bh][seq][64] -> [bh][64][seq]
__global__ void transpose_v_kernel()
{
    __shared__ __half t[32][33];
    const int l0 = blockIdx.x * 32, d0 = blockIdx.y * 32, bh = blockIdx.z;
    const int x = threadIdx.x, y = threadIdx.y;
    const size_t src_base = (size_t)bh * SEQ * HD;
    const size_t dst_base = (size_t)bh * HD * SEQ;
    #pragma unroll
    for (int i = 0; i < 32; i += 8)
        t[y + i][x] = g_v[src_base + (size_t)(l0 + y + i) * HD + d0 + x];
    __syncthreads();
    #pragma unroll
    for (int i = 0; i < 32; i += 8)
        g_vt[dst_base + (size_t)(d0 + y + i) * SEQ + l0 + x] = t[x][y + i];
}

// ---------------------------------------------------------------------------
// fp16 mma.sync GEMM: C = A @ Bt^T + bias (fp32 acc).
// CTA 128x128, 8 warps of 32m x 64n, K chunks of 64 (4 k16 steps), dbl buf.
// Each smem row = 64 halfs (128 B) = 8 x 16B segs -> 1024 cp.asyncs/operand.
// MODE 0: scatter half q(*0.125)/k/v.  MODE 1: fp32 out.
// ---------------------------------------------------------------------------
#define HPU   36                 // u32 per smem row (72 halfs, 64 used)
#define ABUFU (128*HPU)          // u32 per operand buffer

template<int MODE>
__global__ __launch_bounds__(256, 2)
void mma_gemm_kernel(const __half* __restrict__ A, const __half* __restrict__ Bt,
                     const float* __restrict__ bias, float* __restrict__ out)
{
    extern __shared__ uint32_t smu[];
    float* smf = (float*)smu;

    const int tid  = threadIdx.x;
    const int wid  = tid >> 5;
    const int lane = tid & 31;
    const int m0 = blockIdx.y * 128;
    const int n0 = blockIdx.x * 128;
    const int wm = (wid >> 1) * 32;
    const int wn = (wid & 1) * 64;
    const uint32_t sbase = smem_to_u32(smu);
    const int r = lane >> 2;
    const int cl = lane & 3;

    float acc[2][8][4] = {};

    // chunk 0: 128 rows x 8 segs of 16B per operand
    #pragma unroll
    for (int i = 0; i < 4; i++) {
        const int idx = i * 256 + tid;           // 0..1023
        const int row = idx >> 3;                // 0..127
        const int seg = (idx & 7) * 8;           // halfs 0..56
        CP_ASYNC16(sbase + (uint32_t)(0*ABUFU + row*HPU)*4 + seg*2,
                   &A[(size_t)(m0 + row) * KDIM + seg]);
        CP_ASYNC16(sbase + (uint32_t)(2*ABUFU + row*HPU)*4 + seg*2,
                   &Bt[(size_t)(n0 + row) * KDIM + seg]);
    }
    CP_COMMIT();

    for (int c = 0; c < NCHUNK; c++) {
        const int buf = c & 1;
        if (c + 1 < NCHUNK) {
            const int nb = (c + 1) & 1;
            const int k0 = (c + 1) * 64;
            #pragma unroll
            for (int i = 0; i < 4; i++) {
                const int idx = i * 256 + tid;
                const int row = idx >> 3;
                const int seg = (idx & 7) * 8;
                CP_ASYNC16(sbase + (uint32_t)(nb*ABUFU + row*HPU)*4 + seg*2,
                           &A[(size_t)(m0 + row) * KDIM + k0 + seg]);
                CP_ASYNC16(sbase + (uint32_t)((2+nb)*ABUFU + row*HPU)*4 + seg*2,
                           &Bt[(size_t)(n0 + row) * KDIM + k0 + seg]);
            }
            CP_COMMIT();
            CP_WAIT1();
        } else {
            CP_WAIT0();
        }
        __syncthreads();

        const uint32_t* as = smu + buf*ABUFU + wm*HPU;
        const uint32_t* bs = smu + (2+buf)*ABUFU + wn*HPU;

        #pragma unroll
        for (int ks = 0; ks < 4; ks++) {
            const int kbu = ks * 8;              // u32 offset (16 halfs)
            uint32_t af[2][4];
            #pragma unroll
            for (int mi = 0; mi < 2; mi++) {
                const int base = (mi*16 + r) * HPU + kbu + cl;
                af[mi][0] = as[base];
                af[mi][1] = as[base + 8*HPU];
                af[mi][2] = as[base + 4];
                af[mi][3] = as[base + 8*HPU + 4];
            }
            uint32_t bf[8][2];
            #pragma unroll
            for (int ni = 0; ni < 8; ni++) {
                const int base = (ni*8 + r) * HPU + kbu + cl;
                bf[ni][0] = bs[base];
                bf[ni][1] = bs[base + 4];
            }
            #pragma unroll
            for (int mi = 0; mi < 2; mi++)
                #pragma unroll
                for (int ni = 0; ni < 8; ni++)
                    mma_f16(acc[mi][ni], af[mi][0], af[mi][1], af[mi][2], af[mi][3],
                            bf[ni][0], bf[ni][1]);
        }
        __syncthreads();
    }

    // stage C in smem (float [128][132])
    #pragma unroll
    for (int mi = 0; mi < 2; mi++)
        #pragma unroll
        for (int ni = 0; ni < 8; ni++) {
            const int row = wm + mi*16 + r;
            const int col = wn + ni*8 + 2*cl;
            smf[row * 132 + col]       = acc[mi][ni][0];
            smf[row * 132 + col + 1]   = acc[mi][ni][1];
            smf[(row+8) * 132 + col]   = acc[mi][ni][2];
            smf[(row+8) * 132 + col+1] = acc[mi][ni][3];
        }
    __syncthreads();

    #pragma unroll
    for (int i = 0; i < 16; i++) {
        const int f = i * 256 + tid;
        const int row  = f >> 5;
        const int col  = (f & 31) * 4;
        const int m  = m0 + row;
        const int ng = n0 + col;
        float4 v = { smf[row*132 + col + 0] + bias[ng + 0],
                     smf[row*132 + col + 1] + bias[ng + 1],
                     smf[row*132 + col + 2] + bias[ng + 2],
                     smf[row*132 + col + 3] + bias[ng + 3] };
        if (MODE == 0) {
            const int wsel = ng / D_MODEL;
            if (wsel == 0) { v.x *= 0.125f; v.y *= 0.125f; v.z *= 0.125f; v.w *= 0.125f; }
            const int h = (ng % D_MODEL) >> 6;
            const int d = ng & 63;
            const int bb = m >> 11;
            const int l  = m & (SEQ - 1);
            __half* dst = (wsel == 0) ? g_q : (wsel == 1) ? g_k : g_v;
            const size_t off = (((size_t)bb * HEADS + h) * SEQ + l) * HD + d;
            ((uint32_t*)dst)[off/2]     = pack_half2(v.x, v.y);
            ((uint32_t*)dst)[off/2 + 1] = pack_half2(v.z, v.w);
        } else {
            *(float4*)&out[(size_t)m * D_MODEL + ng] = v;
        }
    }
}

// ---------------------------------------------------------------------------
// Flash attention on fp16 mma.sync (m16n8k16).
// CTA = (head, 128 q). 8 warps x (16q x 64keys). K tiles of 64.
// K smem [key][d], VT smem [d][key], both 64 rows x 64 halfs (8 segs/row).
// P staged through smem [q][key] half (pitch 72).
// ---------------------------------------------------------------------------
#define AHP   36                 // u32 per 72-half row
#define KVTU  (64*AHP)           // u32 per K or VT buffer

__global__ __launch_bounds__(256, 2) void attn_kernel(__half* __restrict__ attn_out)
{
    extern __shared__ uint32_t smA[];
    uint32_t* Kb[2]  = { smA,           smA + KVTU };
    uint32_t* Vb[2]  = { smA + 2*KVTU,  smA + 3*KVTU };
    uint32_t* Ps     = smA + 4*KVTU;    // [128][36] u32 = [128][72] half

    const int tid  = threadIdx.x;
    const int wid  = tid >> 5;
    const int lane = tid & 31;
    const int r  = lane >> 2;
    const int cl = lane & 3;
    const int qt = blockIdx.x;
    const int bh = blockIdx.y;
    const size_t head_base = (size_t)bh * SEQ * HD;   // halfs
    const int q0 = wid * 16;

    // Q fragments (g_q pre-scaled): 4 ksteps x 4 regs
    uint32_t qf[4][4];
    {
        const uint32_t* Qp = (const uint32_t*)&g_q[head_base + (size_t)(qt*128 + q0) * HD];
        #pragma unroll
        for (int kk = 0; kk < 4; kk++) {
            qf[kk][0] = Qp[(size_t)r     * 32 + kk*8 + cl];
            qf[kk][1] = Qp[(size_t)(r+8) * 32 + kk*8 + cl];
            qf[kk][2] = Qp[(size_t)r     * 32 + kk*8 + cl + 4];
            qf[kk][3] = Qp[(size_t)(r+8) * 32 + kk*8 + cl + 4];
        }
    }

    float o[8][4] = {};
    float mo0 = -INFINITY, mo1 = -INFINITY, lo0 = 0.0f, lo1 = 0.0f;

    const uint32_t kb[2] = { smem_to_u32(Kb[0]), smem_to_u32(Kb[1]) };
    const uint32_t vb[2] = { smem_to_u32(Vb[0]), smem_to_u32(Vb[1]) };
    const size_t vt_base = (size_t)bh * HD * SEQ;

    // prologue tile 0: K 64 rows x 8 segs (512), VT 64 rows x 8 segs (512)
    #pragma unroll
    for (int i = 0; i < 4; i++) {
        const int idx = i * 256 + tid;     // 0..1023
        const int rr  = (idx >> 3) & 63;
        const int seg = (idx & 7) * 8;
        if (idx < 512) {
            CP_ASYNC16(kb[0] + (uint32_t)(rr*AHP)*4 + seg*2,
                       (const char*)&g_k[head_base + (size_t)rr * HD + seg]);
        } else {
            CP_ASYNC16(vb[0] + (uint32_t)(rr*AHP)*4 + seg*2,
                       (const char*)&g_vt[vt_base + (size_t)rr * SEQ + seg]);
        }
    }
    CP_COMMIT();

    for (int kt = 0; kt < SEQ/64; kt++) {
        const int buf = kt & 1;
        __syncthreads();
        if (kt + 1 < SEQ/64) {
            const int nb = buf ^ 1;
            #pragma unroll
            for (int i = 0; i < 4; i++) {
                const int idx = i * 256 + tid;
                const int rr  = (idx >> 3) & 63;
                const int seg = (idx & 7) * 8;
                if (idx < 512) {
                    CP_ASYNC16(kb[nb] + (uint32_t)(rr*AHP)*4 + seg*2,
                               (const char*)&g_k[head_base + (size_t)((kt+1)*64 + rr) * HD + seg]);
                } else {
                    CP_ASYNC16(vb[nb] + (uint32_t)(rr*AHP)*4 + seg*2,
                               (const char*)&g_vt[vt_base + (size_t)rr * SEQ + (kt+1)*64 + seg]);
                }
            }
            CP_COMMIT();
            CP_WAIT1();
        } else {
            CP_WAIT0();
        }
        __syncthreads();

        // ---- S = Q K^T ----
        const uint32_t* Kc = Kb[buf];
        float s[8][4] = {};
        #pragma unroll
        for (int kk = 0; kk < 4; kk++) {
            #pragma unroll
            for (int nt = 0; nt < 8; nt++) {
                const int base = (nt*8 + r) * AHP + kk*8 + cl;
                mma_f16(s[nt], qf[kk][0], qf[kk][1], qf[kk][2], qf[kk][3],
                        Kc[base], Kc[base + 4]);
            }
        }

        // ---- online softmax ----
        float mx0 = -INFINITY, mx1 = -INFINITY;
        #pragma unroll
        for (int nt = 0; nt < 8; nt++) {
            mx0 = fmaxf(mx0, fmaxf(s[nt][0], s[nt][1]));
            mx1 = fmaxf(mx1, fmaxf(s[nt][2], s[nt][3]));
        }
        mx0 = fmaxf(mx0, __shfl_xor_sync(0xffffffffu, mx0, 1));
        mx0 = fmaxf(mx0, __shfl_xor_sync(0xffffffffu, mx0, 2));
        mx1 = fmaxf(mx1, __shfl_xor_sync(0xffffffffu, mx1, 1));
        mx1 = fmaxf(mx1, __shfl_xor_sync(0xffffffffu, mx1, 2));
        const float mn0 = fmaxf(mo0, mx0);
        const float mn1 = fmaxf(mo1, mx1);
        const float a0 = __expf(mo0 - mn0);
        const float a1 = __expf(mo1 - mn1);
        float sum0 = 0.0f, sum1 = 0.0f;
        #pragma unroll
        for (int nt = 0; nt < 8; nt++) {
            s[nt][0] = __expf(s[nt][0] - mn0);
            s[nt][1] = __expf(s[nt][1] - mn0);
            s[nt][2] = __expf(s[nt][2] - mn1);
            s[nt][3] = __expf(s[nt][3] - mn1);
            sum0 += s[nt][0] + s[nt][1];
            sum1 += s[nt][2] + s[nt][3];
        }
        sum0 += __shfl_xor_sync(0xffffffffu, sum0, 1);
        sum0 += __shfl_xor_sync(0xffffffffu, sum0, 2);
        sum1 += __shfl_xor_sync(0xffffffffu, sum1, 1);
        sum1 += __shfl_xor_sync(0xffffffffu, sum1, 2);
        lo0 = a0 * lo0 + sum0;  mo0 = mn0;
        lo1 = a1 * lo1 + sum1;  mo1 = mn1;
        #pragma unroll
        for (int nt = 0; nt < 8; nt++) {
            o[nt][0] *= a0; o[nt][1] *= a0;
            o[nt][2] *= a1; o[nt][3] *= a1;
        }

        // ---- stash P as half ----
        #pragma unroll
        for (int nt = 0; nt < 8; nt++) {
            Ps[(q0 + r)     * AHP + nt*4 + cl] = pack_half2(s[nt][0], s[nt][1]);
            Ps[(q0 + r + 8) * AHP + nt*4 + cl] = pack_half2(s[nt][2], s[nt][3]);
        }
        __syncwarp();

        // ---- O += P V (A = P from smem, B = VT) ----
        const uint32_t* Vc = Vb[buf];
        #pragma unroll
        for (int kk = 0; kk < 4; kk++) {
            const uint32_t pa0 = Ps[(q0 + r)     * AHP + kk*8 + cl];
            const uint32_t pa1 = Ps[(q0 + r + 8) * AHP + kk*8 + cl];
            const uint32_t pa2 = Ps[(q0 + r)     * AHP + kk*8 + cl + 4];
            const uint32_t pa3 = Ps[(q0 + r + 8) * AHP + kk*8 + cl + 4];
            #pragma unroll
            for (int nt = 0; nt < 8; nt++) {
                const int base = (nt*8 + r) * AHP + kk*8 + cl;
                mma_f16(o[nt], pa0, pa1, pa2, pa3, Vc[base], Vc[base + 4]);
            }
        }
        __syncwarp();
    }

    // ---- epilogue: normalize, write half [B, L, H*64] ----
    const float inv0 = 1.0f / lo0;
    const float inv1 = 1.0f / lo1;
    const int bb = bh / HEADS;
    const int h  = bh % HEADS;
    const int row0 = qt*128 + q0 + r;
    #pragma unroll
    for (int nt = 0; nt < 8; nt++) {
        const int d = h * 64 + nt*8 + 2*cl;
        ((uint32_t*)attn_out)[(((size_t)bb * SEQ + row0)     * D_MODEL + d)/2] =
            pack_half2(o[nt][0] * inv0, o[nt][1] * inv0);
        ((uint32_t*)attn_out)[(((size_t)bb * SEQ + row0 + 8) * D_MODEL + d)/2] =
            pack_half2(o[nt][2] * inv1, o[nt][3] * inv1);
    }
}

// ---------------------------------------------------------------------------

static const int ATTN_SMEM = (4*KVTU + 128*AHP) * (int)sizeof(uint32_t); // 55296
static const int GEMM_SMEM = 4 * ABUFU * (int)sizeof(uint32_t);          // 73728

extern "C" void kernel_launch(void* const* d_in, const int* in_sizes, int n_in,
                              void* d_out, int out_size)
{
    const float* x     = (const float*)d_in[0];
    const float* W_qkv = (const float*)d_in[1];
    const float* b_qkv = (const float*)d_in[2];
    const float* W_out = (const float*)d_in[3];
    const float* b_out = (const float*)d_in[4];
    float* out = (float*)d_out;

    cudaFuncSetAttribute(attn_kernel,
                         cudaFuncAttributeMaxDynamicSharedMemorySize, ATTN_SMEM);
    cudaFuncSetAttribute(mma_gemm_kernel<0>,
                         cudaFuncAttributeMaxDynamicSharedMemorySize, GEMM_SMEM);
    cudaFuncSetAttribute(mma_gemm_kernel<1>,
                         cudaFuncAttributeMaxDynamicSharedMemorySize, GEMM_SMEM);

    __half *xh, *wqkv_t, *wout_t, *attn_h;
    cudaGetSymbolAddress((void**)&xh, g_h);
    cudaGetSymbolAddress((void**)&wqkv_t, g_wqkv_t);
    cudaGetSymbolAddress((void**)&wout_t, g_wout_t);
    attn_h = xh;   // reuse: X consumed by qkv gemm before attn writes

    convert_x_kernel<<<M_TOTAL*D_MODEL/(4*256), 256>>>(x, xh);
    transpose_w_kernel<<<dim3(N_QKV/32, KDIM/32), dim3(32, 8)>>>(W_qkv, wqkv_t, KDIM, N_QKV);
    transpose_w_kernel<<<dim3(D_MODEL/32, KDIM/32), dim3(32, 8)>>>(W_out, wout_t, KDIM, D_MODEL);

    dim3 g1(N_QKV / 128, M_TOTAL / 128);
    mma_gemm_kernel<0><<<g1, 256, GEMM_SMEM>>>(xh, wqkv_t, b_qkv, nullptr);

    transpose_v_kernel<<<dim3(SEQ/32, HD/32, BH), dim3(32, 8)>>>();

    dim3 g2(SEQ / 128, BH);
    attn_kernel<<<g2, 256, ATTN_SMEM>>>(attn_h);

    dim3 g3(D_MODEL / 128, M_TOTAL / 128);
    mma_gemm_kernel<1><<<g3, 256, GEMM_SMEM>>>(attn_h, wout_t, b_out, out);
}

// round 9
// speedup vs baseline: 6.3454x; 1.0740x over previous
#include <cuda_runtime.h>
#include <cuda_fp16.h>
#include <math.h>
#include <stdint.h>

#define D_MODEL 768
#define HEADS   12
#define HD      64
#define BATCH   4
#define SEQ     2048
#define M_TOTAL (BATCH*SEQ)      // 8192
#define N_QKV   (3*D_MODEL)      // 2304
#define BH      (BATCH*HEADS)    // 48
#define KDIM    768
#define NCHUNK  (KDIM/64)        // 12 chunks of K=64

// q scale: 1/sqrt(64) * log2(e)  (softmax done in exp2 domain)
#define QSCALE 0.1803368801111306f

// Scratch (device globals)
__device__ __half g_q[BH*SEQ*HD];       // pre-scaled by QSCALE
__device__ __half g_k[BH*SEQ*HD];
__device__ __half g_vt[BH*HD*SEQ];      // [bh][d][seq]
__device__ __half g_h[M_TOTAL*D_MODEL]; // half X, later attn output
__device__ __half g_wqkv_t[N_QKV*KDIM];
__device__ __half g_wout_t[D_MODEL*KDIM];

// ---------------------------------------------------------------------------
__device__ __forceinline__ uint32_t smem_to_u32(const void* p) {
    uint32_t a;
    asm("{ .reg .u64 t; cvta.to.shared.u64 t, %1; cvt.u32.u64 %0, t; }"
        : "=r"(a) : "l"(p));
    return a;
}
// pack two f32 -> f16x2 in a u32 (lo -> lower 16 bits)
__device__ __forceinline__ uint32_t pack_half2(float lo, float hi) {
    uint32_t u;
    asm("cvt.rn.f16x2.f32 %0, %1, %2;" : "=r"(u) : "f"(hi), "f"(lo));
    return u;
}
#define CP_ASYNC16(smem_addr, gptr) \
    asm volatile("cp.async.cg.shared.global [%0], [%1], 16;" \
        :: "r"(smem_addr), "l"(gptr))
#define CP_COMMIT() asm volatile("cp.async.commit_group;" ::: "memory")
#define CP_WAIT1()  asm volatile("cp.async.wait_group 1;" ::: "memory")
#define CP_WAIT0()  asm volatile("cp.async.wait_group 0;" ::: "memory")

__device__ __forceinline__ void mma_f16(float c[4],
    uint32_t a0, uint32_t a1, uint32_t a2, uint32_t a3,
    uint32_t b0, uint32_t b1)
{
    asm volatile(
        "mma.sync.aligned.m16n8k16.row.col.f32.f16.f16.f32 "
        "{%0,%1,%2,%3}, {%4,%5,%6,%7}, {%8,%9}, {%0,%1,%2,%3};"
        : "+f"(c[0]), "+f"(c[1]), "+f"(c[2]), "+f"(c[3])
        : "r"(a0), "r"(a1), "r"(a2), "r"(a3), "r"(b0), "r"(b1));
}

// ---------------------------------------------------------------------------
// X -> half
__global__ void convert_x_kernel(const float* __restrict__ src, __half* __restrict__ dst)
{
    const int i = (blockIdx.x * blockDim.x + threadIdx.x) * 4;
    float4 v = *(const float4*)&src[i];
    ((uint32_t*)dst)[i/2]     = pack_half2(v.x, v.y);
    ((uint32_t*)dst)[i/2 + 1] = pack_half2(v.z, v.w);
}

// W transpose + half: dst[N][K] = half(src[K][N])
__global__ void transpose_w_kernel(const float* __restrict__ src,
                                   __half* __restrict__ dst, int R, int C)
{
    __shared__ float t[32][33];
    const int bx = blockIdx.x * 32, by = blockIdx.y * 32;
    const int x = threadIdx.x, y = threadIdx.y;
    #pragma unroll
    for (int i = 0; i < 32; i += 8)
        t[y + i][x] = src[(size_t)(by + y + i) * C + bx + x];
    __syncthreads();
    #pragma unroll
    for (int i = 0; i < 32; i += 8)
        dst[(size_t)(bx + y + i) * R + by + x] = __float2half_rn(t[x][y + i]);
}

// ---------------------------------------------------------------------------
// fp16 mma.sync GEMM: C = A @ Bt^T + bias (fp32 acc).
// CTA 128x128, 8 warps of 32m x 64n, K chunks of 64, cp.async dbl buf.
// MODE 0: scatter q(*QSCALE)/k to [bh][seq][64]; V written TRANSPOSED to
//         g_vt [bh][d][seq].  MODE 1: fp32 [M][768] out.
// ---------------------------------------------------------------------------
#define HPU   36                 // u32 per smem row (72 halfs, 64 used)
#define ABUFU (128*HPU)          // u32 per operand buffer
#define CPITCH 133               // floats, epilogue staging pitch

template<int MODE>
__global__ __launch_bounds__(256, 2)
void mma_gemm_kernel(const __half* __restrict__ A, const __half* __restrict__ Bt,
                     const float* __restrict__ bias, float* __restrict__ out)
{
    extern __shared__ uint32_t smu[];
    float* smf = (float*)smu;

    const int tid  = threadIdx.x;
    const int wid  = tid >> 5;
    const int lane = tid & 31;
    const int m0 = blockIdx.y * 128;
    const int n0 = blockIdx.x * 128;
    const int wm = (wid >> 1) * 32;
    const int wn = (wid & 1) * 64;
    const uint32_t sbase = smem_to_u32(smu);
    const int r = lane >> 2;
    const int cl = lane & 3;

    float acc[2][8][4] = {};

    // chunk 0: 128 rows x 8 segs of 16B per operand
    #pragma unroll
    for (int i = 0; i < 4; i++) {
        const int idx = i * 256 + tid;           // 0..1023
        const int row = idx >> 3;                // 0..127
        const int seg = (idx & 7) * 8;           // halfs 0..56
        CP_ASYNC16(sbase + (uint32_t)(0*ABUFU + row*HPU)*4 + seg*2,
                   &A[(size_t)(m0 + row) * KDIM + seg]);
        CP_ASYNC16(sbase + (uint32_t)(2*ABUFU + row*HPU)*4 + seg*2,
                   &Bt[(size_t)(n0 + row) * KDIM + seg]);
    }
    CP_COMMIT();

    for (int c = 0; c < NCHUNK; c++) {
        const int buf = c & 1;
        if (c + 1 < NCHUNK) {
            const int nb = (c + 1) & 1;
            const int k0 = (c + 1) * 64;
            #pragma unroll
            for (int i = 0; i < 4; i++) {
                const int idx = i * 256 + tid;
                const int row = idx >> 3;
                const int seg = (idx & 7) * 8;
                CP_ASYNC16(sbase + (uint32_t)(nb*ABUFU + row*HPU)*4 + seg*2,
                           &A[(size_t)(m0 + row) * KDIM + k0 + seg]);
                CP_ASYNC16(sbase + (uint32_t)((2+nb)*ABUFU + row*HPU)*4 + seg*2,
                           &Bt[(size_t)(n0 + row) * KDIM + k0 + seg]);
            }
            CP_COMMIT();
            CP_WAIT1();
        } else {
            CP_WAIT0();
        }
        __syncthreads();

        const uint32_t* as = smu + buf*ABUFU + wm*HPU;
        const uint32_t* bs = smu + (2+buf)*ABUFU + wn*HPU;

        #pragma unroll
        for (int ks = 0; ks < 4; ks++) {
            const int kbu = ks * 8;              // u32 offset (16 halfs)
            uint32_t af[2][4];
            #pragma unroll
            for (int mi = 0; mi < 2; mi++) {
                const int base = (mi*16 + r) * HPU + kbu + cl;
                af[mi][0] = as[base];
                af[mi][1] = as[base + 8*HPU];
                af[mi][2] = as[base + 4];
                af[mi][3] = as[base + 8*HPU + 4];
            }
            uint32_t bf[8][2];
            #pragma unroll
            for (int ni = 0; ni < 8; ni++) {
                const int base = (ni*8 + r) * HPU + kbu + cl;
                bf[ni][0] = bs[base];
                bf[ni][1] = bs[base + 4];
            }
            #pragma unroll
            for (int mi = 0; mi < 2; mi++)
                #pragma unroll
                for (int ni = 0; ni < 8; ni++)
                    mma_f16(acc[mi][ni], af[mi][0], af[mi][1], af[mi][2], af[mi][3],
                            bf[ni][0], bf[ni][1]);
        }
        __syncthreads();
    }

    // stage C in smem (float [128][CPITCH])
    #pragma unroll
    for (int mi = 0; mi < 2; mi++)
        #pragma unroll
        for (int ni = 0; ni < 8; ni++) {
            const int row = wm + mi*16 + r;
            const int col = wn + ni*8 + 2*cl;
            smf[row * CPITCH + col]       = acc[mi][ni][0];
            smf[row * CPITCH + col + 1]   = acc[mi][ni][1];
            smf[(row+8) * CPITCH + col]   = acc[mi][ni][2];
            smf[(row+8) * CPITCH + col+1] = acc[mi][ni][3];
        }
    __syncthreads();

    if (MODE == 1) {
        #pragma unroll
        for (int i = 0; i < 16; i++) {
            const int f = i * 256 + tid;
            const int row  = f >> 5;
            const int col  = (f & 31) * 4;
            const int m  = m0 + row;
            const int ng = n0 + col;
            float4 v = { smf[row*CPITCH + col + 0] + bias[ng + 0],
                         smf[row*CPITCH + col + 1] + bias[ng + 1],
                         smf[row*CPITCH + col + 2] + bias[ng + 2],
                         smf[row*CPITCH + col + 3] + bias[ng + 3] };
            *(float4*)&out[(size_t)m * D_MODEL + ng] = v;
        }
    } else {
        const int wsel = n0 / D_MODEL;
        if (wsel < 2) {
            // q or k: row-major scatter [bh][seq][64]
            __half* dst = (wsel == 0) ? g_q : g_k;
            const float sc = (wsel == 0) ? QSCALE : 1.0f;
            #pragma unroll
            for (int i = 0; i < 16; i++) {
                const int f = i * 256 + tid;
                const int row  = f >> 5;
                const int col  = (f & 31) * 4;
                const int m  = m0 + row;
                const int ng = n0 + col;
                float4 v = { (smf[row*CPITCH + col + 0] + bias[ng + 0]) * sc,
                             (smf[row*CPITCH + col + 1] + bias[ng + 1]) * sc,
                             (smf[row*CPITCH + col + 2] + bias[ng + 2]) * sc,
                             (smf[row*CPITCH + col + 3] + bias[ng + 3]) * sc };
                const int h = (ng % D_MODEL) >> 6;
                const int d = ng & 63;
                const int bb = m >> 11;
                const int l  = m & (SEQ - 1);
                const size_t off = (((size_t)bb * HEADS + h) * SEQ + l) * HD + d;
                ((uint32_t*)dst)[off/2]     = pack_half2(v.x, v.y);
                ((uint32_t*)dst)[off/2 + 1] = pack_half2(v.z, v.w);
            }
        } else {
            // v: transposed scatter into g_vt [bh][d][seq], coalesced along seq
            const int bb = m0 >> 11;
            const int l0 = m0 & (SEQ - 1);
            #pragma unroll
            for (int it = 0; it < 32; it++) {
                const int idx = it * 256 + tid;   // 0..8191
                const int d  = idx >> 6;          // 0..127 (tile col)
                const int l2 = idx & 63;          // pair index along rows
                const int ng = n0 + d;
                const float bv = bias[ng];
                const int h  = (ng % D_MODEL) >> 6;
                const int dd = ng & 63;
                const float v0 = smf[(2*l2)   * CPITCH + d] + bv;
                const float v1 = smf[(2*l2+1) * CPITCH + d] + bv;
                const size_t off = ((size_t)(bb * HEADS + h) * HD + dd) * SEQ + l0 + 2*l2;
                ((uint32_t*)g_vt)[off/2] = pack_half2(v0, v1);
            }
        }
    }
}

// ---------------------------------------------------------------------------
// Flash attention on fp16 mma.sync (m16n8k16).
// CTA = (head, 128 q). 8 warps x (16q x 64keys). K tiles of 64.
// K smem [key][d], VT smem [d][key], cp.async double buffered.
// P stays in registers: S C-fragments re-packed directly as PV A-fragments.
// Softmax in exp2 domain (q pre-scaled by 0.125*log2e).
// ---------------------------------------------------------------------------
#define AHP   36                 // u32 per 72-half row
#define KVTU  (64*AHP)           // u32 per K or VT buffer

__global__ __launch_bounds__(256, 2) void attn_kernel(__half* __restrict__ attn_out)
{
    extern __shared__ uint32_t smA[];
    uint32_t* Kb[2]  = { smA,           smA + KVTU };
    uint32_t* Vb[2]  = { smA + 2*KVTU,  smA + 3*KVTU };

    const int tid  = threadIdx.x;
    const int wid  = tid >> 5;
    const int lane = tid & 31;
    const int r  = lane >> 2;
    const int cl = lane & 3;
    const int qt = blockIdx.x;
    const int bh = blockIdx.y;
    const size_t head_base = (size_t)bh * SEQ * HD;   // halfs
    const int q0 = wid * 16;

    // Q fragments (g_q pre-scaled): 4 ksteps x 4 regs
    uint32_t qf[4][4];
    {
        const uint32_t* Qp = (const uint32_t*)&g_q[head_base + (size_t)(qt*128 + q0) * HD];
        #pragma unroll
        for (int kk = 0; kk < 4; kk++) {
            qf[kk][0] = Qp[(size_t)r     * 32 + kk*8 + cl];
            qf[kk][1] = Qp[(size_t)(r+8) * 32 + kk*8 + cl];
            qf[kk][2] = Qp[(size_t)r     * 32 + kk*8 + cl + 4];
            qf[kk][3] = Qp[(size_t)(r+8) * 32 + kk*8 + cl + 4];
        }
    }

    float o[8][4] = {};
    float mo0 = -INFINITY, mo1 = -INFINITY, lo0 = 0.0f, lo1 = 0.0f;

    const uint32_t kb[2] = { smem_to_u32(Kb[0]), smem_to_u32(Kb[1]) };
    const uint32_t vb[2] = { smem_to_u32(Vb[0]), smem_to_u32(Vb[1]) };
    const size_t vt_base = (size_t)bh * HD * SEQ;

    // prologue tile 0: K 64 rows x 8 segs (512), VT 64 rows x 8 segs (512)
    #pragma unroll
    for (int i = 0; i < 4; i++) {
        const int idx = i * 256 + tid;     // 0..1023
        const int rr  = (idx >> 3) & 63;
        const int seg = (idx & 7) * 8;
        if (idx < 512) {
            CP_ASYNC16(kb[0] + (uint32_t)(rr*AHP)*4 + seg*2,
                       (const char*)&g_k[head_base + (size_t)rr * HD + seg]);
        } else {
            CP_ASYNC16(vb[0] + (uint32_t)(rr*AHP)*4 + seg*2,
                       (const char*)&g_vt[vt_base + (size_t)rr * SEQ + seg]);
        }
    }
    CP_COMMIT();

    for (int kt = 0; kt < SEQ/64; kt++) {
        const int buf = kt & 1;
        __syncthreads();
        if (kt + 1 < SEQ/64) {
            const int nb = buf ^ 1;
            #pragma unroll
            for (int i = 0; i < 4; i++) {
                const int idx = i * 256 + tid;
                const int rr  = (idx >> 3) & 63;
                const int seg = (idx & 7) * 8;
                if (idx < 512) {
                    CP_ASYNC16(kb[nb] + (uint32_t)(rr*AHP)*4 + seg*2,
                               (const char*)&g_k[head_base + (size_t)((kt+1)*64 + rr) * HD + seg]);
                } else {
                    CP_ASYNC16(vb[nb] + (uint32_t)(rr*AHP)*4 + seg*2,
                               (const char*)&g_vt[vt_base + (size_t)rr * SEQ + (kt+1)*64 + seg]);
                }
            }
            CP_COMMIT();
            CP_WAIT1();
        } else {
            CP_WAIT0();
        }
        __syncthreads();

        // ---- S = Q K^T (exp2-domain logits) ----
        const uint32_t* Kc = Kb[buf];
        float s[8][4] = {};
        #pragma unroll
        for (int kk = 0; kk < 4; kk++) {
            #pragma unroll
            for (int nt = 0; nt < 8; nt++) {
                const int base = (nt*8 + r) * AHP + kk*8 + cl;
                mma_f16(s[nt], qf[kk][0], qf[kk][1], qf[kk][2], qf[kk][3],
                        Kc[base], Kc[base + 4]);
            }
        }

        // ---- online softmax (exp2) ----
        float mx0 = -INFINITY, mx1 = -INFINITY;
        #pragma unroll
        for (int nt = 0; nt < 8; nt++) {
            mx0 = fmaxf(mx0, fmaxf(s[nt][0], s[nt][1]));
            mx1 = fmaxf(mx1, fmaxf(s[nt][2], s[nt][3]));
        }
        mx0 = fmaxf(mx0, __shfl_xor_sync(0xffffffffu, mx0, 1));
        mx0 = fmaxf(mx0, __shfl_xor_sync(0xffffffffu, mx0, 2));
        mx1 = fmaxf(mx1, __shfl_xor_sync(0xffffffffu, mx1, 1));
        mx1 = fmaxf(mx1, __shfl_xor_sync(0xffffffffu, mx1, 2));
        const float mn0 = fmaxf(mo0, mx0);
        const float mn1 = fmaxf(mo1, mx1);
        const float a0 = exp2f(mo0 - mn0);
        const float a1 = exp2f(mo1 - mn1);
        float sum0 = 0.0f, sum1 = 0.0f;
        #pragma unroll
        for (int nt = 0; nt < 8; nt++) {
            s[nt][0] = exp2f(s[nt][0] - mn0);
            s[nt][1] = exp2f(s[nt][1] - mn0);
            s[nt][2] = exp2f(s[nt][2] - mn1);
            s[nt][3] = exp2f(s[nt][3] - mn1);
            sum0 += s[nt][0] + s[nt][1];
            sum1 += s[nt][2] + s[nt][3];
        }
        sum0 += __shfl_xor_sync(0xffffffffu, sum0, 1);
        sum0 += __shfl_xor_sync(0xffffffffu, sum0, 2);
        sum1 += __shfl_xor_sync(0xffffffffu, sum1, 1);
        sum1 += __shfl_xor_sync(0xffffffffu, sum1, 2);
        lo0 = a0 * lo0 + sum0;  mo0 = mn0;
        lo1 = a1 * lo1 + sum1;  mo1 = mn1;
        #pragma unroll
        for (int nt = 0; nt < 8; nt++) {
            o[nt][0] *= a0; o[nt][1] *= a0;
            o[nt][2] *= a1; o[nt][3] *= a1;
        }

        // ---- O += P V : S C-fragments ARE the PV A-fragments ----
        const uint32_t* Vc = Vb[buf];
        #pragma unroll
        for (int kk = 0; kk < 4; kk++) {
            const uint32_t pa0 = pack_half2(s[2*kk][0],   s[2*kk][1]);
            const uint32_t pa1 = pack_half2(s[2*kk][2],   s[2*kk][3]);
            const uint32_t pa2 = pack_half2(s[2*kk+1][0], s[2*kk+1][1]);
            const uint32_t pa3 = pack_half2(s[2*kk+1][2], s[2*kk+1][3]);
            #pragma unroll
            for (int nt = 0; nt < 8; nt++) {
                const int base = (nt*8 + r) * AHP + kk*8 + cl;
                mma_f16(o[nt], pa0, pa1, pa2, pa3, Vc[base], Vc[base + 4]);
            }
        }
    }

    // ---- epilogue: normalize, write half [B, L, H*64] ----
    const float inv0 = 1.0f / lo0;
    const float inv1 = 1.0f / lo1;
    const int bb = bh / HEADS;
    const int h  = bh % HEADS;
    const int row0 = qt*128 + q0 + r;
    #pragma unroll
    for (int nt = 0; nt < 8; nt++) {
        const int d = h * 64 + nt*8 + 2*cl;
        ((uint32_t*)attn_out)[(((size_t)bb * SEQ + row0)     * D_MODEL + d)/2] =
            pack_half2(o[nt][0] * inv0, o[nt][1] * inv0);
        ((uint32_t*)attn_out)[(((size_t)bb * SEQ + row0 + 8) * D_MODEL + d)/2] =
            pack_half2(o[nt][2] * inv1, o[nt][3] * inv1);
    }
}

// ---------------------------------------------------------------------------

static const int ATTN_SMEM = 4 * KVTU * (int)sizeof(uint32_t);           // 36864
static const int GEMM_SMEM = 4 * ABUFU * (int)sizeof(uint32_t);          // 73728

extern "C" void kernel_launch(void* const* d_in, const int* in_sizes, int n_in,
                              void* d_out, int out_size)
{
    const float* x     = (const float*)d_in[0];
    const float* W_qkv = (const float*)d_in[1];
    const float* b_qkv = (const float*)d_in[2];
    const float* W_out = (const float*)d_in[3];
    const float* b_out = (const float*)d_in[4];
    float* out = (float*)d_out;

    cudaFuncSetAttribute(attn_kernel,
                         cudaFuncAttributeMaxDynamicSharedMemorySize, ATTN_SMEM);
    cudaFuncSetAttribute(mma_gemm_kernel<0>,
                         cudaFuncAttributeMaxDynamicSharedMemorySize, GEMM_SMEM);
    cudaFuncSetAttribute(mma_gemm_kernel<1>,
                         cudaFuncAttributeMaxDynamicSharedMemorySize, GEMM_SMEM);

    __half *xh, *wqkv_t, *wout_t, *attn_h;
    cudaGetSymbolAddress((void**)&xh, g_h);
    cudaGetSymbolAddress((void**)&wqkv_t, g_wqkv_t);
    cudaGetSymbolAddress((void**)&wout_t, g_wout_t);
    attn_h = xh;   // reuse: X consumed by qkv gemm before attn writes

    convert_x_kernel<<<M_TOTAL*D_MODEL/(4*256), 256>>>(x, xh);
    transpose_w_kernel<<<dim3(N_QKV/32, KDIM/32), dim3(32, 8)>>>(W_qkv, wqkv_t, KDIM, N_QKV);
    transpose_w_kernel<<<dim3(D_MODEL/32, KDIM/32), dim3(32, 8)>>>(W_out, wout_t, KDIM, D_MODEL);

    dim3 g1(N_QKV / 128, M_TOTAL / 128);
    mma_gemm_kernel<0><<<g1, 256, GEMM_SMEM>>>(xh, wqkv_t, b_qkv, nullptr);

    dim3 g2(SEQ / 128, BH);
    attn_kernel<<<g2, 256, ATTN_SMEM>>>(attn_h);

    dim3 g3(D_MODEL / 128, M_TOTAL / 128);
    mma_gemm_kernel<1><<<g3, 256, GEMM_SMEM>>>(attn_h, wout_t, b_out, out);
}

// round 10
// speedup vs baseline: 7.4761x; 1.1782x over previous
#include <cuda_runtime.h>
#include <cuda_fp16.h>
#include <math.h>
#include <stdint.h>

#define D_MODEL 768
#define HEADS   12
#define HD      64
#define BATCH   4
#define SEQ     2048
#define M_TOTAL (BATCH*SEQ)      // 8192
#define N_QKV   (3*D_MODEL)      // 2304
#define BH      (BATCH*HEADS)    // 48
#define KDIM    768
#define NCHUNK  (KDIM/64)        // 12 chunks of K=64

// q scale: 1/sqrt(64) * log2(e)  (softmax done in exp2 domain)
#define QSCALE 0.1803368801111306f

// Scratch (device globals)
__device__ __half g_q[BH*SEQ*HD];       // pre-scaled by QSCALE
__device__ __half g_k[BH*SEQ*HD];
__device__ __half g_vt[BH*HD*SEQ];      // [bh][d][seq]
__device__ __half g_h[M_TOTAL*D_MODEL]; // half X, later attn output
__device__ __half g_wqkv_t[N_QKV*KDIM];
__device__ __half g_wout_t[D_MODEL*KDIM];

// ---------------------------------------------------------------------------
__device__ __forceinline__ uint32_t smem_to_u32(const void* p) {
    uint32_t a;
    asm("{ .reg .u64 t; cvta.to.shared.u64 t, %1; cvt.u32.u64 %0, t; }"
        : "=r"(a) : "l"(p));
    return a;
}
__device__ __forceinline__ uint32_t pack_half2(float lo, float hi) {
    uint32_t u;
    asm("cvt.rn.f16x2.f32 %0, %1, %2;" : "=r"(u) : "f"(hi), "f"(lo));
    return u;
}
__device__ __forceinline__ void ldsm_x4(uint32_t& r0, uint32_t& r1,
                                        uint32_t& r2, uint32_t& r3, uint32_t addr)
{
    asm volatile("ldmatrix.sync.aligned.m8n8.x4.shared.b16 {%0,%1,%2,%3}, [%4];"
        : "=r"(r0), "=r"(r1), "=r"(r2), "=r"(r3) : "r"(addr));
}
#define CP_ASYNC16(smem_addr, gptr) \
    asm volatile("cp.async.cg.shared.global [%0], [%1], 16;" \
        :: "r"(smem_addr), "l"(gptr))
#define CP_COMMIT() asm volatile("cp.async.commit_group;" ::: "memory")
#define CP_WAIT1()  asm volatile("cp.async.wait_group 1;" ::: "memory")
#define CP_WAIT0()  asm volatile("cp.async.wait_group 0;" ::: "memory")

__device__ __forceinline__ void mma_f16(float c[4],
    uint32_t a0, uint32_t a1, uint32_t a2, uint32_t a3,
    uint32_t b0, uint32_t b1)
{
    asm volatile(
        "mma.sync.aligned.m16n8k16.row.col.f32.f16.f16.f32 "
        "{%0,%1,%2,%3}, {%4,%5,%6,%7}, {%8,%9}, {%0,%1,%2,%3};"
        : "+f"(c[0]), "+f"(c[1]), "+f"(c[2]), "+f"(c[3])
        : "r"(a0), "r"(a1), "r"(a2), "r"(a3), "r"(b0), "r"(b1));
}

// ---------------------------------------------------------------------------
// X -> half
__global__ void convert_x_kernel(const float* __restrict__ src, __half* __restrict__ dst)
{
    const int i = (blockIdx.x * blockDim.x + threadIdx.x) * 4;
    float4 v = *(const float4*)&src[i];
    ((uint32_t*)dst)[i/2]     = pack_half2(v.x, v.y);
    ((uint32_t*)dst)[i/2 + 1] = pack_half2(v.z, v.w);
}

// W transpose + half: dst[N][K] = half(src[K][N])
__global__ void transpose_w_kernel(const float* __restrict__ src,
                                   __half* __restrict__ dst, int R, int C)
{
    __shared__ float t[32][33];
    const int bx = blockIdx.x * 32, by = blockIdx.y * 32;
    const int x = threadIdx.x, y = threadIdx.y;
    #pragma unroll
    for (int i = 0; i < 32; i += 8)
        t[y + i][x] = src[(size_t)(by + y + i) * C + bx + x];
    __syncthreads();
    #pragma unroll
    for (int i = 0; i < 32; i += 8)
        dst[(size_t)(bx + y + i) * R + by + x] = __float2half_rn(t[x][y + i]);
}

// ---------------------------------------------------------------------------
// fp16 mma.sync GEMM with ldmatrix fragment loads.
// CTA 128x128, 8 warps of 32m x 64n, K chunks of 64, cp.async dbl buf.
// MODE 0: scatter q(*QSCALE)/k to [bh][seq][64]; V transposed into g_vt.
// MODE 1: fp32 [M][768] out.
// ---------------------------------------------------------------------------
#define HPU   36                 // u32 per smem row (72 halfs, 64 used)
#define ABUFU (128*HPU)          // u32 per operand buffer
#define CPITCH 133               // floats, epilogue staging pitch

template<int MODE>
__global__ __launch_bounds__(256, 2)
void mma_gemm_kernel(const __half* __restrict__ A, const __half* __restrict__ Bt,
                     const float* __restrict__ bias, float* __restrict__ out)
{
    extern __shared__ uint32_t smu[];
    float* smf = (float*)smu;

    const int tid  = threadIdx.x;
    const int wid  = tid >> 5;
    const int lane = tid & 31;
    const int m0 = blockIdx.y * 128;
    const int n0 = blockIdx.x * 128;
    const int wm = (wid >> 1) * 32;
    const int wn = (wid & 1) * 64;
    const uint32_t sbase = smem_to_u32(smu);
    const int r = lane >> 2;
    const int cl = lane & 3;
    const int mm = lane >> 3;      // ldmatrix matrix id
    const int lrow = lane & 7;

    // ldmatrix lane byte-offsets within an operand buffer
    uint32_t aoff[2], boff[4];
    #pragma unroll
    for (int mi = 0; mi < 2; mi++)
        aoff[mi] = ((wm + mi*16 + (mm & 1)*8 + lrow) * HPU + (mm >> 1)*4) * 4;
    #pragma unroll
    for (int p = 0; p < 4; p++)
        boff[p] = ((wn + (p*2 + (mm >> 1))*8 + lrow) * HPU + (mm & 1)*4) * 4;

    float acc[2][8][4] = {};

    // chunk 0: 128 rows x 8 segs of 16B per operand
    #pragma unroll
    for (int i = 0; i < 4; i++) {
        const int idx = i * 256 + tid;           // 0..1023
        const int row = idx >> 3;                // 0..127
        const int seg = (idx & 7) * 8;           // halfs 0..56
        CP_ASYNC16(sbase + (uint32_t)(0*ABUFU + row*HPU)*4 + seg*2,
                   &A[(size_t)(m0 + row) * KDIM + seg]);
        CP_ASYNC16(sbase + (uint32_t)(2*ABUFU + row*HPU)*4 + seg*2,
                   &Bt[(size_t)(n0 + row) * KDIM + seg]);
    }
    CP_COMMIT();

    for (int c = 0; c < NCHUNK; c++) {
        const int buf = c & 1;
        if (c + 1 < NCHUNK) {
            const int nb = (c + 1) & 1;
            const int k0 = (c + 1) * 64;
            #pragma unroll
            for (int i = 0; i < 4; i++) {
                const int idx = i * 256 + tid;
                const int row = idx >> 3;
                const int seg = (idx & 7) * 8;
                CP_ASYNC16(sbase + (uint32_t)(nb*ABUFU + row*HPU)*4 + seg*2,
                           &A[(size_t)(m0 + row) * KDIM + k0 + seg]);
                CP_ASYNC16(sbase + (uint32_t)((2+nb)*ABUFU + row*HPU)*4 + seg*2,
                           &Bt[(size_t)(n0 + row) * KDIM + k0 + seg]);
            }
            CP_COMMIT();
            CP_WAIT1();
        } else {
            CP_WAIT0();
        }
        __syncthreads();

        const uint32_t aB = sbase + (uint32_t)(buf*ABUFU)*4;
        const uint32_t bB = sbase + (uint32_t)((2+buf)*ABUFU)*4;

        #pragma unroll
        for (int ks = 0; ks < 4; ks++) {
            const uint32_t kbyte = ks * 32;      // 8 u32 per kstep
            uint32_t af[2][4];
            #pragma unroll
            for (int mi = 0; mi < 2; mi++)
                ldsm_x4(af[mi][0], af[mi][1], af[mi][2], af[mi][3],
                        aB + aoff[mi] + kbyte);
            uint32_t bf[8][2];
            #pragma unroll
            for (int p = 0; p < 4; p++)
                ldsm_x4(bf[2*p][0], bf[2*p][1], bf[2*p+1][0], bf[2*p+1][1],
                        bB + boff[p] + kbyte);
            #pragma unroll
            for (int mi = 0; mi < 2; mi++)
                #pragma unroll
                for (int ni = 0; ni < 8; ni++)
                    mma_f16(acc[mi][ni], af[mi][0], af[mi][1], af[mi][2], af[mi][3],
                            bf[ni][0], bf[ni][1]);
        }
        __syncthreads();
    }

    // stage C in smem (float [128][CPITCH])
    #pragma unroll
    for (int mi = 0; mi < 2; mi++)
        #pragma unroll
        for (int ni = 0; ni < 8; ni++) {
            const int row = wm + mi*16 + r;
            const int col = wn + ni*8 + 2*cl;
            smf[row * CPITCH + col]       = acc[mi][ni][0];
            smf[row * CPITCH + col + 1]   = acc[mi][ni][1];
            smf[(row+8) * CPITCH + col]   = acc[mi][ni][2];
            smf[(row+8) * CPITCH + col+1] = acc[mi][ni][3];
        }
    __syncthreads();

    if (MODE == 1) {
        #pragma unroll
        for (int i = 0; i < 16; i++) {
            const int f = i * 256 + tid;
            const int row  = f >> 5;
            const int col  = (f & 31) * 4;
            const int m  = m0 + row;
            const int ng = n0 + col;
            float4 v = { smf[row*CPITCH + col + 0] + bias[ng + 0],
                         smf[row*CPITCH + col + 1] + bias[ng + 1],
                         smf[row*CPITCH + col + 2] + bias[ng + 2],
                         smf[row*CPITCH + col + 3] + bias[ng + 3] };
            *(float4*)&out[(size_t)m * D_MODEL + ng] = v;
        }
    } else {
        const int wsel = n0 / D_MODEL;
        if (wsel < 2) {
            __half* dst = (wsel == 0) ? g_q : g_k;
            const float sc = (wsel == 0) ? QSCALE : 1.0f;
            #pragma unroll
            for (int i = 0; i < 16; i++) {
                const int f = i * 256 + tid;
                const int row  = f >> 5;
                const int col  = (f & 31) * 4;
                const int m  = m0 + row;
                const int ng = n0 + col;
                float4 v = { (smf[row*CPITCH + col + 0] + bias[ng + 0]) * sc,
                             (smf[row*CPITCH + col + 1] + bias[ng + 1]) * sc,
                             (smf[row*CPITCH + col + 2] + bias[ng + 2]) * sc,
                             (smf[row*CPITCH + col + 3] + bias[ng + 3]) * sc };
                const int h = (ng % D_MODEL) >> 6;
                const int d = ng & 63;
                const int bb = m >> 11;
                const int l  = m & (SEQ - 1);
                const size_t off = (((size_t)bb * HEADS + h) * SEQ + l) * HD + d;
                ((uint32_t*)dst)[off/2]     = pack_half2(v.x, v.y);
                ((uint32_t*)dst)[off/2 + 1] = pack_half2(v.z, v.w);
            }
        } else {
            // v: transposed scatter into g_vt [bh][d][seq], coalesced along seq
            const int bb = m0 >> 11;
            const int l0 = m0 & (SEQ - 1);
            #pragma unroll
            for (int it = 0; it < 32; it++) {
                const int idx = it * 256 + tid;   // 0..8191
                const int d  = idx >> 6;          // 0..127 (tile col)
                const int l2 = idx & 63;          // pair index along rows
                const int ng = n0 + d;
                const float bv = bias[ng];
                const int h  = (ng % D_MODEL) >> 6;
                const int dd = ng & 63;
                const float v0 = smf[(2*l2)   * CPITCH + d] + bv;
                const float v1 = smf[(2*l2+1) * CPITCH + d] + bv;
                const size_t off = ((size_t)(bb * HEADS + h) * HD + dd) * SEQ + l0 + 2*l2;
                ((uint32_t*)g_vt)[off/2] = pack_half2(v0, v1);
            }
        }
    }
}

// ---------------------------------------------------------------------------
// Flash attention on fp16 mma.sync + ldmatrix.
// CTA = (head, 128 q). 8 warps x (16q x 64keys). K tiles of 64.
// K smem [key][d], VT smem [d][key], cp.async double buffered.
// P stays in registers (S C-frags repacked as PV A-frags). exp2 softmax.
// ---------------------------------------------------------------------------
#define AHP   36                 // u32 per 72-half row
#define KVTU  (64*AHP)           // u32 per K or VT buffer

__global__ __launch_bounds__(256, 2) void attn_kernel(__half* __restrict__ attn_out)
{
    extern __shared__ uint32_t smA[];

    const int tid  = threadIdx.x;
    const int wid  = tid >> 5;
    const int lane = tid & 31;
    const int r  = lane >> 2;
    const int cl = lane & 3;
    const int mm = lane >> 3;
    const int lrow = lane & 7;
    const int qt = blockIdx.x;
    const int bh = blockIdx.y;
    const size_t head_base = (size_t)bh * SEQ * HD;   // halfs
    const int q0 = wid * 16;

    // ldmatrix lane byte-offsets for a 64x64 tile (b-operand pairs)
    uint32_t foff[4];
    #pragma unroll
    for (int p = 0; p < 4; p++)
        foff[p] = (((p*2 + (mm >> 1))*8 + lrow) * AHP + (mm & 1)*4) * 4;

    // Q fragments (g_q pre-scaled): 4 ksteps x 4 regs
    uint32_t qf[4][4];
    {
        const uint32_t* Qp = (const uint32_t*)&g_q[head_base + (size_t)(qt*128 + q0) * HD];
        #pragma unroll
        for (int kk = 0; kk < 4; kk++) {
            qf[kk][0] = Qp[(size_t)r     * 32 + kk*8 + cl];
            qf[kk][1] = Qp[(size_t)(r+8) * 32 + kk*8 + cl];
            qf[kk][2] = Qp[(size_t)r     * 32 + kk*8 + cl + 4];
            qf[kk][3] = Qp[(size_t)(r+8) * 32 + kk*8 + cl + 4];
        }
    }

    float o[8][4] = {};
    float mo0 = -INFINITY, mo1 = -INFINITY, lo0 = 0.0f, lo1 = 0.0f;

    const uint32_t sb = smem_to_u32(smA);
    const uint32_t kb[2] = { sb,              sb + KVTU*4 };
    const uint32_t vb[2] = { sb + 2*KVTU*4,   sb + 3*KVTU*4 };
    const size_t vt_base = (size_t)bh * HD * SEQ;

    // prologue tile 0
    #pragma unroll
    for (int i = 0; i < 4; i++) {
        const int idx = i * 256 + tid;     // 0..1023
        const int rr  = (idx >> 3) & 63;
        const int seg = (idx & 7) * 8;
        if (idx < 512) {
            CP_ASYNC16(kb[0] + (uint32_t)(rr*AHP)*4 + seg*2,
                       (const char*)&g_k[head_base + (size_t)rr * HD + seg]);
        } else {
            CP_ASYNC16(vb[0] + (uint32_t)(rr*AHP)*4 + seg*2,
                       (const char*)&g_vt[vt_base + (size_t)rr * SEQ + seg]);
        }
    }
    CP_COMMIT();

    for (int kt = 0; kt < SEQ/64; kt++) {
        const int buf = kt & 1;
        __syncthreads();
        if (kt + 1 < SEQ/64) {
            const int nb = buf ^ 1;
            #pragma unroll
            for (int i = 0; i < 4; i++) {
                const int idx = i * 256 + tid;
                const int rr  = (idx >> 3) & 63;
                const int seg = (idx & 7) * 8;
                if (idx < 512) {
                    CP_ASYNC16(kb[nb] + (uint32_t)(rr*AHP)*4 + seg*2,
                               (const char*)&g_k[head_base + (size_t)((kt+1)*64 + rr) * HD + seg]);
                } else {
                    CP_ASYNC16(vb[nb] + (uint32_t)(rr*AHP)*4 + seg*2,
                               (const char*)&g_vt[vt_base + (size_t)rr * SEQ + (kt+1)*64 + seg]);
                }
            }
            CP_COMMIT();
            CP_WAIT1();
        } else {
            CP_WAIT0();
        }
        __syncthreads();

        // ---- S = Q K^T ----
        const uint32_t Kc = kb[buf];
        float s[8][4] = {};
        #pragma unroll
        for (int kk = 0; kk < 4; kk++) {
            const uint32_t kbyte = kk * 32;
            uint32_t bf[8][2];
            #pragma unroll
            for (int p = 0; p < 4; p++)
                ldsm_x4(bf[2*p][0], bf[2*p][1], bf[2*p+1][0], bf[2*p+1][1],
                        Kc + foff[p] + kbyte);
            #pragma unroll
            for (int nt = 0; nt < 8; nt++)
                mma_f16(s[nt], qf[kk][0], qf[kk][1], qf[kk][2], qf[kk][3],
                        bf[nt][0], bf[nt][1]);
        }

        // ---- online softmax (exp2) ----
        float mx0 = -INFINITY, mx1 = -INFINITY;
        #pragma unroll
        for (int nt = 0; nt < 8; nt++) {
            mx0 = fmaxf(mx0, fmaxf(s[nt][0], s[nt][1]));
            mx1 = fmaxf(mx1, fmaxf(s[nt][2], s[nt][3]));
        }
        mx0 = fmaxf(mx0, __shfl_xor_sync(0xffffffffu, mx0, 1));
        mx0 = fmaxf(mx0, __shfl_xor_sync(0xffffffffu, mx0, 2));
        mx1 = fmaxf(mx1, __shfl_xor_sync(0xffffffffu, mx1, 1));
        mx1 = fmaxf(mx1, __shfl_xor_sync(0xffffffffu, mx1, 2));
        const float mn0 = fmaxf(mo0, mx0);
        const float mn1 = fmaxf(mo1, mx1);
        const float a0 = exp2f(mo0 - mn0);
        const float a1 = exp2f(mo1 - mn1);
        float sum0 = 0.0f, sum1 = 0.0f;
        #pragma unroll
        for (int nt = 0; nt < 8; nt++) {
            s[nt][0] = exp2f(s[nt][0] - mn0);
            s[nt][1] = exp2f(s[nt][1] - mn0);
            s[nt][2] = exp2f(s[nt][2] - mn1);
            s[nt][3] = exp2f(s[nt][3] - mn1);
            sum0 += s[nt][0] + s[nt][1];
            sum1 += s[nt][2] + s[nt][3];
        }
        sum0 += __shfl_xor_sync(0xffffffffu, sum0, 1);
        sum0 += __shfl_xor_sync(0xffffffffu, sum0, 2);
        sum1 += __shfl_xor_sync(0xffffffffu, sum1, 1);
        sum1 += __shfl_xor_sync(0xffffffffu, sum1, 2);
        lo0 = a0 * lo0 + sum0;  mo0 = mn0;
        lo1 = a1 * lo1 + sum1;  mo1 = mn1;
        #pragma unroll
        for (int nt = 0; nt < 8; nt++) {
            o[nt][0] *= a0; o[nt][1] *= a0;
            o[nt][2] *= a1; o[nt][3] *= a1;
        }

        // ---- O += P V : S C-fragments repacked as PV A-fragments ----
        const uint32_t Vc = vb[buf];
        #pragma unroll
        for (int kk = 0; kk < 4; kk++) {
            const uint32_t kbyte = kk * 32;
            const uint32_t pa0 = pack_half2(s[2*kk][0],   s[2*kk][1]);
            const uint32_t pa1 = pack_half2(s[2*kk][2],   s[2*kk][3]);
            const uint32_t pa2 = pack_half2(s[2*kk+1][0], s[2*kk+1][1]);
            const uint32_t pa3 = pack_half2(s[2*kk+1][2], s[2*kk+1][3]);
            uint32_t bf[8][2];
            #pragma unroll
            for (int p = 0; p < 4; p++)
                ldsm_x4(bf[2*p][0], bf[2*p][1], bf[2*p+1][0], bf[2*p+1][1],
                        Vc + foff[p] + kbyte);
            #pragma unroll
            for (int nt = 0; nt < 8; nt++)
                mma_f16(o[nt], pa0, pa1, pa2, pa3, bf[nt][0], bf[nt][1]);
        }
    }

    // ---- epilogue: normalize, write half [B, L, H*64] ----
    const float inv0 = 1.0f / lo0;
    const float inv1 = 1.0f / lo1;
    const int bb = bh / HEADS;
    const int h  = bh % HEADS;
    const int row0 = qt*128 + q0 + r;
    #pragma unroll
    for (int nt = 0; nt < 8; nt++) {
        const int d = h * 64 + nt*8 + 2*cl;
        ((uint32_t*)attn_out)[(((size_t)bb * SEQ + row0)     * D_MODEL + d)/2] =
            pack_half2(o[nt][0] * inv0, o[nt][1] * inv0);
        ((uint32_t*)attn_out)[(((size_t)bb * SEQ + row0 + 8) * D_MODEL + d)/2] =
            pack_half2(o[nt][2] * inv1, o[nt][3] * inv1);
    }
}

// ---------------------------------------------------------------------------

static const int ATTN_SMEM = 4 * KVTU * (int)sizeof(uint32_t);           // 36864
static const int GEMM_SMEM = 4 * ABUFU * (int)sizeof(uint32_t);          // 73728

extern "C" void kernel_launch(void* const* d_in, const int* in_sizes, int n_in,
                              void* d_out, int out_size)
{
    const float* x     = (const float*)d_in[0];
    const float* W_qkv = (const float*)d_in[1];
    const float* b_qkv = (const float*)d_in[2];
    const float* W_out = (const float*)d_in[3];
    const float* b_out = (const float*)d_in[4];
    float* out = (float*)d_out;

    cudaFuncSetAttribute(attn_kernel,
                         cudaFuncAttributeMaxDynamicSharedMemorySize, ATTN_SMEM);
    cudaFuncSetAttribute(mma_gemm_kernel<0>,
                         cudaFuncAttributeMaxDynamicSharedMemorySize, GEMM_SMEM);
    cudaFuncSetAttribute(mma_gemm_kernel<1>,
                         cudaFuncAttributeMaxDynamicSharedMemorySize, GEMM_SMEM);

    __half *xh, *wqkv_t, *wout_t, *attn_h;
    cudaGetSymbolAddress((void**)&xh, g_h);
    cudaGetSymbolAddress((void**)&wqkv_t, g_wqkv_t);
    cudaGetSymbolAddress((void**)&wout_t, g_wout_t);
    attn_h = xh;   // reuse: X consumed by qkv gemm before attn writes

    convert_x_kernel<<<M_TOTAL*D_MODEL/(4*256), 256>>>(x, xh);
    transpose_w_kernel<<<dim3(N_QKV/32, KDIM/32), dim3(32, 8)>>>(W_qkv, wqkv_t, KDIM, N_QKV);
    transpose_w_kernel<<<dim3(D_MODEL/32, KDIM/32), dim3(32, 8)>>>(W_out, wout_t, KDIM, D_MODEL);

    dim3 g1(N_QKV / 128, M_TOTAL / 128);
    mma_gemm_kernel<0><<<g1, 256, GEMM_SMEM>>>(xh, wqkv_t, b_qkv, nullptr);

    dim3 g2(SEQ / 128, BH);
    attn_kernel<<<g2, 256, ATTN_SMEM>>>(attn_h);

    dim3 g3(D_MODEL / 128, M_TOTAL / 128);
    mma_gemm_kernel<1><<<g3, 256, GEMM_SMEM>>>(attn_h, wout_t, b_out, out);
}

// round 11
// speedup vs baseline: 7.9045x; 1.0573x over previous
#include <cuda_runtime.h>
#include <cuda_fp16.h>
#include <math.h>
#include <stdint.h>

#define D_MODEL 768
#define HEADS   12
#define HD      64
#define BATCH   4
#define SEQ     2048
#define M_TOTAL (BATCH*SEQ)      // 8192
#define N_QKV   (3*D_MODEL)      // 2304
#define BH      (BATCH*HEADS)    // 48
#define KDIM    768
#define NCHUNK  (KDIM/64)        // 12 chunks of K=64

// q scale: 1/sqrt(64) * log2(e)  (softmax done in exp2 domain)
#define QSCALE 0.1803368801111306f
#define ONES2  0x3C003C00u       // half2(1.0, 1.0)

// Scratch (device globals)
__device__ __half g_q[BH*SEQ*HD];       // pre-scaled by QSCALE
__device__ __half g_k[BH*SEQ*HD];
__device__ __half g_vt[BH*HD*SEQ];      // [bh][d][seq]
__device__ __half g_h[M_TOTAL*D_MODEL]; // half X, later attn output
__device__ __half g_wqkv_t[N_QKV*KDIM];
__device__ __half g_wout_t[D_MODEL*KDIM];

// ---------------------------------------------------------------------------
__device__ __forceinline__ uint32_t smem_to_u32(const void* p) {
    uint32_t a;
    asm("{ .reg .u64 t; cvta.to.shared.u64 t, %1; cvt.u32.u64 %0, t; }"
        : "=r"(a) : "l"(p));
    return a;
}
__device__ __forceinline__ uint32_t pack_half2(float lo, float hi) {
    uint32_t u;
    asm("cvt.rn.f16x2.f32 %0, %1, %2;" : "=r"(u) : "f"(hi), "f"(lo));
    return u;
}
__device__ __forceinline__ uint32_t exp2_h2(uint32_t a) {
    uint32_t d;
    asm("ex2.approx.f16x2 %0, %1;" : "=r"(d) : "r"(a));
    return d;
}
__device__ __forceinline__ void ldsm_x4(uint32_t& r0, uint32_t& r1,
                                        uint32_t& r2, uint32_t& r3, uint32_t addr)
{
    asm volatile("ldmatrix.sync.aligned.m8n8.x4.shared.b16 {%0,%1,%2,%3}, [%4];"
        : "=r"(r0), "=r"(r1), "=r"(r2), "=r"(r3) : "r"(addr));
}
#define CP_ASYNC16(smem_addr, gptr) \
    asm volatile("cp.async.cg.shared.global [%0], [%1], 16;" \
        :: "r"(smem_addr), "l"(gptr))
#define CP_COMMIT() asm volatile("cp.async.commit_group;" ::: "memory")
#define CP_WAIT1()  asm volatile("cp.async.wait_group 1;" ::: "memory")
#define CP_WAIT0()  asm volatile("cp.async.wait_group 0;" ::: "memory")

__device__ __forceinline__ void mma_f16(float c[4],
    uint32_t a0, uint32_t a1, uint32_t a2, uint32_t a3,
    uint32_t b0, uint32_t b1)
{
    asm volatile(
        "mma.sync.aligned.m16n8k16.row.col.f32.f16.f16.f32 "
        "{%0,%1,%2,%3}, {%4,%5,%6,%7}, {%8,%9}, {%0,%1,%2,%3};"
        : "+f"(c[0]), "+f"(c[1]), "+f"(c[2]), "+f"(c[3])
        : "r"(a0), "r"(a1), "r"(a2), "r"(a3), "r"(b0), "r"(b1));
}

// ---------------------------------------------------------------------------
// X -> half
__global__ void convert_x_kernel(const float* __restrict__ src, __half* __restrict__ dst)
{
    const int i = (blockIdx.x * blockDim.x + threadIdx.x) * 4;
    float4 v = *(const float4*)&src[i];
    ((uint32_t*)dst)[i/2]     = pack_half2(v.x, v.y);
    ((uint32_t*)dst)[i/2 + 1] = pack_half2(v.z, v.w);
}

// W transpose + half: dst[N][K] = half(src[K][N])
__global__ void transpose_w_kernel(const float* __restrict__ src,
                                   __half* __restrict__ dst, int R, int C)
{
    __shared__ float t[32][33];
    const int bx = blockIdx.x * 32, by = blockIdx.y * 32;
    const int x = threadIdx.x, y = threadIdx.y;
    #pragma unroll
    for (int i = 0; i < 32; i += 8)
        t[y + i][x] = src[(size_t)(by + y + i) * C + bx + x];
    __syncthreads();
    #pragma unroll
    for (int i = 0; i < 32; i += 8)
        dst[(size_t)(bx + y + i) * R + by + x] = __float2half_rn(t[x][y + i]);
}

// ---------------------------------------------------------------------------
// fp16 mma.sync GEMM, ldmatrix fragments, 3-stage cp.async pipeline.
// CTA 128x128, 8 warps of 32m x 64n, K chunks of 64.
// MODE 0: scatter q(*QSCALE)/k to [bh][seq][64]; V transposed into g_vt.
// MODE 1: fp32 [M][768] out.
// ---------------------------------------------------------------------------
#define HPU   36                 // u32 per smem row (72 halfs, 64 used)
#define ABUFU (128*HPU)          // u32 per operand buffer
#define CPITCH 133               // floats, epilogue staging pitch

template<int MODE>
__global__ __launch_bounds__(256, 2)
void mma_gemm_kernel(const __half* __restrict__ A, const __half* __restrict__ Bt,
                     const float* __restrict__ bias, float* __restrict__ out)
{
    extern __shared__ uint32_t smu[];
    float* smf = (float*)smu;

    const int tid  = threadIdx.x;
    const int wid  = tid >> 5;
    const int lane = tid & 31;
    const int m0 = blockIdx.y * 128;
    const int n0 = blockIdx.x * 128;
    const int wm = (wid >> 1) * 32;
    const int wn = (wid & 1) * 64;
    const uint32_t sbase = smem_to_u32(smu);
    const int r = lane >> 2;
    const int cl = lane & 3;
    const int mm = lane >> 3;      // ldmatrix matrix id
    const int lrow = lane & 7;

    // ldmatrix lane byte-offsets within an operand buffer
    uint32_t aoff[2], boff[4];
    #pragma unroll
    for (int mi = 0; mi < 2; mi++)
        aoff[mi] = ((wm + mi*16 + (mm & 1)*8 + lrow) * HPU + (mm >> 1)*4) * 4;
    #pragma unroll
    for (int p = 0; p < 4; p++)
        boff[p] = ((wn + (p*2 + (mm >> 1))*8 + lrow) * HPU + (mm & 1)*4) * 4;

    float acc[2][8][4] = {};

    // load mapping: 128 rows x 8 segs of 16B per operand per chunk
    const int lrw = tid >> 1;             // unused helper
    (void)lrw;

    // prologue: chunks 0 and 1 into stages 0 and 1
    #pragma unroll
    for (int s = 0; s < 2; s++) {
        const int k0 = s * 64;
        #pragma unroll
        for (int i = 0; i < 4; i++) {
            const int idx = i * 256 + tid;
            const int row = idx >> 3;
            const int seg = (idx & 7) * 8;
            CP_ASYNC16(sbase + (uint32_t)(s*ABUFU + row*HPU)*4 + seg*2,
                       &A[(size_t)(m0 + row) * KDIM + k0 + seg]);
            CP_ASYNC16(sbase + (uint32_t)((3+s)*ABUFU + row*HPU)*4 + seg*2,
                       &Bt[(size_t)(n0 + row) * KDIM + k0 + seg]);
        }
        CP_COMMIT();
    }

    int stg = 0;          // stage of chunk c
    int stg2 = 2;         // stage for chunk c+2
    for (int c = 0; c < NCHUNK; c++) {
        if (c + 1 < NCHUNK) { CP_WAIT1(); } else { CP_WAIT0(); }
        __syncthreads();   // chunk c visible; all warps done with chunk c-1

        if (c + 2 < NCHUNK) {
            const int k0 = (c + 2) * 64;
            #pragma unroll
            for (int i = 0; i < 4; i++) {
                const int idx = i * 256 + tid;
                const int row = idx >> 3;
                const int seg = (idx & 7) * 8;
                CP_ASYNC16(sbase + (uint32_t)(stg2*ABUFU + row*HPU)*4 + seg*2,
                           &A[(size_t)(m0 + row) * KDIM + k0 + seg]);
                CP_ASYNC16(sbase + (uint32_t)((3+stg2)*ABUFU + row*HPU)*4 + seg*2,
                           &Bt[(size_t)(n0 + row) * KDIM + k0 + seg]);
            }
            CP_COMMIT();
        }

        const uint32_t aB = sbase + (uint32_t)(stg*ABUFU)*4;
        const uint32_t bB = sbase + (uint32_t)((3+stg)*ABUFU)*4;

        #pragma unroll
        for (int ks = 0; ks < 4; ks++) {
            const uint32_t kbyte = ks * 32;
            uint32_t af[2][4];
            #pragma unroll
            for (int mi = 0; mi < 2; mi++)
                ldsm_x4(af[mi][0], af[mi][1], af[mi][2], af[mi][3],
                        aB + aoff[mi] + kbyte);
            uint32_t bf[8][2];
            #pragma unroll
            for (int p = 0; p < 4; p++)
                ldsm_x4(bf[2*p][0], bf[2*p][1], bf[2*p+1][0], bf[2*p+1][1],
                        bB + boff[p] + kbyte);
            #pragma unroll
            for (int mi = 0; mi < 2; mi++)
                #pragma unroll
                for (int ni = 0; ni < 8; ni++)
                    mma_f16(acc[mi][ni], af[mi][0], af[mi][1], af[mi][2], af[mi][3],
                            bf[ni][0], bf[ni][1]);
        }
        stg  = (stg  == 2) ? 0 : stg  + 1;
        stg2 = (stg2 == 2) ? 0 : stg2 + 1;
    }
    __syncthreads();   // all compute done before epilogue reuses smem

    // stage C in smem (float [128][CPITCH])
    #pragma unroll
    for (int mi = 0; mi < 2; mi++)
        #pragma unroll
        for (int ni = 0; ni < 8; ni++) {
            const int row = wm + mi*16 + r;
            const int col = wn + ni*8 + 2*cl;
            smf[row * CPITCH + col]       = acc[mi][ni][0];
            smf[row * CPITCH + col + 1]   = acc[mi][ni][1];
            smf[(row+8) * CPITCH + col]   = acc[mi][ni][2];
            smf[(row+8) * CPITCH + col+1] = acc[mi][ni][3];
        }
    __syncthreads();

    if (MODE == 1) {
        #pragma unroll
        for (int i = 0; i < 16; i++) {
            const int f = i * 256 + tid;
            const int row  = f >> 5;
            const int col  = (f & 31) * 4;
            const int m  = m0 + row;
            const int ng = n0 + col;
            float4 v = { smf[row*CPITCH + col + 0] + bias[ng + 0],
                         smf[row*CPITCH + col + 1] + bias[ng + 1],
                         smf[row*CPITCH + col + 2] + bias[ng + 2],
                         smf[row*CPITCH + col + 3] + bias[ng + 3] };
            *(float4*)&out[(size_t)m * D_MODEL + ng] = v;
        }
    } else {
        const int wsel = n0 / D_MODEL;
        if (wsel < 2) {
            __half* dst = (wsel == 0) ? g_q : g_k;
            const float sc = (wsel == 0) ? QSCALE : 1.0f;
            #pragma unroll
            for (int i = 0; i < 16; i++) {
                const int f = i * 256 + tid;
                const int row  = f >> 5;
                const int col  = (f & 31) * 4;
                const int m  = m0 + row;
                const int ng = n0 + col;
                float4 v = { (smf[row*CPITCH + col + 0] + bias[ng + 0]) * sc,
                             (smf[row*CPITCH + col + 1] + bias[ng + 1]) * sc,
                             (smf[row*CPITCH + col + 2] + bias[ng + 2]) * sc,
                             (smf[row*CPITCH + col + 3] + bias[ng + 3]) * sc };
                const int h = (ng % D_MODEL) >> 6;
                const int d = ng & 63;
                const int bb = m >> 11;
                const int l  = m & (SEQ - 1);
                const size_t off = (((size_t)bb * HEADS + h) * SEQ + l) * HD + d;
                ((uint32_t*)dst)[off/2]     = pack_half2(v.x, v.y);
                ((uint32_t*)dst)[off/2 + 1] = pack_half2(v.z, v.w);
            }
        } else {
            // v: transposed scatter into g_vt [bh][d][seq], coalesced along seq
            const int bb = m0 >> 11;
            const int l0 = m0 & (SEQ - 1);
            #pragma unroll
            for (int it = 0; it < 32; it++) {
                const int idx = it * 256 + tid;   // 0..8191
                const int d  = idx >> 6;          // 0..127 (tile col)
                const int l2 = idx & 63;          // pair index along rows
                const int ng = n0 + d;
                const float bv = bias[ng];
                const int h  = (ng % D_MODEL) >> 6;
                const int dd = ng & 63;
                const float v0 = smf[(2*l2)   * CPITCH + d] + bv;
                const float v1 = smf[(2*l2+1) * CPITCH + d] + bv;
                const size_t off = ((size_t)(bb * HEADS + h) * HD + dd) * SEQ + l0 + 2*l2;
                ((uint32_t*)g_vt)[off/2] = pack_half2(v0, v1);
            }
        }
    }
}

// ---------------------------------------------------------------------------
// Flash attention: fp16 mma.sync + ldmatrix, f16x2 exp2, ones-MMA row sums.
// CTA = (head, 128 q). 8 warps x (16q x 64keys). K tiles of 64, dbl buf.
// ---------------------------------------------------------------------------
#define AHP   36                 // u32 per 72-half row
#define KVTU  (64*AHP)           // u32 per K or VT buffer

__global__ __launch_bounds__(256, 2) void attn_kernel(__half* __restrict__ attn_out)
{
    extern __shared__ uint32_t smA[];

    const int tid  = threadIdx.x;
    const int wid  = tid >> 5;
    const int lane = tid & 31;
    const int r  = lane >> 2;
    const int cl = lane & 3;
    const int mm = lane >> 3;
    const int lrow = lane & 7;
    const int qt = blockIdx.x;
    const int bh = blockIdx.y;
    const size_t head_base = (size_t)bh * SEQ * HD;   // halfs
    const int q0 = wid * 16;

    uint32_t foff[4];
    #pragma unroll
    for (int p = 0; p < 4; p++)
        foff[p] = (((p*2 + (mm >> 1))*8 + lrow) * AHP + (mm & 1)*4) * 4;

    // Q fragments (g_q pre-scaled): 4 ksteps x 4 regs
    uint32_t qf[4][4];
    {
        const uint32_t* Qp = (const uint32_t*)&g_q[head_base + (size_t)(qt*128 + q0) * HD];
        #pragma unroll
        for (int kk = 0; kk < 4; kk++) {
            qf[kk][0] = Qp[(size_t)r     * 32 + kk*8 + cl];
            qf[kk][1] = Qp[(size_t)(r+8) * 32 + kk*8 + cl];
            qf[kk][2] = Qp[(size_t)r     * 32 + kk*8 + cl + 4];
            qf[kk][3] = Qp[(size_t)(r+8) * 32 + kk*8 + cl + 4];
        }
    }

    float o[8][4] = {};
    float mo0 = -INFINITY, mo1 = -INFINITY, lo0 = 0.0f, lo1 = 0.0f;

    const uint32_t sb = smem_to_u32(smA);
    const uint32_t kb[2] = { sb,              sb + KVTU*4 };
    const uint32_t vb[2] = { sb + 2*KVTU*4,   sb + 3*KVTU*4 };
    const size_t vt_base = (size_t)bh * HD * SEQ;

    // prologue tile 0
    #pragma unroll
    for (int i = 0; i < 4; i++) {
        const int idx = i * 256 + tid;     // 0..1023
        const int rr  = (idx >> 3) & 63;
        const int seg = (idx & 7) * 8;
        if (idx < 512) {
            CP_ASYNC16(kb[0] + (uint32_t)(rr*AHP)*4 + seg*2,
                       (const char*)&g_k[head_base + (size_t)rr * HD + seg]);
        } else {
            CP_ASYNC16(vb[0] + (uint32_t)(rr*AHP)*4 + seg*2,
                       (const char*)&g_vt[vt_base + (size_t)rr * SEQ + seg]);
        }
    }
    CP_COMMIT();

    for (int kt = 0; kt < SEQ/64; kt++) {
        const int buf = kt & 1;
        __syncthreads();
        if (kt + 1 < SEQ/64) {
            const int nb = buf ^ 1;
            #pragma unroll
            for (int i = 0; i < 4; i++) {
                const int idx = i * 256 + tid;
                const int rr  = (idx >> 3) & 63;
                const int seg = (idx & 7) * 8;
                if (idx < 512) {
                    CP_ASYNC16(kb[nb] + (uint32_t)(rr*AHP)*4 + seg*2,
                               (const char*)&g_k[head_base + (size_t)((kt+1)*64 + rr) * HD + seg]);
                } else {
                    CP_ASYNC16(vb[nb] + (uint32_t)(rr*AHP)*4 + seg*2,
                               (const char*)&g_vt[vt_base + (size_t)rr * SEQ + (kt+1)*64 + seg]);
                }
            }
            CP_COMMIT();
            CP_WAIT1();
        } else {
            CP_WAIT0();
        }
        __syncthreads();

        // ---- S = Q K^T (exp2-domain logits, f32 acc) ----
        const uint32_t Kc = kb[buf];
        float s[8][4] = {};
        #pragma unroll
        for (int kk = 0; kk < 4; kk++) {
            const uint32_t kbyte = kk * 32;
            uint32_t bf[8][2];
            #pragma unroll
            for (int p = 0; p < 4; p++)
                ldsm_x4(bf[2*p][0], bf[2*p][1], bf[2*p+1][0], bf[2*p+1][1],
                        Kc + foff[p] + kbyte);
            #pragma unroll
            for (int nt = 0; nt < 8; nt++)
                mma_f16(s[nt], qf[kk][0], qf[kk][1], qf[kk][2], qf[kk][3],
                        bf[nt][0], bf[nt][1]);
        }

        // ---- row max (quad reduction) ----
        float mx0 = -INFINITY, mx1 = -INFINITY;
        #pragma unroll
        for (int nt = 0; nt < 8; nt++) {
            mx0 = fmaxf(mx0, fmaxf(s[nt][0], s[nt][1]));
            mx1 = fmaxf(mx1, fmaxf(s[nt][2], s[nt][3]));
        }
        mx0 = fmaxf(mx0, __shfl_xor_sync(0xffffffffu, mx0, 1));
        mx0 = fmaxf(mx0, __shfl_xor_sync(0xffffffffu, mx0, 2));
        mx1 = fmaxf(mx1, __shfl_xor_sync(0xffffffffu, mx1, 1));
        mx1 = fmaxf(mx1, __shfl_xor_sync(0xffffffffu, mx1, 2));
        const float mn0 = fmaxf(mo0, mx0);
        const float mn1 = fmaxf(mo1, mx1);
        const float a0 = exp2f(mo0 - mn0);
        const float a1 = exp2f(mo1 - mn1);

        // ---- P = exp2(s - m) in f16x2, packed directly as PV A-fragments ----
        uint32_t pf[4][4];
        #pragma unroll
        for (int kk = 0; kk < 4; kk++) {
            pf[kk][0] = exp2_h2(pack_half2(s[2*kk][0]   - mn0, s[2*kk][1]   - mn0));
            pf[kk][1] = exp2_h2(pack_half2(s[2*kk][2]   - mn1, s[2*kk][3]   - mn1));
            pf[kk][2] = exp2_h2(pack_half2(s[2*kk+1][0] - mn0, s[2*kk+1][1] - mn0));
            pf[kk][3] = exp2_h2(pack_half2(s[2*kk+1][2] - mn1, s[2*kk+1][3] - mn1));
        }

        // ---- row sums via ones-MMA (c[0]=row r sum, c[2]=row r+8 sum) ----
        float ls[4] = {};
        #pragma unroll
        for (int kk = 0; kk < 4; kk++)
            mma_f16(ls, pf[kk][0], pf[kk][1], pf[kk][2], pf[kk][3], ONES2, ONES2);

        lo0 = a0 * lo0 + ls[0];  mo0 = mn0;
        lo1 = a1 * lo1 + ls[2];  mo1 = mn1;
        #pragma unroll
        for (int nt = 0; nt < 8; nt++) {
            o[nt][0] *= a0; o[nt][1] *= a0;
            o[nt][2] *= a1; o[nt][3] *= a1;
        }

        // ---- O += P V ----
        const uint32_t Vc = vb[buf];
        #pragma unroll
        for (int kk = 0; kk < 4; kk++) {
            const uint32_t kbyte = kk * 32;
            uint32_t bf[8][2];
            #pragma unroll
            for (int p = 0; p < 4; p++)
                ldsm_x4(bf[2*p][0], bf[2*p][1], bf[2*p+1][0], bf[2*p+1][1],
                        Vc + foff[p] + kbyte);
            #pragma unroll
            for (int nt = 0; nt < 8; nt++)
                mma_f16(o[nt], pf[kk][0], pf[kk][1], pf[kk][2], pf[kk][3],
                        bf[nt][0], bf[nt][1]);
        }
    }

    // ---- epilogue: normalize, write half [B, L, H*64] ----
    const float inv0 = 1.0f / lo0;
    const float inv1 = 1.0f / lo1;
    const int bb = bh / HEADS;
    const int h  = bh % HEADS;
    const int row0 = qt*128 + q0 + r;
    #pragma unroll
    for (int nt = 0; nt < 8; nt++) {
        const int d = h * 64 + nt*8 + 2*cl;
        ((uint32_t*)attn_out)[(((size_t)bb * SEQ + row0)     * D_MODEL + d)/2] =
            pack_half2(o[nt][0] * inv0, o[nt][1] * inv0);
        ((uint32_t*)attn_out)[(((size_t)bb * SEQ + row0 + 8) * D_MODEL + d)/2] =
            pack_half2(o[nt][2] * inv1, o[nt][3] * inv1);
    }
}

// ---------------------------------------------------------------------------

static const int ATTN_SMEM = 4 * KVTU * (int)sizeof(uint32_t);           // 36864
static const int GEMM_SMEM = 6 * ABUFU * (int)sizeof(uint32_t);          // 110592

extern "C" void kernel_launch(void* const* d_in, const int* in_sizes, int n_in,
                              void* d_out, int out_size)
{
    const float* x     = (const float*)d_in[0];
    const float* W_qkv = (const float*)d_in[1];
    const float* b_qkv = (const float*)d_in[2];
    const float* W_out = (const float*)d_in[3];
    const float* b_out = (const float*)d_in[4];
    float* out = (float*)d_out;

    cudaFuncSetAttribute(attn_kernel,
                         cudaFuncAttributeMaxDynamicSharedMemorySize, ATTN_SMEM);
    cudaFuncSetAttribute(mma_gemm_kernel<0>,
                         cudaFuncAttributeMaxDynamicSharedMemorySize, GEMM_SMEM);
    cudaFuncSetAttribute(mma_gemm_kernel<1>,
                         cudaFuncAttributeMaxDynamicSharedMemorySize, GEMM_SMEM);

    __half *xh, *wqkv_t, *wout_t, *attn_h;
    cudaGetSymbolAddress((void**)&xh, g_h);
    cudaGetSymbolAddress((void**)&wqkv_t, g_wqkv_t);
    cudaGetSymbolAddress((void**)&wout_t, g_wout_t);
    attn_h = xh;   // reuse: X consumed by qkv gemm before attn writes

    convert_x_kernel<<<M_TOTAL*D_MODEL/(4*256), 256>>>(x, xh);
    transpose_w_kernel<<<dim3(N_QKV/32, KDIM/32), dim3(32, 8)>>>(W_qkv, wqkv_t, KDIM, N_QKV);
    transpose_w_kernel<<<dim3(D_MODEL/32, KDIM/32), dim3(32, 8)>>>(W_out, wout_t, KDIM, D_MODEL);

    dim3 g1(N_QKV / 128, M_TOTAL / 128);
    mma_gemm_kernel<0><<<g1, 256, GEMM_SMEM>>>(xh, wqkv_t, b_qkv, nullptr);

    dim3 g2(SEQ / 128, BH);
    attn_kernel<<<g2, 256, ATTN_SMEM>>>(attn_h);

    dim3 g3(D_MODEL / 128, M_TOTAL / 128);
    mma_gemm_kernel<1><<<g3, 256, GEMM_SMEM>>>(attn_h, wout_t, b_out, out);
}

// round 12
// speedup vs baseline: 8.0242x; 1.0151x over previous
#include <cuda_runtime.h>
#include <cuda_fp16.h>
#include <math.h>
#include <stdint.h>

#define D_MODEL 768
#define HEADS   12
#define HD      64
#define BATCH   4
#define SEQ     2048
#define M_TOTAL (BATCH*SEQ)      // 8192
#define N_QKV   (3*D_MODEL)      // 2304
#define BH      (BATCH*HEADS)    // 48
#define KDIM    768
#define NCHUNK  (KDIM/64)        // 12 chunks of K=64

// q scale: 1/sqrt(64) * log2(e)  (softmax done in exp2 domain)
#define QSCALE 0.1803368801111306f
#define ONES2  0x3C003C00u       // half2(1.0, 1.0)

// Scratch (device globals)
__device__ __half g_q[BH*SEQ*HD];       // pre-scaled by QSCALE
__device__ __half g_k[BH*SEQ*HD];
__device__ __half g_vt[BH*HD*SEQ];      // [bh][d][seq]
__device__ __half g_h[M_TOTAL*D_MODEL]; // half X, later attn output
__device__ __half g_wqkv_t[N_QKV*KDIM];
__device__ __half g_wout_t[D_MODEL*KDIM];

// ---------------------------------------------------------------------------
__device__ __forceinline__ uint32_t smem_to_u32(const void* p) {
    uint32_t a;
    asm("{ .reg .u64 t; cvta.to.shared.u64 t, %1; cvt.u32.u64 %0, t; }"
        : "=r"(a) : "l"(p));
    return a;
}
__device__ __forceinline__ uint32_t pack_half2(float lo, float hi) {
    uint32_t u;
    asm("cvt.rn.f16x2.f32 %0, %1, %2;" : "=r"(u) : "f"(hi), "f"(lo));
    return u;
}
__device__ __forceinline__ uint32_t exp2_h2(uint32_t a) {
    uint32_t d;
    asm("ex2.approx.f16x2 %0, %1;" : "=r"(d) : "r"(a));
    return d;
}
__device__ __forceinline__ void ldsm_x4(uint32_t& r0, uint32_t& r1,
                                        uint32_t& r2, uint32_t& r3, uint32_t addr)
{
    asm volatile("ldmatrix.sync.aligned.m8n8.x4.shared.b16 {%0,%1,%2,%3}, [%4];"
        : "=r"(r0), "=r"(r1), "=r"(r2), "=r"(r3) : "r"(addr));
}
#define CP_ASYNC16(smem_addr, gptr) \
    asm volatile("cp.async.cg.shared.global [%0], [%1], 16;" \
        :: "r"(smem_addr), "l"(gptr))
#define CP_COMMIT() asm volatile("cp.async.commit_group;" ::: "memory")
#define CP_WAIT1()  asm volatile("cp.async.wait_group 1;" ::: "memory")
#define CP_WAIT0()  asm volatile("cp.async.wait_group 0;" ::: "memory")

__device__ __forceinline__ void mma_f16(float c[4],
    uint32_t a0, uint32_t a1, uint32_t a2, uint32_t a3,
    uint32_t b0, uint32_t b1)
{
    asm volatile(
        "mma.sync.aligned.m16n8k16.row.col.f32.f16.f16.f32 "
        "{%0,%1,%2,%3}, {%4,%5,%6,%7}, {%8,%9}, {%0,%1,%2,%3};"
        : "+f"(c[0]), "+f"(c[1]), "+f"(c[2]), "+f"(c[3])
        : "r"(a0), "r"(a1), "r"(a2), "r"(a3), "r"(b0), "r"(b1));
}

// ---------------------------------------------------------------------------
// X -> half
__global__ void convert_x_kernel(const float* __restrict__ src, __half* __restrict__ dst)
{
    const int i = (blockIdx.x * blockDim.x + threadIdx.x) * 4;
    float4 v = *(const float4*)&src[i];
    ((uint32_t*)dst)[i/2]     = pack_half2(v.x, v.y);
    ((uint32_t*)dst)[i/2 + 1] = pack_half2(v.z, v.w);
}

// W transpose + half: dst[N][K] = half(src[K][N])
__global__ void transpose_w_kernel(const float* __restrict__ src,
                                   __half* __restrict__ dst, int R, int C)
{
    __shared__ float t[32][33];
    const int bx = blockIdx.x * 32, by = blockIdx.y * 32;
    const int x = threadIdx.x, y = threadIdx.y;
    #pragma unroll
    for (int i = 0; i < 32; i += 8)
        t[y + i][x] = src[(size_t)(by + y + i) * C + bx + x];
    __syncthreads();
    #pragma unroll
    for (int i = 0; i < 32; i += 8)
        dst[(size_t)(bx + y + i) * R + by + x] = __float2half_rn(t[x][y + i]);
}

// ---------------------------------------------------------------------------
// fp16 mma.sync GEMM, ldmatrix fragments, 3-stage cp.async pipeline.
// (unchanged from R11 — known-good at ~49% tensor)
// ---------------------------------------------------------------------------
#define HPU   36                 // u32 per smem row (72 halfs, 64 used)
#define ABUFU (128*HPU)          // u32 per operand buffer
#define CPITCH 133               // floats, epilogue staging pitch

template<int MODE>
__global__ __launch_bounds__(256, 2)
void mma_gemm_kernel(const __half* __restrict__ A, const __half* __restrict__ Bt,
                     const float* __restrict__ bias, float* __restrict__ out)
{
    extern __shared__ uint32_t smu[];
    float* smf = (float*)smu;

    const int tid  = threadIdx.x;
    const int wid  = tid >> 5;
    const int lane = tid & 31;
    const int m0 = blockIdx.y * 128;
    const int n0 = blockIdx.x * 128;
    const int wm = (wid >> 1) * 32;
    const int wn = (wid & 1) * 64;
    const uint32_t sbase = smem_to_u32(smu);
    const int r = lane >> 2;
    const int cl = lane & 3;
    const int mm = lane >> 3;
    const int lrow = lane & 7;

    uint32_t aoff[2], boff[4];
    #pragma unroll
    for (int mi = 0; mi < 2; mi++)
        aoff[mi] = ((wm + mi*16 + (mm & 1)*8 + lrow) * HPU + (mm >> 1)*4) * 4;
    #pragma unroll
    for (int p = 0; p < 4; p++)
        boff[p] = ((wn + (p*2 + (mm >> 1))*8 + lrow) * HPU + (mm & 1)*4) * 4;

    float acc[2][8][4] = {};

    #pragma unroll
    for (int s = 0; s < 2; s++) {
        const int k0 = s * 64;
        #pragma unroll
        for (int i = 0; i < 4; i++) {
            const int idx = i * 256 + tid;
            const int row = idx >> 3;
            const int seg = (idx & 7) * 8;
            CP_ASYNC16(sbase + (uint32_t)(s*ABUFU + row*HPU)*4 + seg*2,
                       &A[(size_t)(m0 + row) * KDIM + k0 + seg]);
            CP_ASYNC16(sbase + (uint32_t)((3+s)*ABUFU + row*HPU)*4 + seg*2,
                       &Bt[(size_t)(n0 + row) * KDIM + k0 + seg]);
        }
        CP_COMMIT();
    }

    int stg = 0;
    int stg2 = 2;
    for (int c = 0; c < NCHUNK; c++) {
        if (c + 1 < NCHUNK) { CP_WAIT1(); } else { CP_WAIT0(); }
        __syncthreads();

        if (c + 2 < NCHUNK) {
            const int k0 = (c + 2) * 64;
            #pragma unroll
            for (int i = 0; i < 4; i++) {
                const int idx = i * 256 + tid;
                const int row = idx >> 3;
                const int seg = (idx & 7) * 8;
                CP_ASYNC16(sbase + (uint32_t)(stg2*ABUFU + row*HPU)*4 + seg*2,
                           &A[(size_t)(m0 + row) * KDIM + k0 + seg]);
                CP_ASYNC16(sbase + (uint32_t)((3+stg2)*ABUFU + row*HPU)*4 + seg*2,
                           &Bt[(size_t)(n0 + row) * KDIM + k0 + seg]);
            }
            CP_COMMIT();
        }

        const uint32_t aB = sbase + (uint32_t)(stg*ABUFU)*4;
        const uint32_t bB = sbase + (uint32_t)((3+stg)*ABUFU)*4;

        #pragma unroll
        for (int ks = 0; ks < 4; ks++) {
            const uint32_t kbyte = ks * 32;
            uint32_t af[2][4];
            #pragma unroll
            for (int mi = 0; mi < 2; mi++)
                ldsm_x4(af[mi][0], af[mi][1], af[mi][2], af[mi][3],
                        aB + aoff[mi] + kbyte);
            uint32_t bf[8][2];
            #pragma unroll
            for (int p = 0; p < 4; p++)
                ldsm_x4(bf[2*p][0], bf[2*p][1], bf[2*p+1][0], bf[2*p+1][1],
                        bB + boff[p] + kbyte);
            #pragma unroll
            for (int mi = 0; mi < 2; mi++)
                #pragma unroll
                for (int ni = 0; ni < 8; ni++)
                    mma_f16(acc[mi][ni], af[mi][0], af[mi][1], af[mi][2], af[mi][3],
                            bf[ni][0], bf[ni][1]);
        }
        stg  = (stg  == 2) ? 0 : stg  + 1;
        stg2 = (stg2 == 2) ? 0 : stg2 + 1;
    }
    __syncthreads();

    #pragma unroll
    for (int mi = 0; mi < 2; mi++)
        #pragma unroll
        for (int ni = 0; ni < 8; ni++) {
            const int row = wm + mi*16 + r;
            const int col = wn + ni*8 + 2*cl;
            smf[row * CPITCH + col]       = acc[mi][ni][0];
            smf[row * CPITCH + col + 1]   = acc[mi][ni][1];
            smf[(row+8) * CPITCH + col]   = acc[mi][ni][2];
            smf[(row+8) * CPITCH + col+1] = acc[mi][ni][3];
        }
    __syncthreads();

    if (MODE == 1) {
        #pragma unroll
        for (int i = 0; i < 16; i++) {
            const int f = i * 256 + tid;
            const int row  = f >> 5;
            const int col  = (f & 31) * 4;
            const int m  = m0 + row;
            const int ng = n0 + col;
            float4 v = { smf[row*CPITCH + col + 0] + bias[ng + 0],
                         smf[row*CPITCH + col + 1] + bias[ng + 1],
                         smf[row*CPITCH + col + 2] + bias[ng + 2],
                         smf[row*CPITCH + col + 3] + bias[ng + 3] };
            *(float4*)&out[(size_t)m * D_MODEL + ng] = v;
        }
    } else {
        const int wsel = n0 / D_MODEL;
        if (wsel < 2) {
            __half* dst = (wsel == 0) ? g_q : g_k;
            const float sc = (wsel == 0) ? QSCALE : 1.0f;
            #pragma unroll
            for (int i = 0; i < 16; i++) {
                const int f = i * 256 + tid;
                const int row  = f >> 5;
                const int col  = (f & 31) * 4;
                const int m  = m0 + row;
                const int ng = n0 + col;
                float4 v = { (smf[row*CPITCH + col + 0] + bias[ng + 0]) * sc,
                             (smf[row*CPITCH + col + 1] + bias[ng + 1]) * sc,
                             (smf[row*CPITCH + col + 2] + bias[ng + 2]) * sc,
                             (smf[row*CPITCH + col + 3] + bias[ng + 3]) * sc };
                const int h = (ng % D_MODEL) >> 6;
                const int d = ng & 63;
                const int bb = m >> 11;
                const int l  = m & (SEQ - 1);
                const size_t off = (((size_t)bb * HEADS + h) * SEQ + l) * HD + d;
                ((uint32_t*)dst)[off/2]     = pack_half2(v.x, v.y);
                ((uint32_t*)dst)[off/2 + 1] = pack_half2(v.z, v.w);
            }
        } else {
            const int bb = m0 >> 11;
            const int l0 = m0 & (SEQ - 1);
            #pragma unroll
            for (int it = 0; it < 32; it++) {
                const int idx = it * 256 + tid;
                const int d  = idx >> 6;
                const int l2 = idx & 63;
                const int ng = n0 + d;
                const float bv = bias[ng];
                const int h  = (ng % D_MODEL) >> 6;
                const int dd = ng & 63;
                const float v0 = smf[(2*l2)   * CPITCH + d] + bv;
                const float v1 = smf[(2*l2+1) * CPITCH + d] + bv;
                const size_t off = ((size_t)(bb * HEADS + h) * HD + dd) * SEQ + l0 + 2*l2;
                ((uint32_t*)g_vt)[off/2] = pack_half2(v0, v1);
            }
        }
    }
}

// ---------------------------------------------------------------------------
// Flash attention: 128-key tiles, two barrier-free 64-key sub-phases.
// CTA = (head, 128 q). 8 warps x 16q. K smem [key 128][d 64] pitch 72h,
// VT smem [d 64][key 128] pitch 136h. cp.async double buffered.
// f16x2 exp2 softmax, ones-MMA row sums, P in registers.
// ---------------------------------------------------------------------------
#define KPU   36                         // u32 per K row (72 halfs)
#define VPU   68                         // u32 per VT row (136 halfs)
#define KTILEU (128*KPU)                 // 4608 u32
#define VTILEU (64*VPU)                  // 4352 u32
#define STAGEU (KTILEU + VTILEU)         // 8960 u32 per stage

__global__ __launch_bounds__(256, 2) void attn_kernel(__half* __restrict__ attn_out)
{
    extern __shared__ uint32_t smA[];

    const int tid  = threadIdx.x;
    const int wid  = tid >> 5;
    const int lane = tid & 31;
    const int r  = lane >> 2;
    const int cl = lane & 3;
    const int mm = lane >> 3;
    const int lrow = lane & 7;
    const int qt = blockIdx.x;
    const int bh = blockIdx.y;
    const size_t head_base = (size_t)bh * SEQ * HD;   // halfs
    const int q0 = wid * 16;

    uint32_t fkoff[4], fvoff[4];
    #pragma unroll
    for (int p = 0; p < 4; p++) {
        fkoff[p] = (((p*2 + (mm >> 1))*8 + lrow) * KPU + (mm & 1)*4) * 4;
        fvoff[p] = (((p*2 + (mm >> 1))*8 + lrow) * VPU + (mm & 1)*4) * 4;
    }

    // Q fragments (g_q pre-scaled): 4 ksteps x 4 regs
    uint32_t qf[4][4];
    {
        const uint32_t* Qp = (const uint32_t*)&g_q[head_base + (size_t)(qt*128 + q0) * HD];
        #pragma unroll
        for (int kk = 0; kk < 4; kk++) {
            qf[kk][0] = Qp[(size_t)r     * 32 + kk*8 + cl];
            qf[kk][1] = Qp[(size_t)(r+8) * 32 + kk*8 + cl];
            qf[kk][2] = Qp[(size_t)r     * 32 + kk*8 + cl + 4];
            qf[kk][3] = Qp[(size_t)(r+8) * 32 + kk*8 + cl + 4];
        }
    }

    float o[8][4] = {};
    float mo0 = -INFINITY, mo1 = -INFINITY, lo0 = 0.0f, lo1 = 0.0f;

    const uint32_t sb = smem_to_u32(smA);
    const uint32_t kb[2] = { sb,              sb + STAGEU*4 };
    const uint32_t vb[2] = { sb + KTILEU*4,   sb + (STAGEU + KTILEU)*4 };
    const size_t vt_base = (size_t)bh * HD * SEQ;

    // prologue tile 0: K 128 rows x 8 segs (1024), VT 64 rows x 16 segs (1024)
    #pragma unroll
    for (int i = 0; i < 8; i++) {
        const int idx = i * 256 + tid;     // 0..2047
        if (idx < 1024) {
            const int row = idx >> 3;
            const int seg = (idx & 7) * 8;
            CP_ASYNC16(kb[0] + (uint32_t)(row*KPU)*4 + seg*2,
                       (const char*)&g_k[head_base + (size_t)row * HD + seg]);
        } else {
            const int j = idx - 1024;
            const int row = j >> 4;
            const int seg = (j & 15) * 8;
            CP_ASYNC16(vb[0] + (uint32_t)(row*VPU)*4 + seg*2,
                       (const char*)&g_vt[vt_base + (size_t)row * SEQ + seg]);
        }
    }
    CP_COMMIT();

    for (int kt = 0; kt < SEQ/128; kt++) {
        const int buf = kt & 1;
        __syncthreads();   // everyone done with buffer buf^1
        if (kt + 1 < SEQ/128) {
            const int nb = buf ^ 1;
            #pragma unroll
            for (int i = 0; i < 8; i++) {
                const int idx = i * 256 + tid;
                if (idx < 1024) {
                    const int row = idx >> 3;
                    const int seg = (idx & 7) * 8;
                    CP_ASYNC16(kb[nb] + (uint32_t)(row*KPU)*4 + seg*2,
                               (const char*)&g_k[head_base + (size_t)((kt+1)*128 + row) * HD + seg]);
                } else {
                    const int j = idx - 1024;
                    const int row = j >> 4;
                    const int seg = (j & 15) * 8;
                    CP_ASYNC16(vb[nb] + (uint32_t)(row*VPU)*4 + seg*2,
                               (const char*)&g_vt[vt_base + (size_t)row * SEQ + (kt+1)*128 + seg]);
                }
            }
            CP_COMMIT();
            CP_WAIT1();
        } else {
            CP_WAIT0();
        }
        __syncthreads();   // tile kt visible

        // ---- two 64-key sub-phases, no barrier between them ----
        #pragma unroll
        for (int sub = 0; sub < 2; sub++) {
            const uint32_t Kc = kb[buf] + sub * (64*KPU*4);  // +64 key rows
            const uint32_t Vc = vb[buf] + sub * 128;         // +64 keys in row

            // S = Q K^T
            float s[8][4] = {};
            #pragma unroll
            for (int kk = 0; kk < 4; kk++) {
                const uint32_t kbyte = kk * 32;
                uint32_t bf[8][2];
                #pragma unroll
                for (int p = 0; p < 4; p++)
                    ldsm_x4(bf[2*p][0], bf[2*p][1], bf[2*p+1][0], bf[2*p+1][1],
                            Kc + fkoff[p] + kbyte);
                #pragma unroll
                for (int nt = 0; nt < 8; nt++)
                    mma_f16(s[nt], qf[kk][0], qf[kk][1], qf[kk][2], qf[kk][3],
                            bf[nt][0], bf[nt][1]);
            }

            // row max (quad reduction)
            float mx0 = -INFINITY, mx1 = -INFINITY;
            #pragma unroll
            for (int nt = 0; nt < 8; nt++) {
                mx0 = fmaxf(mx0, fmaxf(s[nt][0], s[nt][1]));
                mx1 = fmaxf(mx1, fmaxf(s[nt][2], s[nt][3]));
            }
            mx0 = fmaxf(mx0, __shfl_xor_sync(0xffffffffu, mx0, 1));
            mx0 = fmaxf(mx0, __shfl_xor_sync(0xffffffffu, mx0, 2));
            mx1 = fmaxf(mx1, __shfl_xor_sync(0xffffffffu, mx1, 1));
            mx1 = fmaxf(mx1, __shfl_xor_sync(0xffffffffu, mx1, 2));
            const float mn0 = fmaxf(mo0, mx0);
            const float mn1 = fmaxf(mo1, mx1);
            const float a0 = exp2f(mo0 - mn0);
            const float a1 = exp2f(mo1 - mn1);

            // P = exp2(s - m) packed as PV A-fragments
            uint32_t pf[4][4];
            #pragma unroll
            for (int kk = 0; kk < 4; kk++) {
                pf[kk][0] = exp2_h2(pack_half2(s[2*kk][0]   - mn0, s[2*kk][1]   - mn0));
                pf[kk][1] = exp2_h2(pack_half2(s[2*kk][2]   - mn1, s[2*kk][3]   - mn1));
                pf[kk][2] = exp2_h2(pack_half2(s[2*kk+1][0] - mn0, s[2*kk+1][1] - mn0));
                pf[kk][3] = exp2_h2(pack_half2(s[2*kk+1][2] - mn1, s[2*kk+1][3] - mn1));
            }

            // row sums via ones-MMA
            float ls[4] = {};
            #pragma unroll
            for (int kk = 0; kk < 4; kk++)
                mma_f16(ls, pf[kk][0], pf[kk][1], pf[kk][2], pf[kk][3], ONES2, ONES2);

            lo0 = a0 * lo0 + ls[0];  mo0 = mn0;
            lo1 = a1 * lo1 + ls[2];  mo1 = mn1;
            #pragma unroll
            for (int nt = 0; nt < 8; nt++) {
                o[nt][0] *= a0; o[nt][1] *= a0;
                o[nt][2] *= a1; o[nt][3] *= a1;
            }

            // O += P V
            #pragma unroll
            for (int kk = 0; kk < 4; kk++) {
                const uint32_t kbyte = kk * 32;
                uint32_t bf[8][2];
                #pragma unroll
                for (int p = 0; p < 4; p++)
                    ldsm_x4(bf[2*p][0], bf[2*p][1], bf[2*p+1][0], bf[2*p+1][1],
                            Vc + fvoff[p] + kbyte);
                #pragma unroll
                for (int nt = 0; nt < 8; nt++)
                    mma_f16(o[nt], pf[kk][0], pf[kk][1], pf[kk][2], pf[kk][3],
                            bf[nt][0], bf[nt][1]);
            }
        }
    }

    // ---- epilogue: normalize, write half [B, L, H*64] ----
    const float inv0 = 1.0f / lo0;
    const float inv1 = 1.0f / lo1;
    const int bb = bh / HEADS;
    const int h  = bh % HEADS;
    const int row0 = qt*128 + q0 + r;
    #pragma unroll
    for (int nt = 0; nt < 8; nt++) {
        const int d = h * 64 + nt*8 + 2*cl;
        ((uint32_t*)attn_out)[(((size_t)bb * SEQ + row0)     * D_MODEL + d)/2] =
            pack_half2(o[nt][0] * inv0, o[nt][1] * inv0);
        ((uint32_t*)attn_out)[(((size_t)bb * SEQ + row0 + 8) * D_MODEL + d)/2] =
            pack_half2(o[nt][2] * inv1, o[nt][3] * inv1);
    }
}

// ---------------------------------------------------------------------------

static const int ATTN_SMEM = 2 * STAGEU * (int)sizeof(uint32_t);         // 71680
static const int GEMM_SMEM = 6 * ABUFU * (int)sizeof(uint32_t);          // 110592

extern "C" void kernel_launch(void* const* d_in, const int* in_sizes, int n_in,
                              void* d_out, int out_size)
{
    const float* x     = (const float*)d_in[0];
    const float* W_qkv = (const float*)d_in[1];
    const float* b_qkv = (const float*)d_in[2];
    const float* W_out = (const float*)d_in[3];
    const float* b_out = (const float*)d_in[4];
    float* out = (float*)d_out;

    cudaFuncSetAttribute(attn_kernel,
                         cudaFuncAttributeMaxDynamicSharedMemorySize, ATTN_SMEM);
    cudaFuncSetAttribute(mma_gemm_kernel<0>,
                         cudaFuncAttributeMaxDynamicSharedMemorySize, GEMM_SMEM);
    cudaFuncSetAttribute(mma_gemm_kernel<1>,
                         cudaFuncAttributeMaxDynamicSharedMemorySize, GEMM_SMEM);

    __half *xh, *wqkv_t, *wout_t, *attn_h;
    cudaGetSymbolAddress((void**)&xh, g_h);
    cudaGetSymbolAddress((void**)&wqkv_t, g_wqkv_t);
    cudaGetSymbolAddress((void**)&wout_t, g_wout_t);
    attn_h = xh;   // reuse: X consumed by qkv gemm before attn writes

    convert_x_kernel<<<M_TOTAL*D_MODEL/(4*256), 256>>>(x, xh);
    transpose_w_kernel<<<dim3(N_QKV/32, KDIM/32), dim3(32, 8)>>>(W_qkv, wqkv_t, KDIM, N_QKV);
    transpose_w_kernel<<<dim3(D_MODEL/32, KDIM/32), dim3(32, 8)>>>(W_out, wout_t, KDIM, D_MODEL);

    dim3 g1(N_QKV / 128, M_TOTAL / 128);
    mma_gemm_kernel<0><<<g1, 256, GEMM_SMEM>>>(xh, wqkv_t, b_qkv, nullptr);

    dim3 g2(SEQ / 128, BH);
    attn_kernel<<<g2, 256, ATTN_SMEM>>>(attn_h);

    dim3 g3(D_MODEL / 128, M_TOTAL / 128);
    mma_gemm_kernel<1><<<g3, 256, GEMM_SMEM>>>(attn_h, wout_t, b_out, out);
}

// round 13
// speedup vs baseline: 8.0499x; 1.0032x over previous
#include <cuda_runtime.h>
#include <cuda_fp16.h>
#include <math.h>
#include <stdint.h>

#define D_MODEL 768
#define HEADS   12
#define HD      64
#define BATCH   4
#define SEQ     2048
#define M_TOTAL (BATCH*SEQ)      // 8192
#define N_QKV   (3*D_MODEL)      // 2304
#define BH      (BATCH*HEADS)    // 48
#define KDIM    768
#define NCHUNK  (KDIM/64)        // 12 chunks of K=64

// q scale: 1/sqrt(64) * log2(e)  (softmax done in exp2 domain)
#define QSCALE 0.1803368801111306f
#define ONES2  0x3C003C00u       // half2(1.0, 1.0)

// Scratch (device globals)
__device__ __half g_q[BH*SEQ*HD];       // pre-scaled by QSCALE
__device__ __half g_k[BH*SEQ*HD];
__device__ __half g_vt[BH*HD*SEQ];      // [bh][d][seq]
__device__ __half g_h[M_TOTAL*D_MODEL]; // half X, later attn output
__device__ __half g_wqkv_t[N_QKV*KDIM];
__device__ __half g_wout_t[D_MODEL*KDIM];

// ---------------------------------------------------------------------------
__device__ __forceinline__ uint32_t smem_to_u32(const void* p) {
    uint32_t a;
    asm("{ .reg .u64 t; cvta.to.shared.u64 t, %1; cvt.u32.u64 %0, t; }"
        : "=r"(a) : "l"(p));
    return a;
}
__device__ __forceinline__ uint32_t pack_half2(float lo, float hi) {
    uint32_t u;
    asm("cvt.rn.f16x2.f32 %0, %1, %2;" : "=r"(u) : "f"(hi), "f"(lo));
    return u;
}
__device__ __forceinline__ uint32_t exp2_h2(uint32_t a) {
    uint32_t d;
    asm("ex2.approx.f16x2 %0, %1;" : "=r"(d) : "r"(a));
    return d;
}
__device__ __forceinline__ void ldsm_x4(uint32_t& r0, uint32_t& r1,
                                        uint32_t& r2, uint32_t& r3, uint32_t addr)
{
    asm volatile("ldmatrix.sync.aligned.m8n8.x4.shared.b16 {%0,%1,%2,%3}, [%4];"
        : "=r"(r0), "=r"(r1), "=r"(r2), "=r"(r3) : "r"(addr));
}
#define CP_ASYNC16(smem_addr, gptr) \
    asm volatile("cp.async.cg.shared.global [%0], [%1], 16;" \
        :: "r"(smem_addr), "l"(gptr))
#define CP_COMMIT() asm volatile("cp.async.commit_group;" ::: "memory")
#define CP_WAIT1()  asm volatile("cp.async.wait_group 1;" ::: "memory")
#define CP_WAIT0()  asm volatile("cp.async.wait_group 0;" ::: "memory")

__device__ __forceinline__ void mma_f16(float c[4],
    uint32_t a0, uint32_t a1, uint32_t a2, uint32_t a3,
    uint32_t b0, uint32_t b1)
{
    asm volatile(
        "mma.sync.aligned.m16n8k16.row.col.f32.f16.f16.f32 "
        "{%0,%1,%2,%3}, {%4,%5,%6,%7}, {%8,%9}, {%0,%1,%2,%3};"
        : "+f"(c[0]), "+f"(c[1]), "+f"(c[2]), "+f"(c[3])
        : "r"(a0), "r"(a1), "r"(a2), "r"(a3), "r"(b0), "r"(b1));
}

// ---------------------------------------------------------------------------
// X -> half
__global__ void convert_x_kernel(const float* __restrict__ src, __half* __restrict__ dst)
{
    const int i = (blockIdx.x * blockDim.x + threadIdx.x) * 4;
    float4 v = *(const float4*)&src[i];
    ((uint32_t*)dst)[i/2]     = pack_half2(v.x, v.y);
    ((uint32_t*)dst)[i/2 + 1] = pack_half2(v.z, v.w);
}

// W transpose + half: dst[N][K] = half(src[K][N])
__global__ void transpose_w_kernel(const float* __restrict__ src,
                                   __half* __restrict__ dst, int R, int C)
{
    __shared__ float t[32][33];
    const int bx = blockIdx.x * 32, by = blockIdx.y * 32;
    const int x = threadIdx.x, y = threadIdx.y;
    #pragma unroll
    for (int i = 0; i < 32; i += 8)
        t[y + i][x] = src[(size_t)(by + y + i) * C + bx + x];
    __syncthreads();
    #pragma unroll
    for (int i = 0; i < 32; i += 8)
        dst[(size_t)(bx + y + i) * R + by + x] = __float2half_rn(t[x][y + i]);
}

// ---------------------------------------------------------------------------
// fp16 mma.sync GEMM, ldmatrix fragments, 3-stage cp.async pipeline,
// REGISTER double-buffered B-fragments across ksteps (R13 experiment).
// CTA 128x128, 8 warps of 32m x 64n, K chunks of 64.
// MODE 0: scatter q(*QSCALE)/k to [bh][seq][64]; V transposed into g_vt.
// MODE 1: fp32 [M][768] out.
// ---------------------------------------------------------------------------
#define HPU   36                 // u32 per smem row (72 halfs, 64 used)
#define ABUFU (128*HPU)          // u32 per operand buffer
#define CPITCH 133               // floats, epilogue staging pitch

template<int MODE>
__global__ __launch_bounds__(256, 2)
void mma_gemm_kernel(const __half* __restrict__ A, const __half* __restrict__ Bt,
                     const float* __restrict__ bias, float* __restrict__ out)
{
    extern __shared__ uint32_t smu[];
    float* smf = (float*)smu;

    const int tid  = threadIdx.x;
    const int wid  = tid >> 5;
    const int lane = tid & 31;
    const int m0 = blockIdx.y * 128;
    const int n0 = blockIdx.x * 128;
    const int wm = (wid >> 1) * 32;
    const int wn = (wid & 1) * 64;
    const uint32_t sbase = smem_to_u32(smu);
    const int r = lane >> 2;
    const int cl = lane & 3;
    const int mm = lane >> 3;
    const int lrow = lane & 7;

    uint32_t aoff[2], boff[4];
    #pragma unroll
    for (int mi = 0; mi < 2; mi++)
        aoff[mi] = ((wm + mi*16 + (mm & 1)*8 + lrow) * HPU + (mm >> 1)*4) * 4;
    #pragma unroll
    for (int p = 0; p < 4; p++)
        boff[p] = ((wn + (p*2 + (mm >> 1))*8 + lrow) * HPU + (mm & 1)*4) * 4;

    float acc[2][8][4] = {};

    #pragma unroll
    for (int s = 0; s < 2; s++) {
        const int k0 = s * 64;
        #pragma unroll
        for (int i = 0; i < 4; i++) {
            const int idx = i * 256 + tid;
            const int row = idx >> 3;
            const int seg = (idx & 7) * 8;
            CP_ASYNC16(sbase + (uint32_t)(s*ABUFU + row*HPU)*4 + seg*2,
                       &A[(size_t)(m0 + row) * KDIM + k0 + seg]);
            CP_ASYNC16(sbase + (uint32_t)((3+s)*ABUFU + row*HPU)*4 + seg*2,
                       &Bt[(size_t)(n0 + row) * KDIM + k0 + seg]);
        }
        CP_COMMIT();
    }

    int stg = 0;
    int stg2 = 2;
    for (int c = 0; c < NCHUNK; c++) {
        if (c + 1 < NCHUNK) { CP_WAIT1(); } else { CP_WAIT0(); }
        __syncthreads();

        const uint32_t aB = sbase + (uint32_t)(stg*ABUFU)*4;
        const uint32_t bB = sbase + (uint32_t)((3+stg)*ABUFU)*4;

        // B-fragment register double buffer; kstep 0 loaded up front
        uint32_t bf[2][8][2];
        #pragma unroll
        for (int p = 0; p < 4; p++)
            ldsm_x4(bf[0][2*p][0], bf[0][2*p][1], bf[0][2*p+1][0], bf[0][2*p+1][1],
                    bB + boff[p]);

        // issue next-next chunk's cp.async AFTER the first LDSM wave
        if (c + 2 < NCHUNK) {
            const int k0 = (c + 2) * 64;
            #pragma unroll
            for (int i = 0; i < 4; i++) {
                const int idx = i * 256 + tid;
                const int row = idx >> 3;
                const int seg = (idx & 7) * 8;
                CP_ASYNC16(sbase + (uint32_t)(stg2*ABUFU + row*HPU)*4 + seg*2,
                           &A[(size_t)(m0 + row) * KDIM + k0 + seg]);
                CP_ASYNC16(sbase + (uint32_t)((3+stg2)*ABUFU + row*HPU)*4 + seg*2,
                           &Bt[(size_t)(n0 + row) * KDIM + k0 + seg]);
            }
            CP_COMMIT();
        }

        #pragma unroll
        for (int ks = 0; ks < 4; ks++) {
            const int cur = ks & 1;
            const int nxt = cur ^ 1;
            const uint32_t kbyte = ks * 32;

            // A fragments for this kstep
            uint32_t af[2][4];
            #pragma unroll
            for (int mi = 0; mi < 2; mi++)
                ldsm_x4(af[mi][0], af[mi][1], af[mi][2], af[mi][3],
                        aB + aoff[mi] + kbyte);

            // prefetch next kstep's B fragments (independent of MMAs below)
            if (ks < 3) {
                const uint32_t nkbyte = kbyte + 32;
                #pragma unroll
                for (int p = 0; p < 4; p++)
                    ldsm_x4(bf[nxt][2*p][0], bf[nxt][2*p][1],
                            bf[nxt][2*p+1][0], bf[nxt][2*p+1][1],
                            bB + boff[p] + nkbyte);
            }

            #pragma unroll
            for (int mi = 0; mi < 2; mi++)
                #pragma unroll
                for (int ni = 0; ni < 8; ni++)
                    mma_f16(acc[mi][ni], af[mi][0], af[mi][1], af[mi][2], af[mi][3],
                            bf[cur][ni][0], bf[cur][ni][1]);
        }
        stg  = (stg  == 2) ? 0 : stg  + 1;
        stg2 = (stg2 == 2) ? 0 : stg2 + 1;
    }
    __syncthreads();

    #pragma unroll
    for (int mi = 0; mi < 2; mi++)
        #pragma unroll
        for (int ni = 0; ni < 8; ni++) {
            const int row = wm + mi*16 + r;
            const int col = wn + ni*8 + 2*cl;
            smf[row * CPITCH + col]       = acc[mi][ni][0];
            smf[row * CPITCH + col + 1]   = acc[mi][ni][1];
            smf[(row+8) * CPITCH + col]   = acc[mi][ni][2];
            smf[(row+8) * CPITCH + col+1] = acc[mi][ni][3];
        }
    __syncthreads();

    if (MODE == 1) {
        #pragma unroll
        for (int i = 0; i < 16; i++) {
            const int f = i * 256 + tid;
            const int row  = f >> 5;
            const int col  = (f & 31) * 4;
            const int m  = m0 + row;
            const int ng = n0 + col;
            float4 v = { smf[row*CPITCH + col + 0] + bias[ng + 0],
                         smf[row*CPITCH + col + 1] + bias[ng + 1],
                         smf[row*CPITCH + col + 2] + bias[ng + 2],
                         smf[row*CPITCH + col + 3] + bias[ng + 3] };
            *(float4*)&out[(size_t)m * D_MODEL + ng] = v;
        }
    } else {
        const int wsel = n0 / D_MODEL;
        if (wsel < 2) {
            __half* dst = (wsel == 0) ? g_q : g_k;
            const float sc = (wsel == 0) ? QSCALE : 1.0f;
            #pragma unroll
            for (int i = 0; i < 16; i++) {
                const int f = i * 256 + tid;
                const int row  = f >> 5;
                const int col  = (f & 31) * 4;
                const int m  = m0 + row;
                const int ng = n0 + col;
                float4 v = { (smf[row*CPITCH + col + 0] + bias[ng + 0]) * sc,
                             (smf[row*CPITCH + col + 1] + bias[ng + 1]) * sc,
                             (smf[row*CPITCH + col + 2] + bias[ng + 2]) * sc,
                             (smf[row*CPITCH + col + 3] + bias[ng + 3]) * sc };
                const int h = (ng % D_MODEL) >> 6;
                const int d = ng & 63;
                const int bb = m >> 11;
                const int l  = m & (SEQ - 1);
                const size_t off = (((size_t)bb * HEADS + h) * SEQ + l) * HD + d;
                ((uint32_t*)dst)[off/2]     = pack_half2(v.x, v.y);
                ((uint32_t*)dst)[off/2 + 1] = pack_half2(v.z, v.w);
            }
        } else {
            const int bb = m0 >> 11;
            const int l0 = m0 & (SEQ - 1);
            #pragma unroll
            for (int it = 0; it < 32; it++) {
                const int idx = it * 256 + tid;
                const int d  = idx >> 6;
                const int l2 = idx & 63;
                const int ng = n0 + d;
                const float bv = bias[ng];
                const int h  = (ng % D_MODEL) >> 6;
                const int dd = ng & 63;
                const float v0 = smf[(2*l2)   * CPITCH + d] + bv;
                const float v1 = smf[(2*l2+1) * CPITCH + d] + bv;
                const size_t off = ((size_t)(bb * HEADS + h) * HD + dd) * SEQ + l0 + 2*l2;
                ((uint32_t*)g_vt)[off/2] = pack_half2(v0, v1);
            }
        }
    }
}

// ---------------------------------------------------------------------------
// Flash attention (unchanged from R12): 128-key tiles, two barrier-free
// 64-key sub-phases, f16x2 exp2 softmax, ones-MMA row sums, P in registers.
// ---------------------------------------------------------------------------
#define KPU   36                         // u32 per K row (72 halfs)
#define VPU   68                         // u32 per VT row (136 halfs)
#define KTILEU (128*KPU)                 // 4608 u32
#define VTILEU (64*VPU)                  // 4352 u32
#define STAGEU (KTILEU + VTILEU)         // 8960 u32 per stage

__global__ __launch_bounds__(256, 2) void attn_kernel(__half* __restrict__ attn_out)
{
    extern __shared__ uint32_t smA[];

    const int tid  = threadIdx.x;
    const int wid  = tid >> 5;
    const int lane = tid & 31;
    const int r  = lane >> 2;
    const int cl = lane & 3;
    const int mm = lane >> 3;
    const int lrow = lane & 7;
    const int qt = blockIdx.x;
    const int bh = blockIdx.y;
    const size_t head_base = (size_t)bh * SEQ * HD;   // halfs
    const int q0 = wid * 16;

    uint32_t fkoff[4], fvoff[4];
    #pragma unroll
    for (int p = 0; p < 4; p++) {
        fkoff[p] = (((p*2 + (mm >> 1))*8 + lrow) * KPU + (mm & 1)*4) * 4;
        fvoff[p] = (((p*2 + (mm >> 1))*8 + lrow) * VPU + (mm & 1)*4) * 4;
    }

    uint32_t qf[4][4];
    {
        const uint32_t* Qp = (const uint32_t*)&g_q[head_base + (size_t)(qt*128 + q0) * HD];
        #pragma unroll
        for (int kk = 0; kk < 4; kk++) {
            qf[kk][0] = Qp[(size_t)r     * 32 + kk*8 + cl];
            qf[kk][1] = Qp[(size_t)(r+8) * 32 + kk*8 + cl];
            qf[kk][2] = Qp[(size_t)r     * 32 + kk*8 + cl + 4];
            qf[kk][3] = Qp[(size_t)(r+8) * 32 + kk*8 + cl + 4];
        }
    }

    float o[8][4] = {};
    float mo0 = -INFINITY, mo1 = -INFINITY, lo0 = 0.0f, lo1 = 0.0f;

    const uint32_t sb = smem_to_u32(smA);
    const uint32_t kb[2] = { sb,              sb + STAGEU*4 };
    const uint32_t vb[2] = { sb + KTILEU*4,   sb + (STAGEU + KTILEU)*4 };
    const size_t vt_base = (size_t)bh * HD * SEQ;

    #pragma unroll
    for (int i = 0; i < 8; i++) {
        const int idx = i * 256 + tid;
        if (idx < 1024) {
            const int row = idx >> 3;
            const int seg = (idx & 7) * 8;
            CP_ASYNC16(kb[0] + (uint32_t)(row*KPU)*4 + seg*2,
                       (const char*)&g_k[head_base + (size_t)row * HD + seg]);
        } else {
            const int j = idx - 1024;
            const int row = j >> 4;
            const int seg = (j & 15) * 8;
            CP_ASYNC16(vb[0] + (uint32_t)(row*VPU)*4 + seg*2,
                       (const char*)&g_vt[vt_base + (size_t)row * SEQ + seg]);
        }
    }
    CP_COMMIT();

    for (int kt = 0; kt < SEQ/128; kt++) {
        const int buf = kt & 1;
        __syncthreads();
        if (kt + 1 < SEQ/128) {
            const int nb = buf ^ 1;
            #pragma unroll
            for (int i = 0; i < 8; i++) {
                const int idx = i * 256 + tid;
                if (idx < 1024) {
                    const int row = idx >> 3;
                    const int seg = (idx & 7) * 8;
                    CP_ASYNC16(kb[nb] + (uint32_t)(row*KPU)*4 + seg*2,
                               (const char*)&g_k[head_base + (size_t)((kt+1)*128 + row) * HD + seg]);
                } else {
                    const int j = idx - 1024;
                    const int row = j >> 4;
                    const int seg = (j & 15) * 8;
                    CP_ASYNC16(vb[nb] + (uint32_t)(row*VPU)*4 + seg*2,
                               (const char*)&g_vt[vt_base + (size_t)row * SEQ + (kt+1)*128 + seg]);
                }
            }
            CP_COMMIT();
            CP_WAIT1();
        } else {
            CP_WAIT0();
        }
        __syncthreads();

        #pragma unroll
        for (int sub = 0; sub < 2; sub++) {
            const uint32_t Kc = kb[buf] + sub * (64*KPU*4);
            const uint32_t Vc = vb[buf] + sub * 128;

            float s[8][4] = {};
            #pragma unroll
            for (int kk = 0; kk < 4; kk++) {
                const uint32_t kbyte = kk * 32;
                uint32_t bf[8][2];
                #pragma unroll
                for (int p = 0; p < 4; p++)
                    ldsm_x4(bf[2*p][0], bf[2*p][1], bf[2*p+1][0], bf[2*p+1][1],
                            Kc + fkoff[p] + kbyte);
                #pragma unroll
                for (int nt = 0; nt < 8; nt++)
                    mma_f16(s[nt], qf[kk][0], qf[kk][1], qf[kk][2], qf[kk][3],
                            bf[nt][0], bf[nt][1]);
            }

            float mx0 = -INFINITY, mx1 = -INFINITY;
            #pragma unroll
            for (int nt = 0; nt < 8; nt++) {
                mx0 = fmaxf(mx0, fmaxf(s[nt][0], s[nt][1]));
                mx1 = fmaxf(mx1, fmaxf(s[nt][2], s[nt][3]));
            }
            mx0 = fmaxf(mx0, __shfl_xor_sync(0xffffffffu, mx0, 1));
            mx0 = fmaxf(mx0, __shfl_xor_sync(0xffffffffu, mx0, 2));
            mx1 = fmaxf(mx1, __shfl_xor_sync(0xffffffffu, mx1, 1));
            mx1 = fmaxf(mx1, __shfl_xor_sync(0xffffffffu, mx1, 2));
            const float mn0 = fmaxf(mo0, mx0);
            const float mn1 = fmaxf(mo1, mx1);
            const float a0 = exp2f(mo0 - mn0);
            const float a1 = exp2f(mo1 - mn1);

            uint32_t pf[4][4];
            #pragma unroll
            for (int kk = 0; kk < 4; kk++) {
                pf[kk][0] = exp2_h2(pack_half2(s[2*kk][0]   - mn0, s[2*kk][1]   - mn0));
                pf[kk][1] = exp2_h2(pack_half2(s[2*kk][2]   - mn1, s[2*kk][3]   - mn1));
                pf[kk][2] = exp2_h2(pack_half2(s[2*kk+1][0] - mn0, s[2*kk+1][1] - mn0));
                pf[kk][3] = exp2_h2(pack_half2(s[2*kk+1][2] - mn1, s[2*kk+1][3] - mn1));
            }

            float ls[4] = {};
            #pragma unroll
            for (int kk = 0; kk < 4; kk++)
                mma_f16(ls, pf[kk][0], pf[kk][1], pf[kk][2], pf[kk][3], ONES2, ONES2);

            lo0 = a0 * lo0 + ls[0];  mo0 = mn0;
            lo1 = a1 * lo1 + ls[2];  mo1 = mn1;
            #pragma unroll
            for (int nt = 0; nt < 8; nt++) {
                o[nt][0] *= a0; o[nt][1] *= a0;
                o[nt][2] *= a1; o[nt][3] *= a1;
            }

            #pragma unroll
            for (int kk = 0; kk < 4; kk++) {
                const uint32_t kbyte = kk * 32;
                uint32_t bf[8][2];
                #pragma unroll
                for (int p = 0; p < 4; p++)
                    ldsm_x4(bf[2*p][0], bf[2*p][1], bf[2*p+1][0], bf[2*p+1][1],
                            Vc + fvoff[p] + kbyte);
                #pragma unroll
                for (int nt = 0; nt < 8; nt++)
                    mma_f16(o[nt], pf[kk][0], pf[kk][1], pf[kk][2], pf[kk][3],
                            bf[nt][0], bf[nt][1]);
            }
        }
    }

    const float inv0 = 1.0f / lo0;
    const float inv1 = 1.0f / lo1;
    const int bb = bh / HEADS;
    const int h  = bh % HEADS;
    const int row0 = qt*128 + q0 + r;
    #pragma unroll
    for (int nt = 0; nt < 8; nt++) {
        const int d = h * 64 + nt*8 + 2*cl;
        ((uint32_t*)attn_out)[(((size_t)bb * SEQ + row0)     * D_MODEL + d)/2] =
            pack_half2(o[nt][0] * inv0, o[nt][1] * inv0);
        ((uint32_t*)attn_out)[(((size_t)bb * SEQ + row0 + 8) * D_MODEL + d)/2] =
            pack_half2(o[nt][2] * inv1, o[nt][3] * inv1);
    }
}

// ---------------------------------------------------------------------------

static const int ATTN_SMEM = 2 * STAGEU * (int)sizeof(uint32_t);         // 71680
static const int GEMM_SMEM = 6 * ABUFU * (int)sizeof(uint32_t);          // 110592

extern "C" void kernel_launch(void* const* d_in, const int* in_sizes, int n_in,
                              void* d_out, int out_size)
{
    const float* x     = (const float*)d_in[0];
    const float* W_qkv = (const float*)d_in[1];
    const float* b_qkv = (const float*)d_in[2];
    const float* W_out = (const float*)d_in[3];
    const float* b_out = (const float*)d_in[4];
    float* out = (float*)d_out;

    cudaFuncSetAttribute(attn_kernel,
                         cudaFuncAttributeMaxDynamicSharedMemorySize, ATTN_SMEM);
    cudaFuncSetAttribute(mma_gemm_kernel<0>,
                         cudaFuncAttributeMaxDynamicSharedMemorySize, GEMM_SMEM);
    cudaFuncSetAttribute(mma_gemm_kernel<1>,
                         cudaFuncAttributeMaxDynamicSharedMemorySize, GEMM_SMEM);

    __half *xh, *wqkv_t, *wout_t, *attn_h;
    cudaGetSymbolAddress((void**)&xh, g_h);
    cudaGetSymbolAddress((void**)&wqkv_t, g_wqkv_t);
    cudaGetSymbolAddress((void**)&wout_t, g_wout_t);
    attn_h = xh;   // reuse: X consumed by qkv gemm before attn writes

    convert_x_kernel<<<M_TOTAL*D_MODEL/(4*256), 256>>>(x, xh);
    transpose_w_kernel<<<dim3(N_QKV/32, KDIM/32), dim3(32, 8)>>>(W_qkv, wqkv_t, KDIM, N_QKV);
    transpose_w_kernel<<<dim3(D_MODEL/32, KDIM/32), dim3(32, 8)>>>(W_out, wout_t, KDIM, D_MODEL);

    dim3 g1(N_QKV / 128, M_TOTAL / 128);
    mma_gemm_kernel<0><<<g1, 256, GEMM_SMEM>>>(xh, wqkv_t, b_qkv, nullptr);

    dim3 g2(SEQ / 128, BH);
    attn_kernel<<<g2, 256, ATTN_SMEM>>>(attn_h);

    dim3 g3(D_MODEL / 128, M_TOTAL / 128);
    mma_gemm_kernel<1><<<g3, 256, GEMM_SMEM>>>(attn_h, wout_t, b_out, out);
}

// round 14
// speedup vs baseline: 8.4439x; 1.0490x over previous
#include <cuda_runtime.h>
#include <cuda_fp16.h>
#include <math.h>
#include <stdint.h>

#define D_MODEL 768
#define HEADS   12
#define HD      64
#define BATCH   4
#define SEQ     2048
#define M_TOTAL (BATCH*SEQ)      // 8192
#define N_QKV   (3*D_MODEL)      // 2304
#define BH      (BATCH*HEADS)    // 48
#define KDIM    768
#define NCHUNK  (KDIM/64)        // 12 chunks of K=64

// q scale: 1/sqrt(64) * log2(e)  (softmax done in exp2 domain)
#define QSCALE 0.1803368801111306f
#define ONES2  0x3C003C00u       // half2(1.0, 1.0)

// Scratch (device globals)
__device__ __half g_q[BH*SEQ*HD];       // pre-scaled by QSCALE
__device__ __half g_k[BH*SEQ*HD];
__device__ __half g_vt[BH*HD*SEQ];      // [bh][d][seq]
__device__ __half g_h[M_TOTAL*D_MODEL]; // half X, later attn output
__device__ __half g_wqkv_t[N_QKV*KDIM];
__device__ __half g_wout_t[D_MODEL*KDIM];

// ---------------------------------------------------------------------------
__device__ __forceinline__ uint32_t smem_to_u32(const void* p) {
    uint32_t a;
    asm("{ .reg .u64 t; cvta.to.shared.u64 t, %1; cvt.u32.u64 %0, t; }"
        : "=r"(a) : "l"(p));
    return a;
}
__device__ __forceinline__ uint32_t pack_half2(float lo, float hi) {
    uint32_t u;
    asm("cvt.rn.f16x2.f32 %0, %1, %2;" : "=r"(u) : "f"(hi), "f"(lo));
    return u;
}
__device__ __forceinline__ uint32_t exp2_h2(uint32_t a) {
    uint32_t d;
    asm("ex2.approx.f16x2 %0, %1;" : "=r"(d) : "r"(a));
    return d;
}
__device__ __forceinline__ void ldsm_x4(uint32_t& r0, uint32_t& r1,
                                        uint32_t& r2, uint32_t& r3, uint32_t addr)
{
    asm volatile("ldmatrix.sync.aligned.m8n8.x4.shared.b16 {%0,%1,%2,%3}, [%4];"
        : "=r"(r0), "=r"(r1), "=r"(r2), "=r"(r3) : "r"(addr));
}
#define CP_ASYNC16(smem_addr, gptr) \
    asm volatile("cp.async.cg.shared.global [%0], [%1], 16;" \
        :: "r"(smem_addr), "l"(gptr))
#define CP_COMMIT() asm volatile("cp.async.commit_group;" ::: "memory")
#define CP_WAIT1()  asm volatile("cp.async.wait_group 1;" ::: "memory")
#define CP_WAIT0()  asm volatile("cp.async.wait_group 0;" ::: "memory")

__device__ __forceinline__ void mma_f16(float c[4],
    uint32_t a0, uint32_t a1, uint32_t a2, uint32_t a3,
    uint32_t b0, uint32_t b1)
{
    asm volatile(
        "mma.sync.aligned.m16n8k16.row.col.f32.f16.f16.f32 "
        "{%0,%1,%2,%3}, {%4,%5,%6,%7}, {%8,%9}, {%0,%1,%2,%3};"
        : "+f"(c[0]), "+f"(c[1]), "+f"(c[2]), "+f"(c[3])
        : "r"(a0), "r"(a1), "r"(a2), "r"(a3), "r"(b0), "r"(b1));
}

// ---------------------------------------------------------------------------
// X -> half
__global__ void convert_x_kernel(const float* __restrict__ src, __half* __restrict__ dst)
{
    const int i = (blockIdx.x * blockDim.x + threadIdx.x) * 4;
    float4 v = *(const float4*)&src[i];
    ((uint32_t*)dst)[i/2]     = pack_half2(v.x, v.y);
    ((uint32_t*)dst)[i/2 + 1] = pack_half2(v.z, v.w);
}

// W transpose + half: dst[N][K] = half(src[K][N])
__global__ void transpose_w_kernel(const float* __restrict__ src,
                                   __half* __restrict__ dst, int R, int C)
{
    __shared__ float t[32][33];
    const int bx = blockIdx.x * 32, by = blockIdx.y * 32;
    const int x = threadIdx.x, y = threadIdx.y;
    #pragma unroll
    for (int i = 0; i < 32; i += 8)
        t[y + i][x] = src[(size_t)(by + y + i) * C + bx + x];
    __syncthreads();
    #pragma unroll
    for (int i = 0; i < 32; i += 8)
        dst[(size_t)(bx + y + i) * R + by + x] = __float2half_rn(t[x][y + i]);
}

// ---------------------------------------------------------------------------
// fp16 mma.sync GEMM: 128-thread CTAs (4 warps), tile 64m x 128n, 4 CTAs/SM.
// 2-stage cp.async, K chunks of 64, ldmatrix fragments.
// MODE 0: scatter q(*QSCALE)/k to [bh][seq][64]; V transposed into g_vt.
// MODE 1: fp32 [M][768] out.
// ---------------------------------------------------------------------------
#define HPU   36                 // u32 per smem row (72 halfs, 64 used)
#define ABUF  (64*HPU)           // A stage: 2304 u32
#define BBUF  (128*HPU)          // B stage: 4608 u32
#define CPITCH 133               // floats, epilogue staging pitch

template<int MODE>
__global__ __launch_bounds__(128, 4)
void mma_gemm_kernel(const __half* __restrict__ A, const __half* __restrict__ Bt,
                     const float* __restrict__ bias, float* __restrict__ out)
{
    extern __shared__ uint32_t smu[];
    float* smf = (float*)smu;

    const int tid  = threadIdx.x;
    const int wid  = tid >> 5;        // 0..3
    const int lane = tid & 31;
    const int m0 = blockIdx.y * 64;
    const int n0 = blockIdx.x * 128;
    const int wm = (wid >> 1) * 32;   // 0/32
    const int wn = (wid & 1) * 64;    // 0/64
    const uint32_t sbase = smem_to_u32(smu);
    const int r = lane >> 2;
    const int cl = lane & 3;
    const int mm = lane >> 3;
    const int lrow = lane & 7;

    uint32_t aoff[2], boff[4];
    #pragma unroll
    for (int mi = 0; mi < 2; mi++)
        aoff[mi] = ((wm + mi*16 + (mm & 1)*8 + lrow) * HPU + (mm >> 1)*4) * 4;
    #pragma unroll
    for (int p = 0; p < 4; p++)
        boff[p] = ((wn + (p*2 + (mm >> 1))*8 + lrow) * HPU + (mm & 1)*4) * 4;

    float acc[2][8][4] = {};

    // prologue: chunk 0 into stage 0. 512 A-loads + 1024 B-loads = 12/thread
    #pragma unroll
    for (int i = 0; i < 12; i++) {
        const int idx = i * 128 + tid;       // 0..1535
        if (idx < 512) {
            const int row = idx >> 3;
            const int seg = (idx & 7) * 8;
            CP_ASYNC16(sbase + (uint32_t)(row*HPU)*4 + seg*2,
                       &A[(size_t)(m0 + row) * KDIM + seg]);
        } else {
            const int j = idx - 512;
            const int row = j >> 3;
            const int seg = (j & 7) * 8;
            CP_ASYNC16(sbase + (uint32_t)(2*ABUF + row*HPU)*4 + seg*2,
                       &Bt[(size_t)(n0 + row) * KDIM + seg]);
        }
    }
    CP_COMMIT();

    for (int c = 0; c < NCHUNK; c++) {
        const int buf = c & 1;
        if (c + 1 < NCHUNK) {
            const int nb = buf ^ 1;
            const int k0 = (c + 1) * 64;
            #pragma unroll
            for (int i = 0; i < 12; i++) {
                const int idx = i * 128 + tid;
                if (idx < 512) {
                    const int row = idx >> 3;
                    const int seg = (idx & 7) * 8;
                    CP_ASYNC16(sbase + (uint32_t)(nb*ABUF + row*HPU)*4 + seg*2,
                               &A[(size_t)(m0 + row) * KDIM + k0 + seg]);
                } else {
                    const int j = idx - 512;
                    const int row = j >> 3;
                    const int seg = (j & 7) * 8;
                    CP_ASYNC16(sbase + (uint32_t)(2*ABUF + nb*BBUF + row*HPU)*4 + seg*2,
                               &Bt[(size_t)(n0 + row) * KDIM + k0 + seg]);
                }
            }
            CP_COMMIT();
            CP_WAIT1();
        } else {
            CP_WAIT0();
        }
        __syncthreads();

        const uint32_t aB = sbase + (uint32_t)(buf*ABUF)*4;
        const uint32_t bB = sbase + (uint32_t)(2*ABUF + buf*BBUF)*4;

        #pragma unroll
        for (int ks = 0; ks < 4; ks++) {
            const uint32_t kbyte = ks * 32;
            uint32_t af[2][4];
            #pragma unroll
            for (int mi = 0; mi < 2; mi++)
                ldsm_x4(af[mi][0], af[mi][1], af[mi][2], af[mi][3],
                        aB + aoff[mi] + kbyte);
            uint32_t bf[8][2];
            #pragma unroll
            for (int p = 0; p < 4; p++)
                ldsm_x4(bf[2*p][0], bf[2*p][1], bf[2*p+1][0], bf[2*p+1][1],
                        bB + boff[p] + kbyte);
            #pragma unroll
            for (int mi = 0; mi < 2; mi++)
                #pragma unroll
                for (int ni = 0; ni < 8; ni++)
                    mma_f16(acc[mi][ni], af[mi][0], af[mi][1], af[mi][2], af[mi][3],
                            bf[ni][0], bf[ni][1]);
        }
        __syncthreads();   // compute done before next chunk overwrites buf
    }

    // stage C in smem (float [64][CPITCH] = 34 KB, fits in operand smem)
    #pragma unroll
    for (int mi = 0; mi < 2; mi++)
        #pragma unroll
        for (int ni = 0; ni < 8; ni++) {
            const int row = wm + mi*16 + r;
            const int col = wn + ni*8 + 2*cl;
            smf[row * CPITCH + col]       = acc[mi][ni][0];
            smf[row * CPITCH + col + 1]   = acc[mi][ni][1];
            smf[(row+8) * CPITCH + col]   = acc[mi][ni][2];
            smf[(row+8) * CPITCH + col+1] = acc[mi][ni][3];
        }
    __syncthreads();

    if (MODE == 1) {
        // 64 x 128 floats = 2048 float4 / 128 thr = 16 each
        #pragma unroll
        for (int i = 0; i < 16; i++) {
            const int f = i * 128 + tid;
            const int row  = f >> 5;          // 0..63
            const int col  = (f & 31) * 4;
            const int m  = m0 + row;
            const int ng = n0 + col;
            float4 v = { smf[row*CPITCH + col + 0] + bias[ng + 0],
                         smf[row*CPITCH + col + 1] + bias[ng + 1],
                         smf[row*CPITCH + col + 2] + bias[ng + 2],
                         smf[row*CPITCH + col + 3] + bias[ng + 3] };
            *(float4*)&out[(size_t)m * D_MODEL + ng] = v;
        }
    } else {
        const int wsel = n0 / D_MODEL;
        if (wsel < 2) {
            __half* dst = (wsel == 0) ? g_q : g_k;
            const float sc = (wsel == 0) ? QSCALE : 1.0f;
            #pragma unroll
            for (int i = 0; i < 16; i++) {
                const int f = i * 128 + tid;
                const int row  = f >> 5;
                const int col  = (f & 31) * 4;
                const int m  = m0 + row;
                const int ng = n0 + col;
                float4 v = { (smf[row*CPITCH + col + 0] + bias[ng + 0]) * sc,
                             (smf[row*CPITCH + col + 1] + bias[ng + 1]) * sc,
                             (smf[row*CPITCH + col + 2] + bias[ng + 2]) * sc,
                             (smf[row*CPITCH + col + 3] + bias[ng + 3]) * sc };
                const int h = (ng % D_MODEL) >> 6;
                const int d = ng & 63;
                const int bb = m >> 11;
                const int l  = m & (SEQ - 1);
                const size_t off = (((size_t)bb * HEADS + h) * SEQ + l) * HD + d;
                ((uint32_t*)dst)[off/2]     = pack_half2(v.x, v.y);
                ((uint32_t*)dst)[off/2 + 1] = pack_half2(v.z, v.w);
            }
        } else {
            // v: transposed scatter into g_vt [bh][d][seq], coalesced along seq
            const int bb = m0 >> 11;
            const int l0 = m0 & (SEQ - 1);
            // 128 d-cols x 32 row-pairs = 4096 u32 / 128 thr = 32 each
            #pragma unroll
            for (int it = 0; it < 32; it++) {
                const int idx = it * 128 + tid;   // 0..4095
                const int d  = idx >> 5;          // 0..127
                const int l2 = idx & 31;          // row-pair 0..31
                const int ng = n0 + d;
                const float bv = bias[ng];
                const int h  = (ng % D_MODEL) >> 6;
                const int dd = ng & 63;
                const float v0 = smf[(2*l2)   * CPITCH + d] + bv;
                const float v1 = smf[(2*l2+1) * CPITCH + d] + bv;
                const size_t off = ((size_t)(bb * HEADS + h) * HD + dd) * SEQ + l0 + 2*l2;
                ((uint32_t*)g_vt)[off/2] = pack_half2(v0, v1);
            }
        }
    }
}

// ---------------------------------------------------------------------------
// Flash attention: 128-thread CTAs (4 warps x 16q = 64 q rows), 4 CTAs/SM.
// 64-key tiles double-buffered. K smem [key][d] pitch 72h, VT [d][key] pitch
// 72h. f16x2 exp2 softmax, ones-MMA row sums, P in registers.
// ---------------------------------------------------------------------------
#define AKPU  36                 // u32 per 72-half row
#define KTU   (64*AKPU)          // 2304 u32 per K or VT tile

__global__ __launch_bounds__(128, 4) void attn_kernel(__half* __restrict__ attn_out)
{
    extern __shared__ uint32_t smA[];

    const int tid  = threadIdx.x;
    const int wid  = tid >> 5;        // 0..3
    const int lane = tid & 31;
    const int r  = lane >> 2;
    const int cl = lane & 3;
    const int mm = lane >> 3;
    const int lrow = lane & 7;
    const int qt = blockIdx.x;        // 0..31 (64-q tiles)
    const int bh = blockIdx.y;
    const size_t head_base = (size_t)bh * SEQ * HD;   // halfs
    const int q0 = wid * 16;

    uint32_t foff[4];
    #pragma unroll
    for (int p = 0; p < 4; p++)
        foff[p] = (((p*2 + (mm >> 1))*8 + lrow) * AKPU + (mm & 1)*4) * 4;

    // Q fragments (g_q pre-scaled): 4 ksteps x 4 regs
    uint32_t qf[4][4];
    {
        const uint32_t* Qp = (const uint32_t*)&g_q[head_base + (size_t)(qt*64 + q0) * HD];
        #pragma unroll
        for (int kk = 0; kk < 4; kk++) {
            qf[kk][0] = Qp[(size_t)r     * 32 + kk*8 + cl];
            qf[kk][1] = Qp[(size_t)(r+8) * 32 + kk*8 + cl];
            qf[kk][2] = Qp[(size_t)r     * 32 + kk*8 + cl + 4];
            qf[kk][3] = Qp[(size_t)(r+8) * 32 + kk*8 + cl + 4];
        }
    }

    float o[8][4] = {};
    float mo0 = -INFINITY, mo1 = -INFINITY, lo0 = 0.0f, lo1 = 0.0f;

    const uint32_t sb = smem_to_u32(smA);
    // layout: [K0, V0, K1, V1]
    const uint32_t kb[2] = { sb,              sb + 2*KTU*4 };
    const uint32_t vb[2] = { sb + KTU*4,      sb + 3*KTU*4 };
    const size_t vt_base = (size_t)bh * HD * SEQ;

    // prologue tile 0: K 64x8 segs (512) + VT 64x8 segs (512) = 8/thread
    #pragma unroll
    for (int i = 0; i < 8; i++) {
        const int idx = i * 128 + tid;     // 0..1023
        if (idx < 512) {
            const int row = idx >> 3;
            const int seg = (idx & 7) * 8;
            CP_ASYNC16(kb[0] + (uint32_t)(row*AKPU)*4 + seg*2,
                       (const char*)&g_k[head_base + (size_t)row * HD + seg]);
        } else {
            const int j = idx - 512;
            const int row = j >> 3;
            const int seg = (j & 7) * 8;
            CP_ASYNC16(vb[0] + (uint32_t)(row*AKPU)*4 + seg*2,
                       (const char*)&g_vt[vt_base + (size_t)row * SEQ + seg]);
        }
    }
    CP_COMMIT();

    for (int kt = 0; kt < SEQ/64; kt++) {
        const int buf = kt & 1;
        __syncthreads();   // done with buf^1
        if (kt + 1 < SEQ/64) {
            const int nb = buf ^ 1;
            #pragma unroll
            for (int i = 0; i < 8; i++) {
                const int idx = i * 128 + tid;
                if (idx < 512) {
                    const int row = idx >> 3;
                    const int seg = (idx & 7) * 8;
                    CP_ASYNC16(kb[nb] + (uint32_t)(row*AKPU)*4 + seg*2,
                               (const char*)&g_k[head_base + (size_t)((kt+1)*64 + row) * HD + seg]);
                } else {
                    const int j = idx - 512;
                    const int row = j >> 3;
                    const int seg = (j & 7) * 8;
                    CP_ASYNC16(vb[nb] + (uint32_t)(row*AKPU)*4 + seg*2,
                               (const char*)&g_vt[vt_base + (size_t)row * SEQ + (kt+1)*64 + seg]);
                }
            }
            CP_COMMIT();
            CP_WAIT1();
        } else {
            CP_WAIT0();
        }
        __syncthreads();   // tile kt visible

        // ---- S = Q K^T ----
        const uint32_t Kc = kb[buf];
        float s[8][4] = {};
        #pragma unroll
        for (int kk = 0; kk < 4; kk++) {
            const uint32_t kbyte = kk * 32;
            uint32_t bf[8][2];
            #pragma unroll
            for (int p = 0; p < 4; p++)
                ldsm_x4(bf[2*p][0], bf[2*p][1], bf[2*p+1][0], bf[2*p+1][1],
                        Kc + foff[p] + kbyte);
            #pragma unroll
            for (int nt = 0; nt < 8; nt++)
                mma_f16(s[nt], qf[kk][0], qf[kk][1], qf[kk][2], qf[kk][3],
                        bf[nt][0], bf[nt][1]);
        }

        // ---- row max (quad reduction) ----
        float mx0 = -INFINITY, mx1 = -INFINITY;
        #pragma unroll
        for (int nt = 0; nt < 8; nt++) {
            mx0 = fmaxf(mx0, fmaxf(s[nt][0], s[nt][1]));
            mx1 = fmaxf(mx1, fmaxf(s[nt][2], s[nt][3]));
        }
        mx0 = fmaxf(mx0, __shfl_xor_sync(0xffffffffu, mx0, 1));
        mx0 = fmaxf(mx0, __shfl_xor_sync(0xffffffffu, mx0, 2));
        mx1 = fmaxf(mx1, __shfl_xor_sync(0xffffffffu, mx1, 1));
        mx1 = fmaxf(mx1, __shfl_xor_sync(0xffffffffu, mx1, 2));
        const float mn0 = fmaxf(mo0, mx0);
        const float mn1 = fmaxf(mo1, mx1);
        const float a0 = exp2f(mo0 - mn0);
        const float a1 = exp2f(mo1 - mn1);

        // ---- P = exp2(s - m) in f16x2, packed as PV A-fragments ----
        uint32_t pf[4][4];
        #pragma unroll
        for (int kk = 0; kk < 4; kk++) {
            pf[kk][0] = exp2_h2(pack_half2(s[2*kk][0]   - mn0, s[2*kk][1]   - mn0));
            pf[kk][1] = exp2_h2(pack_half2(s[2*kk][2]   - mn1, s[2*kk][3]   - mn1));
            pf[kk][2] = exp2_h2(pack_half2(s[2*kk+1][0] - mn0, s[2*kk+1][1] - mn0));
            pf[kk][3] = exp2_h2(pack_half2(s[2*kk+1][2] - mn1, s[2*kk+1][3] - mn1));
        }

        // ---- row sums via ones-MMA ----
        float ls[4] = {};
        #pragma unroll
        for (int kk = 0; kk < 4; kk++)
            mma_f16(ls, pf[kk][0], pf[kk][1], pf[kk][2], pf[kk][3], ONES2, ONES2);

        lo0 = a0 * lo0 + ls[0];  mo0 = mn0;
        lo1 = a1 * lo1 + ls[2];  mo1 = mn1;
        #pragma unroll
        for (int nt = 0; nt < 8; nt++) {
            o[nt][0] *= a0; o[nt][1] *= a0;
            o[nt][2] *= a1; o[nt][3] *= a1;
        }

        // ---- O += P V ----
        const uint32_t Vc = vb[buf];
        #pragma unroll
        for (int kk = 0; kk < 4; kk++) {
            const uint32_t kbyte = kk * 32;
            uint32_t bf[8][2];
            #pragma unroll
            for (int p = 0; p < 4; p++)
                ldsm_x4(bf[2*p][0], bf[2*p][1], bf[2*p+1][0], bf[2*p+1][1],
                        Vc + foff[p] + kbyte);
            #pragma unroll
            for (int nt = 0; nt < 8; nt++)
                mma_f16(o[nt], pf[kk][0], pf[kk][1], pf[kk][2], pf[kk][3],
                        bf[nt][0], bf[nt][1]);
        }
    }

    // ---- epilogue: normalize, write half [B, L, H*64] ----
    const float inv0 = 1.0f / lo0;
    const float inv1 = 1.0f / lo1;
    const int bb = bh / HEADS;
    const int h  = bh % HEADS;
    const int row0 = qt*64 + q0 + r;
    #pragma unroll
    for (int nt = 0; nt < 8; nt++) {
        const int d = h * 64 + nt*8 + 2*cl;
        ((uint32_t*)attn_out)[(((size_t)bb * SEQ + row0)     * D_MODEL + d)/2] =
            pack_half2(o[nt][0] * inv0, o[nt][1] * inv0);
        ((uint32_t*)attn_out)[(((size_t)bb * SEQ + row0 + 8) * D_MODEL + d)/2] =
            pack_half2(o[nt][2] * inv1, o[nt][3] * inv1);
    }
}

// ---------------------------------------------------------------------------

static const int ATTN_SMEM = 4 * KTU * (int)sizeof(uint32_t);               // 36864
static const int GEMM_SMEM = (2*ABUF + 2*BBUF) * (int)sizeof(uint32_t);     // 55296

extern "C" void kernel_launch(void* const* d_in, const int* in_sizes, int n_in,
                              void* d_out, int out_size)
{
    const float* x     = (const float*)d_in[0];
    const float* W_qkv = (const float*)d_in[1];
    const float* b_qkv = (const float*)d_in[2];
    const float* W_out = (const float*)d_in[3];
    const float* b_out = (const float*)d_in[4];
    float* out = (float*)d_out;

    cudaFuncSetAttribute(attn_kernel,
                         cudaFuncAttributeMaxDynamicSharedMemorySize, ATTN_SMEM);
    cudaFuncSetAttribute(mma_gemm_kernel<0>,
                         cudaFuncAttributeMaxDynamicSharedMemorySize, GEMM_SMEM);
    cudaFuncSetAttribute(mma_gemm_kernel<1>,
                         cudaFuncAttributeMaxDynamicSharedMemorySize, GEMM_SMEM);

    __half *xh, *wqkv_t, *wout_t, *attn_h;
    cudaGetSymbolAddress((void**)&xh, g_h);
    cudaGetSymbolAddress((void**)&wqkv_t, g_wqkv_t);
    cudaGetSymbolAddress((void**)&wout_t, g_wout_t);
    attn_h = xh;   // reuse: X consumed by qkv gemm before attn writes

    convert_x_kernel<<<M_TOTAL*D_MODEL/(4*256), 256>>>(x, xh);
    transpose_w_kernel<<<dim3(N_QKV/32, KDIM/32), dim3(32, 8)>>>(W_qkv, wqkv_t, KDIM, N_QKV);
    transpose_w_kernel<<<dim3(D_MODEL/32, KDIM/32), dim3(32, 8)>>>(W_out, wout_t, KDIM, D_MODEL);

    dim3 g1(N_QKV / 128, M_TOTAL / 64);      // 18 x 128
    mma_gemm_kernel<0><<<g1, 128, GEMM_SMEM>>>(xh, wqkv_t, b_qkv, nullptr);

    dim3 g2(SEQ / 64, BH);                   // 32 x 48
    attn_kernel<<<g2, 128, ATTN_SMEM>>>(attn_h);

    dim3 g3(D_MODEL / 128, M_TOTAL / 64);    // 6 x 128
    mma_gemm_kernel<1><<<g3, 128, GEMM_SMEM>>>(attn_h, wout_t, b_out, out);
}